// round 2
// baseline (speedup 1.0000x reference)
#include <cuda_runtime.h>
#include <cuda_bf16.h>

// ---------------------------------------------------------------------------
// Attention3D: B=2, D=8,H=16,W=32 -> N=4096, C=128, heads=4, dim_head=32
// cosine attention, SCALE=10. All fp32.
// ---------------------------------------------------------------------------

#define B_   2
#define N_   4096
#define C_   128
#define NH   4
#define DH   32
#define DIM  128          // NH*DH
#define QKV  384          // 3*DIM
#define ROWS_TOT (B_*N_)  // 8192

// SCALE * log2(e)
#define C0 14.4269504088896340736f

// ---------------- scratch (no allocations allowed) -------------------------
__device__ __align__(16) float g_q[B_*NH*N_*DH];   // [bh][n][d], pre-scaled by SCALE*log2e
__device__ __align__(16) float g_k[B_*NH*N_*DH];   // [bh][n][d], unit norm
__device__ __align__(16) float g_v[B_*NH*N_*DH];   // [bh][n][d]
__device__ __align__(16) float g_ao[B_*N_*DIM];    // attention output [b][n][h*32+d]

// ---------------- packed f32x2 helpers -------------------------------------
__device__ __forceinline__ unsigned long long pack2(float a, float b) {
    unsigned long long r;
    asm("mov.b64 %0, {%1,%2};" : "=l"(r) : "f"(a), "f"(b));
    return r;
}
__device__ __forceinline__ float2 unpack2(unsigned long long v) {
    float2 f;
    asm("mov.b64 {%0,%1}, %2;" : "=f"(f.x), "=f"(f.y) : "l"(v));
    return f;
}
__device__ __forceinline__ unsigned long long ffma2(unsigned long long a,
                                                    unsigned long long b,
                                                    unsigned long long c) {
    unsigned long long d;
    asm("fma.rn.f32x2 %0, %1, %2, %3;" : "=l"(d) : "l"(a), "l"(b), "l"(c));
    return d;
}
__device__ __forceinline__ float ex2(float x) {
    float r;
    asm("ex2.approx.ftz.f32 %0, %1;" : "=f"(r) : "f"(x));
    return r;
}

// ---------------------------------------------------------------------------
// Kernel A: qkv = x @ w_qkv, then per-head L2 norm of q,k.
// 128 blocks x 192 threads; each block caches full w_qkv (196KB) in smem and
// streams 64 rows. Thread j owns column pair (2j, 2j+1).
// ---------------------------------------------------------------------------
__global__ void __launch_bounds__(192) qkv_kernel(const float* __restrict__ x,
                                                  const float* __restrict__ w) {
    extern __shared__ float smA[];
    float* ws = smA;                                            // 49152 floats
    unsigned long long* xu = (unsigned long long*)(smA + C_*QKV); // 2*128 ull

    const int tid = threadIdx.x;

    // cooperative load of w_qkv into smem (coalesced float4)
    const float4* w4 = (const float4*)w;
    float4* ws4 = (float4*)ws;
    for (int i = tid; i < (C_*QKV)/4; i += 192) ws4[i] = w4[i];
    __syncthreads();

    const unsigned long long* wsu = (const unsigned long long*)ws; // [c][192] pairs
    const int j = tid;

    for (int r = 0; r < 64; ++r) {
        const int row = blockIdx.x * 64 + r;
        // warp0 stages the x row, duplicated into f32x2 lanes
        if (tid < 32) {
            float4 v = ((const float4*)(x + (size_t)row * C_))[tid];
            int base = (r & 1) * 128 + tid * 4;
            xu[base+0] = pack2(v.x, v.x);
            xu[base+1] = pack2(v.y, v.y);
            xu[base+2] = pack2(v.z, v.z);
            xu[base+3] = pack2(v.w, v.w);
        }
        __syncthreads();
        const unsigned long long* xb = xu + (r & 1) * 128;

        unsigned long long acc = 0ULL;
        #pragma unroll 8
        for (int c = 0; c < C_; ++c)
            acc = ffma2(xb[c], wsu[c * 192 + j], acc);
        float2 a = unpack2(acc);

        const int b = row >> 12;
        const int n = row & (N_ - 1);

        if (j < 128) {
            // q (j<64) or k (64<=j<128): per-head L2 norm over 16-lane group
            float ss = a.x * a.x + a.y * a.y;
            #pragma unroll
            for (int o = 8; o; o >>= 1)
                ss += __shfl_xor_sync(0xffffffffu, ss, o, 16);
            float inv = 1.0f / fmaxf(sqrtf(ss), 1e-12f);
            if (j < 64) inv *= C0;          // bake SCALE*log2e into q
            const int jj = j & 63;
            const int h  = jj >> 4;
            const int d  = (jj & 15) * 2;
            float* dst = (j < 64 ? g_q : g_k) + (((size_t)(b*NH + h) * N_ + n) * DH + d);
            *(float2*)dst = make_float2(a.x * inv, a.y * inv);
        } else {
            const int jj = j - 128;
            const int h  = jj >> 4;
            const int d  = (jj & 15) * 2;
            *(float2*)(g_v + (((size_t)(b*NH + h) * N_ + n) * DH + d)) =
                make_float2(a.x, a.y);
        }
    }
}

// ---------------------------------------------------------------------------
// Kernel B: flash attention with fixed softmax offset (scores bounded by 10).
// grid (32 q-tiles, 8 bh), 128 threads; one query row per thread.
// KV tiles of 128 keys staged in smem; inner loops are f32x2 FMA with
// broadcast LDS.128 reads of the shared key/value row.
// ---------------------------------------------------------------------------
__global__ void __launch_bounds__(128) attn_kernel() {
    __shared__ __align__(16) float sK[128 * DH];
    __shared__ __align__(16) float sV[128 * DH];

    const int bh  = blockIdx.y;
    const int row = blockIdx.x * 128 + threadIdx.x;

    // load this thread's q row (pre-scaled by SCALE*log2e)
    unsigned long long q[16];
    {
        const ulonglong2* q2 = (const ulonglong2*)(g_q + ((size_t)bh * N_ + row) * DH);
        #pragma unroll
        for (int i = 0; i < 8; ++i) { ulonglong2 t = q2[i]; q[2*i] = t.x; q[2*i+1] = t.y; }
    }

    unsigned long long o[16];
    #pragma unroll
    for (int i = 0; i < 16; ++i) o[i] = 0ULL;
    float l = 0.f;

    const float4* Kb = (const float4*)(g_k + (size_t)bh * N_ * DH);
    const float4* Vb = (const float4*)(g_v + (size_t)bh * N_ * DH);

    for (int t = 0; t < N_ / 128; ++t) {
        __syncthreads();
        #pragma unroll
        for (int i = 0; i < 8; ++i) {
            ((float4*)sK)[threadIdx.x + i*128] = Kb[t*1024 + threadIdx.x + i*128];
            ((float4*)sV)[threadIdx.x + i*128] = Vb[t*1024 + threadIdx.x + i*128];
        }
        __syncthreads();

        #pragma unroll 2
        for (int jj = 0; jj < 128; ++jj) {
            const ulonglong2* kr = (const ulonglong2*)(sK + jj * DH);
            unsigned long long a0 = 0ULL, a1 = 0ULL;
            #pragma unroll
            for (int i = 0; i < 4; ++i) {
                ulonglong2 k0 = kr[2*i], k1 = kr[2*i+1];
                a0 = ffma2(q[4*i+0], k0.x, a0);
                a1 = ffma2(q[4*i+1], k0.y, a1);
                a0 = ffma2(q[4*i+2], k1.x, a0);
                a1 = ffma2(q[4*i+3], k1.y, a1);
            }
            float2 f0 = unpack2(a0), f1 = unpack2(a1);
            float s = (f0.x + f0.y) + (f1.x + f1.y);   // = 10*log2e*cos(q,k)
            float p = ex2(s - C0);                     // exp(score - 10)
            l += p;
            unsigned long long pp = pack2(p, p);
            const ulonglong2* vr = (const ulonglong2*)(sV + jj * DH);
            #pragma unroll
            for (int i = 0; i < 8; ++i) {
                ulonglong2 vv = vr[i];
                o[2*i]   = ffma2(pp, vv.x, o[2*i]);
                o[2*i+1] = ffma2(pp, vv.y, o[2*i+1]);
            }
        }
    }

    const float inv = 1.0f / l;
    const int b = bh >> 2, h = bh & 3;
    float* op = g_ao + ((size_t)(b * N_) + row) * DIM + h * DH;
    #pragma unroll
    for (int i = 0; i < 16; ++i) {
        float2 f = unpack2(o[i]);
        ((float2*)op)[i] = make_float2(f.x * inv, f.y * inv);
    }
}

// ---------------------------------------------------------------------------
// Kernel C: out = g_ao @ w_out + b_out.  128 blocks x 128 threads, w_out in
// smem (64KB dynamic), 64 rows per block, thread j owns output column j.
// ---------------------------------------------------------------------------
__global__ void __launch_bounds__(128) out_kernel(const float* __restrict__ wout,
                                                  const float* __restrict__ bout,
                                                  float* __restrict__ out) {
    extern __shared__ float smC[];
    float* ws = smC;                 // 16384 floats
    float* xb = smC + DIM * DIM;     // 2*128 floats

    const int tid = threadIdx.x;
    const float4* w4 = (const float4*)wout;
    float4* ws4 = (float4*)ws;
    for (int i = tid; i < (DIM*DIM)/4; i += 128) ws4[i] = w4[i];
    const float bj = bout[tid];
    __syncthreads();

    for (int r = 0; r < 64; ++r) {
        const int row = blockIdx.x * 64 + r;
        if (tid < 32)
            ((float4*)(xb + (r & 1) * 128))[tid] =
                ((const float4*)(g_ao + (size_t)row * DIM))[tid];
        __syncthreads();
        const float* xs = xb + (r & 1) * 128;
        float acc = bj;
        #pragma unroll 8
        for (int c = 0; c < DIM; ++c)
            acc = fmaf(xs[c], ws[c * DIM + tid], acc);
        out[(size_t)row * DIM + tid] = acc;
    }
}

// ---------------------------------------------------------------------------
extern "C" void kernel_launch(void* const* d_in, const int* in_sizes, int n_in,
                              void* d_out, int out_size) {
    // identify inputs by element count (robust to ordering)
    const float* x = nullptr, *wqkv = nullptr, *wout = nullptr, *bout = nullptr;
    for (int i = 0; i < n_in; ++i) {
        switch (in_sizes[i]) {
            case ROWS_TOT * C_: x    = (const float*)d_in[i]; break; // 1048576*? = 8192*128
            case C_ * QKV:      wqkv = (const float*)d_in[i]; break; // 49152
            case DIM * C_:      wout = (const float*)d_in[i]; break; // 16384
            case C_:            bout = (const float*)d_in[i]; break; // 128
        }
    }
    float* out = (float*)d_out;

    const int smA = C_ * QKV * 4 + 256 * 8;       // 198656 B
    const int smC = DIM * DIM * 4 + 256 * 4;      // 66560 B
    cudaFuncSetAttribute(qkv_kernel, cudaFuncAttributeMaxDynamicSharedMemorySize, smA);
    cudaFuncSetAttribute(out_kernel, cudaFuncAttributeMaxDynamicSharedMemorySize, smC);

    qkv_kernel<<<128, 192, smA>>>(x, wqkv);
    attn_kernel<<<dim3(32, 8), 128>>>();
    out_kernel<<<128, 128, smC>>>(wout, bout, out);
}

// round 3
// speedup vs baseline: 1.9256x; 1.9256x over previous
#include <cuda_runtime.h>

#define B_   2
#define N_   4096
#define C_   128
#define NH   4
#define DH   32
#define DIM  128
#define QKV  384
#define ROWS_TOT (B_*N_)
#define C0 14.4269504088896340736f

// ---------------- scratch ---------------------------------------------------
__device__ __align__(16) float g_qhi[8*N_*DH];
__device__ __align__(16) float g_qlo[8*N_*DH];
__device__ __align__(16) float g_khi[8*N_*DH];   // [bh][key][dim-permuted]
__device__ __align__(16) float g_klo[8*N_*DH];
__device__ __align__(16) float g_vhi[8*DH*N_];   // [bh][dim][key-permuted]
__device__ __align__(16) float g_vlo[8*DH*N_];
__device__ __align__(16) float g_ao [B_*N_*DIM];

// ---------------- helpers ----------------------------------------------------
__device__ __forceinline__ unsigned long long pack2(float a, float b) {
    unsigned long long r;
    asm("mov.b64 %0, {%1,%2};" : "=l"(r) : "f"(a), "f"(b));
    return r;
}
__device__ __forceinline__ float2 unpack2(unsigned long long v) {
    float2 f;
    asm("mov.b64 {%0,%1}, %2;" : "=f"(f.x), "=f"(f.y) : "l"(v));
    return f;
}
__device__ __forceinline__ unsigned long long ffma2(unsigned long long a,
                                                    unsigned long long b,
                                                    unsigned long long c) {
    unsigned long long d;
    asm("fma.rn.f32x2 %0, %1, %2, %3;" : "=l"(d) : "l"(a), "l"(b), "l"(c));
    return d;
}
__device__ __forceinline__ float ex2(float x) {
    float r;
    asm("ex2.approx.ftz.f32 %0, %1;" : "=f"(r) : "f"(x));
    return r;
}
// round-to-nearest tf32; returns value as float (low mantissa bits zero)
__device__ __forceinline__ float tf32r(float x) {
    unsigned u;
    asm("cvt.rna.tf32.f32 %0, %1;" : "=r"(u) : "f"(x));
    return __uint_as_float(u);
}
__device__ __forceinline__ void split2(float x, float& hi, float& lo) {
    hi = tf32r(x); lo = x - hi;
}
// m16n8k8 tf32 mma, fp32 accumulate
__device__ __forceinline__ void mma8(float& c0, float& c1, float& c2, float& c3,
                                     unsigned a0, unsigned a1, unsigned a2, unsigned a3,
                                     unsigned b0, unsigned b1) {
    asm volatile("mma.sync.aligned.m16n8k8.row.col.f32.tf32.tf32.f32 "
                 "{%0,%1,%2,%3},{%4,%5,%6,%7},{%8,%9},{%0,%1,%2,%3};"
                 : "+f"(c0), "+f"(c1), "+f"(c2), "+f"(c3)
                 : "r"(a0), "r"(a1), "r"(a2), "r"(a3), "r"(b0), "r"(b1));
}

// ---------------------------------------------------------------------------
// Kernel A: qkv = x @ w_qkv, L2-norm q,k, tf32 hi/lo splits, permuted layouts.
// 128 blocks x 192 threads; w_qkv in smem; 8-row register batching.
// ---------------------------------------------------------------------------
__global__ void __launch_bounds__(192) qkv_kernel(const float* __restrict__ x,
                                                  const float* __restrict__ w) {
    extern __shared__ float smA[];
    unsigned long long* wsu = (unsigned long long*)smA;             // [c][192]
    unsigned long long* xs  = (unsigned long long*)(smA + C_*QKV);  // 8 rows dup pairs

    const int tid = threadIdx.x;
    const float4* w4 = (const float4*)w;
    float4* ws4 = (float4*)smA;
    for (int i = tid; i < (C_*QKV)/4; i += 192) ws4[i] = w4[i];
    const int j = tid;

    for (int bt = 0; bt < 8; ++bt) {
        const int row0 = blockIdx.x * 64 + bt * 8;
        __syncthreads();
        for (int i = tid; i < 256; i += 192) {
            int r = i >> 5, c4 = i & 31;
            float4 v = ((const float4*)(x + (size_t)(row0 + r) * C_))[c4];
            unsigned long long* d = xs + r * 128 + c4 * 4;
            d[0] = pack2(v.x, v.x); d[1] = pack2(v.y, v.y);
            d[2] = pack2(v.z, v.z); d[3] = pack2(v.w, v.w);
        }
        __syncthreads();

        unsigned long long acc[8];
        #pragma unroll
        for (int r = 0; r < 8; ++r) acc[r] = 0ULL;
        #pragma unroll 4
        for (int c = 0; c < C_; ++c) {
            unsigned long long wp = wsu[c * 192 + j];
            #pragma unroll
            for (int r = 0; r < 8; ++r)
                acc[r] = ffma2(xs[r * 128 + c], wp, acc[r]);
        }

        #pragma unroll
        for (int r = 0; r < 8; ++r) {
            float2 a = unpack2(acc[r]);
            const int row = row0 + r, b = row >> 12, n = row & (N_ - 1);
            if (j < 128) {            // q or k: L2 norm over 16-lane head group
                float ss = a.x * a.x + a.y * a.y;
                #pragma unroll
                for (int o = 8; o; o >>= 1)
                    ss += __shfl_xor_sync(0xffffffffu, ss, o, 16);
                float inv = 1.0f / fmaxf(sqrtf(ss), 1e-12f);
                if (j < 64) {         // q: scale by SCALE*log2e, natural layout
                    inv *= C0;
                    const int h = j >> 4, d = (j & 15) * 2;
                    size_t base = ((size_t)(b * NH + h) * N_ + n) * DH + d;
                    float hx, lx, hy, ly;
                    split2(a.x * inv, hx, lx); split2(a.y * inv, hy, ly);
                    *(float2*)(g_qhi + base) = make_float2(hx, hy);
                    *(float2*)(g_qlo + base) = make_float2(lx, ly);
                } else {              // k: dim-permuted layout
                    const int jj = j - 64, h = jj >> 4, d = (jj & 15) * 2;
                    const int rr = d & 7;
                    const int pc = (d >> 3) * 8 + (rr & 3) * 2 + (rr >> 2);
                    size_t base = ((size_t)(b * NH + h) * N_ + n) * DH;
                    float hx, lx, hy, ly;
                    split2(a.x * inv, hx, lx); split2(a.y * inv, hy, ly);
                    g_khi[base + pc] = hx; g_khi[base + pc + 2] = hy;
                    g_klo[base + pc] = lx; g_klo[base + pc + 2] = ly;
                }
            } else {                  // v: transposed + key-permuted layout
                const int jj = j - 128, h = jj >> 4, d = (jj & 15) * 2;
                const int pk = (n & ~7) + (n & 3) * 2 + ((n >> 2) & 1);
                size_t vb = ((size_t)(b * NH + h) * DH + d) * N_ + pk;
                float hx, lx, hy, ly;
                split2(a.x, hx, lx); split2(a.y, hy, ly);
                g_vhi[vb] = hx; g_vhi[vb + N_] = hy;
                g_vlo[vb] = lx; g_vlo[vb + N_] = ly;
            }
        }
    }
}

// ---------------------------------------------------------------------------
// Kernel B: tf32 mma flash attention, 3xTF32 QK and PV, fixed softmax offset.
// grid (32, 8), 256 threads (8 warps x 16 query rows). Key chunks of 64.
// ---------------------------------------------------------------------------
__global__ void __launch_bounds__(256, 2) attn_kernel() {
    __shared__ __align__(16) float sKh[64*40], sKl[64*40];
    __shared__ __align__(16) float sVh[32*72], sVl[32*72];

    const int bh   = blockIdx.y;
    const int tid  = threadIdx.x;
    const int warp = tid >> 5, lane = tid & 31;
    const int quad = lane >> 2, qr = lane & 3;
    const int qb   = blockIdx.x * 128 + warp * 16;
    const int src1 = (lane & ~3) | (qr >> 1);
    const int src2 = src1 + 2;
    const bool oddl = lane & 1;

    // preload Q A-fragments (hi/lo)
    unsigned qh[4][4], ql[4][4];
    {
        const float* Qh = g_qhi + ((size_t)bh * N_ + qb + quad) * DH;
        const float* Ql = g_qlo + ((size_t)bh * N_ + qb + quad) * DH;
        #pragma unroll
        for (int ks = 0; ks < 4; ++ks) {
            qh[ks][0] = __float_as_uint(Qh[ks*8 + qr]);
            qh[ks][1] = __float_as_uint(Qh[8*DH + ks*8 + qr]);
            qh[ks][2] = __float_as_uint(Qh[ks*8 + qr + 4]);
            qh[ks][3] = __float_as_uint(Qh[8*DH + ks*8 + qr + 4]);
            ql[ks][0] = __float_as_uint(Ql[ks*8 + qr]);
            ql[ks][1] = __float_as_uint(Ql[8*DH + ks*8 + qr]);
            ql[ks][2] = __float_as_uint(Ql[ks*8 + qr + 4]);
            ql[ks][3] = __float_as_uint(Ql[8*DH + ks*8 + qr + 4]);
        }
    }

    float o[4][4];
    #pragma unroll
    for (int nt = 0; nt < 4; ++nt)
        o[nt][0] = o[nt][1] = o[nt][2] = o[nt][3] = 0.f;
    float l0 = 0.f, l1 = 0.f;

    const float* Kh = g_khi + (size_t)bh * N_ * DH;
    const float* Kl = g_klo + (size_t)bh * N_ * DH;
    const float* Vh = g_vhi + (size_t)bh * DH * N_;
    const float* Vl = g_vlo + (size_t)bh * DH * N_;

    for (int ch = 0; ch < N_ / 64; ++ch) {
        const int key0 = ch * 64;
        __syncthreads();
        #pragma unroll
        for (int i = tid; i < 512; i += 256) {
            int key = i >> 3, off = (i & 7) * 4;
            *(float4*)(sKh + key*40 + off) = *(const float4*)(Kh + (size_t)(key0+key)*DH + off);
            *(float4*)(sKl + key*40 + off) = *(const float4*)(Kl + (size_t)(key0+key)*DH + off);
        }
        #pragma unroll
        for (int i = tid; i < 512; i += 256) {
            int dm = i >> 4, off = (i & 15) * 4;
            *(float4*)(sVh + dm*72 + off) = *(const float4*)(Vh + (size_t)dm*N_ + key0 + off);
            *(float4*)(sVl + dm*72 + off) = *(const float4*)(Vl + (size_t)dm*N_ + key0 + off);
        }
        __syncthreads();

        #pragma unroll
        for (int h = 0; h < 2; ++h) {
            // ---- QK: S tile 16 x 32, accumulator init -C0 bakes the offset
            float p[4][4];
            #pragma unroll
            for (int nt = 0; nt < 4; ++nt)
                p[nt][0] = p[nt][1] = p[nt][2] = p[nt][3] = -C0;
            #pragma unroll
            for (int ks = 0; ks < 4; ++ks) {
                #pragma unroll
                for (int nt = 0; nt < 4; ++nt) {
                    const int off = (h*32 + nt*8 + quad) * 40 + ks*8 + qr*2;
                    float2 bh2 = *(const float2*)(sKh + off);
                    float2 bl2 = *(const float2*)(sKl + off);
                    unsigned b0 = __float_as_uint(bh2.x), b1 = __float_as_uint(bh2.y);
                    mma8(p[nt][0],p[nt][1],p[nt][2],p[nt][3],
                         qh[ks][0],qh[ks][1],qh[ks][2],qh[ks][3], b0, b1);
                    mma8(p[nt][0],p[nt][1],p[nt][2],p[nt][3],
                         ql[ks][0],ql[ks][1],ql[ks][2],ql[ks][3], b0, b1);
                    mma8(p[nt][0],p[nt][1],p[nt][2],p[nt][3],
                         qh[ks][0],qh[ks][1],qh[ks][2],qh[ks][3],
                         __float_as_uint(bl2.x), __float_as_uint(bl2.y));
                }
            }
            // ---- exp + row-sum accumulation (no rescale: fixed offset)
            #pragma unroll
            for (int nt = 0; nt < 4; ++nt) {
                p[nt][0] = ex2(p[nt][0]); p[nt][1] = ex2(p[nt][1]);
                p[nt][2] = ex2(p[nt][2]); p[nt][3] = ex2(p[nt][3]);
                l0 += p[nt][0] + p[nt][1];
                l1 += p[nt][2] + p[nt][3];
            }
            // ---- PV: for each k-step, shuffle P C-frag -> A-frag, split, mma
            #pragma unroll
            for (int ks = 0; ks < 4; ++ks) {
                float u0 = __shfl_sync(0xffffffffu, p[ks][0], src1);
                float u1 = __shfl_sync(0xffffffffu, p[ks][1], src1);
                float u2 = __shfl_sync(0xffffffffu, p[ks][2], src1);
                float u3 = __shfl_sync(0xffffffffu, p[ks][3], src1);
                float w0 = __shfl_sync(0xffffffffu, p[ks][0], src2);
                float w1 = __shfl_sync(0xffffffffu, p[ks][1], src2);
                float w2 = __shfl_sync(0xffffffffu, p[ks][2], src2);
                float w3 = __shfl_sync(0xffffffffu, p[ks][3], src2);
                float a0 = oddl ? u1 : u0;
                float a1 = oddl ? u3 : u2;
                float a2 = oddl ? w1 : w0;
                float a3 = oddl ? w3 : w2;
                float h0,g0,h1,g1,h2,g2,h3,g3;
                split2(a0,h0,g0); split2(a1,h1,g1);
                split2(a2,h2,g2); split2(a3,h3,g3);
                unsigned phi0=__float_as_uint(h0), phi1=__float_as_uint(h1),
                         phi2=__float_as_uint(h2), phi3=__float_as_uint(h3);
                unsigned plo0=__float_as_uint(g0), plo1=__float_as_uint(g1),
                         plo2=__float_as_uint(g2), plo3=__float_as_uint(g3);
                #pragma unroll
                for (int nt = 0; nt < 4; ++nt) {
                    const int off = (nt*8 + quad) * 72 + h*32 + ks*8 + qr*2;
                    float2 vh2 = *(const float2*)(sVh + off);
                    float2 vl2 = *(const float2*)(sVl + off);
                    unsigned b0 = __float_as_uint(vh2.x), b1 = __float_as_uint(vh2.y);
                    mma8(o[nt][0],o[nt][1],o[nt][2],o[nt][3], phi0,phi1,phi2,phi3, b0, b1);
                    mma8(o[nt][0],o[nt][1],o[nt][2],o[nt][3], plo0,plo1,plo2,plo3, b0, b1);
                    mma8(o[nt][0],o[nt][1],o[nt][2],o[nt][3], phi0,phi1,phi2,phi3,
                         __float_as_uint(vl2.x), __float_as_uint(vl2.y));
                }
            }
        }
    }

    // final row-sum reduce across quad, normalize, write
    l0 += __shfl_xor_sync(0xffffffffu, l0, 1);
    l0 += __shfl_xor_sync(0xffffffffu, l0, 2);
    l1 += __shfl_xor_sync(0xffffffffu, l1, 1);
    l1 += __shfl_xor_sync(0xffffffffu, l1, 2);
    const float i0 = 1.0f / l0, i1 = 1.0f / l1;
    const int b = bh >> 2, hh = bh & 3;
    float* op = g_ao + ((size_t)b * N_ + qb + quad) * DIM + hh * DH;
    #pragma unroll
    for (int nt = 0; nt < 4; ++nt) {
        *(float2*)(op + nt*8 + qr*2)          = make_float2(o[nt][0]*i0, o[nt][1]*i0);
        *(float2*)(op + 8*DIM + nt*8 + qr*2)  = make_float2(o[nt][2]*i1, o[nt][3]*i1);
    }
}

// ---------------------------------------------------------------------------
// Kernel C: out = g_ao @ w_out + b_out. 256 blocks x 128 threads, 32 rows each.
// ---------------------------------------------------------------------------
__global__ void __launch_bounds__(128) out_kernel(const float* __restrict__ wout,
                                                  const float* __restrict__ bout,
                                                  float* __restrict__ out) {
    extern __shared__ float smC[];
    float* ws = smC;
    float* xs = smC + DIM * DIM;

    const int tid = threadIdx.x;
    for (int i = tid; i < (DIM*DIM)/4; i += 128)
        ((float4*)ws)[i] = ((const float4*)wout)[i];
    const float bj = bout[tid];

    for (int bt = 0; bt < 4; ++bt) {
        const int row0 = blockIdx.x * 32 + bt * 8;
        __syncthreads();
        for (int i = tid; i < 256; i += 128) {
            int r = i >> 5, c4 = i & 31;
            ((float4*)(xs + r * 128))[c4] =
                ((const float4*)(g_ao + (size_t)(row0 + r) * DIM))[c4];
        }
        __syncthreads();
        float acc[8];
        #pragma unroll
        for (int r = 0; r < 8; ++r) acc[r] = bj;
        #pragma unroll 4
        for (int c = 0; c < DIM; ++c) {
            float wv = ws[c * DIM + tid];
            #pragma unroll
            for (int r = 0; r < 8; ++r)
                acc[r] = fmaf(xs[r * 128 + c], wv, acc[r]);
        }
        #pragma unroll
        for (int r = 0; r < 8; ++r)
            out[(size_t)(row0 + r) * DIM + tid] = acc[r];
    }
}

// ---------------------------------------------------------------------------
extern "C" void kernel_launch(void* const* d_in, const int* in_sizes, int n_in,
                              void* d_out, int out_size) {
    const float *x = nullptr, *wqkv = nullptr, *wout = nullptr, *bout = nullptr;
    for (int i = 0; i < n_in; ++i) {
        switch (in_sizes[i]) {
            case ROWS_TOT * C_: x    = (const float*)d_in[i]; break;
            case C_ * QKV:      wqkv = (const float*)d_in[i]; break;
            case DIM * C_:      wout = (const float*)d_in[i]; break;
            case C_:            bout = (const float*)d_in[i]; break;
        }
    }
    float* out = (float*)d_out;

    const int smA = C_ * QKV * 4 + 8 * 128 * 8;    // 204800 B
    const int smC = DIM * DIM * 4 + 8 * 128 * 4;   // 69632 B
    cudaFuncSetAttribute(qkv_kernel, cudaFuncAttributeMaxDynamicSharedMemorySize, smA);
    cudaFuncSetAttribute(out_kernel, cudaFuncAttributeMaxDynamicSharedMemorySize, smC);

    qkv_kernel<<<128, 192, smA>>>(x, wqkv);
    attn_kernel<<<dim3(32, 8), 256>>>();
    out_kernel<<<256, 128, smC>>>(wout, bout, out);
}

// round 4
// speedup vs baseline: 3.0097x; 1.5630x over previous
#include <cuda_runtime.h>
#include <cuda_bf16.h>

#define B_   2
#define N_   4096
#define C_   128
#define NH   4
#define DH   32
#define DIM  128
#define QKV  384
#define ROWS_TOT (B_*N_)
#define C0 14.4269504088896340736f

// ---------------- scratch ---------------------------------------------------
// q/k: per row 16 uints bf16x2 hi + 16 lo (k dim-pair permuted for b-frags)
__device__ __align__(16) unsigned g_q[8*N_*32];
__device__ __align__(16) unsigned g_k[8*N_*32];
// v: [bh][dim][key] bf16 hi/lo, key-permuted within 16-key blocks
__device__ __align__(16) unsigned short g_vhi[8*DH*N_];
__device__ __align__(16) unsigned short g_vlo[8*DH*N_];
__device__ __align__(16) float g_ao[B_*N_*DIM];

// ---------------- helpers ----------------------------------------------------
__device__ __forceinline__ unsigned long long pack2(float a, float b) {
    unsigned long long r;
    asm("mov.b64 %0, {%1,%2};" : "=l"(r) : "f"(a), "f"(b));
    return r;
}
__device__ __forceinline__ float2 unpack2(unsigned long long v) {
    float2 f;
    asm("mov.b64 {%0,%1}, %2;" : "=f"(f.x), "=f"(f.y) : "l"(v));
    return f;
}
__device__ __forceinline__ unsigned long long ffma2(unsigned long long a,
                                                    unsigned long long b,
                                                    unsigned long long c) {
    unsigned long long d;
    asm("fma.rn.f32x2 %0, %1, %2, %3;" : "=l"(d) : "l"(a), "l"(b), "l"(c));
    return d;
}
__device__ __forceinline__ float ex2(float x) {
    float r;
    asm("ex2.approx.ftz.f32 %0, %1;" : "=f"(r) : "f"(x));
    return r;
}
// pack two floats to bf16x2: lo -> lower half, hi -> upper half
__device__ __forceinline__ unsigned packbf(float lo, float hi) {
    unsigned d;
    asm("cvt.rn.bf16x2.f32 %0, %1, %2;" : "=r"(d) : "f"(hi), "f"(lo));
    return d;
}
__device__ __forceinline__ float bf_lo(unsigned u) { return __uint_as_float(u << 16); }
__device__ __forceinline__ float bf_hi(unsigned u) { return __uint_as_float(u & 0xffff0000u); }

// m16n8k16 bf16 mma, fp32 accumulate
#define MMA16(c, a0,a1,a2,a3, b0, b1)                                          \
    asm volatile("mma.sync.aligned.m16n8k16.row.col.f32.bf16.bf16.f32 "        \
                 "{%0,%1,%2,%3},{%4,%5,%6,%7},{%8,%9},{%0,%1,%2,%3};"          \
                 : "+f"(c[0]), "+f"(c[1]), "+f"(c[2]), "+f"(c[3])              \
                 : "r"(a0), "r"(a1), "r"(a2), "r"(a3), "r"(b0), "r"(b1))

// dim-pair permutation within an 8-slot k-step block: (t, t+4) adjacent
__device__ __forceinline__ int perm8(int t) { return (t < 4) ? 2*t : 2*(t-4)+1; }

// ---------------------------------------------------------------------------
// Kernel A: qkv = x @ w_qkv, L2-norm q,k, bf16 hi/lo splits, mma-ready layouts.
// 128 blocks x 192 threads. Inner loop: LDS.128 on both w and x, f32x2 FMA.
// ---------------------------------------------------------------------------
__global__ void __launch_bounds__(192) qkv_kernel(const float* __restrict__ x,
                                                  const float* __restrict__ w) {
    extern __shared__ float smA[];
    unsigned long long* ws = (unsigned long long*)smA;              // [c2][192][2]
    unsigned long long* xs = (unsigned long long*)(smA + C_*QKV);   // [8][128] dup pairs

    const int tid = threadIdx.x;
    // stage w: global [c][192 pairs] -> smem [(c>>1)*384 + j*2 + (c&1)]
    const unsigned long long* wg = (const unsigned long long*)w;
    for (int c = 0; c < C_; ++c)
        ws[(c >> 1) * 384 + tid * 2 + (c & 1)] = wg[c * 192 + tid];

    const int j = tid;
    for (int bt = 0; bt < 8; ++bt) {
        const int row0 = blockIdx.x * 64 + bt * 8;
        __syncthreads();
        for (int i = tid; i < 256; i += 192) {
            int r = i >> 5, c4 = i & 31;
            float4 v = ((const float4*)(x + (size_t)(row0 + r) * C_))[c4];
            unsigned long long* d = xs + r * 128 + c4 * 4;
            d[0] = pack2(v.x, v.x); d[1] = pack2(v.y, v.y);
            d[2] = pack2(v.z, v.z); d[3] = pack2(v.w, v.w);
        }
        __syncthreads();

        unsigned long long acc[8];
        #pragma unroll
        for (int r = 0; r < 8; ++r) acc[r] = 0ULL;
        #pragma unroll 4
        for (int c2 = 0; c2 < 64; ++c2) {
            ulonglong2 wv = ((const ulonglong2*)ws)[c2 * 192 + j];
            #pragma unroll
            for (int r = 0; r < 8; ++r) {
                ulonglong2 xv = ((const ulonglong2*)(xs + r * 128))[c2];
                acc[r] = ffma2(xv.x, wv.x, acc[r]);
                acc[r] = ffma2(xv.y, wv.y, acc[r]);
            }
        }

        #pragma unroll
        for (int r = 0; r < 8; ++r) {
            float2 a = unpack2(acc[r]);
            const int row = row0 + r, b = row >> 12, n = row & (N_ - 1);
            if (j < 128) {          // q or k: L2 norm over 16-lane head group
                float ss = a.x * a.x + a.y * a.y;
                #pragma unroll
                for (int o = 8; o; o >>= 1)
                    ss += __shfl_xor_sync(0xffffffffu, ss, o, 16);
                float inv = 1.0f / fmaxf(sqrtf(ss), 1e-12f);
                if (j < 64) inv *= C0;           // bake SCALE*log2e into q
                float vx = a.x * inv, vy = a.y * inv;
                unsigned hi = packbf(vx, vy);
                unsigned lo = packbf(vx - bf_lo(hi), vy - bf_hi(hi));
                if (j < 64) {                    // q: natural dp order
                    const int h = j >> 4, dp = j & 15;
                    unsigned* base = g_q + (((size_t)(b*NH + h) * N_ + n) * 32);
                    base[dp] = hi; base[16 + dp] = lo;
                } else {                         // k: (t,t+4)-paired dp order
                    const int jj = j - 64, h = jj >> 4, dp = jj & 15;
                    const int pos = (dp >> 3) * 8 + perm8(dp & 7);
                    unsigned* base = g_k + (((size_t)(b*NH + h) * N_ + n) * 32);
                    base[pos] = hi; base[16 + pos] = lo;
                }
            } else {                // v: [dim][key] bf16, key-permuted
                const int jj = j - 128, h = jj >> 4, d = (jj & 15) * 2;
                const int t = (n >> 1) & 7;
                const int posn = (n & ~15) + perm8(t) * 2 + (n & 1);
                size_t vb = ((size_t)(b*NH + h) * DH + d) * N_ + posn;
                unsigned hi = packbf(a.x, a.y);
                unsigned lo = packbf(a.x - bf_lo(hi), a.y - bf_hi(hi));
                g_vhi[vb]       = (unsigned short)(hi & 0xffffu);
                g_vhi[vb + N_]  = (unsigned short)(hi >> 16);
                g_vlo[vb]       = (unsigned short)(lo & 0xffffu);
                g_vlo[vb + N_]  = (unsigned short)(lo >> 16);
            }
        }
    }
}

// ---------------------------------------------------------------------------
// Kernel B: bf16 m16n8k16 flash attention, hi/lo 3-product splits, fixed
// softmax offset. grid (32, 8), 256 threads (8 warps x 16 q rows), 64-key chunks.
// ---------------------------------------------------------------------------
__global__ void __launch_bounds__(256, 2) attn_kernel() {
    __shared__ __align__(16) unsigned sK[64 * 36];   // per key: 16 hi + 16 lo words
    __shared__ __align__(16) unsigned sV[32 * 68];   // per dim: 32 hi + 32 lo words

    const int bh = blockIdx.y, tid = threadIdx.x;
    const int warp = tid >> 5, lane = tid & 31, quad = lane >> 2, qr = lane & 3;
    const int qb = blockIdx.x * 128 + warp * 16;

    // Q A-fragments (hi/lo) straight from global
    unsigned qh[2][4], ql[2][4];
    {
        const unsigned* Q0 = g_q + ((size_t)bh * N_ + qb + quad) * 32;
        const unsigned* Q8 = Q0 + 8 * 32;
        #pragma unroll
        for (int ks = 0; ks < 2; ++ks) {
            qh[ks][0] = Q0[ks*8 + qr];      qh[ks][1] = Q8[ks*8 + qr];
            qh[ks][2] = Q0[ks*8 + qr + 4];  qh[ks][3] = Q8[ks*8 + qr + 4];
            ql[ks][0] = Q0[16 + ks*8 + qr];     ql[ks][1] = Q8[16 + ks*8 + qr];
            ql[ks][2] = Q0[16 + ks*8 + qr + 4]; ql[ks][3] = Q8[16 + ks*8 + qr + 4];
        }
    }

    float o[4][4];
    #pragma unroll
    for (int nt = 0; nt < 4; ++nt)
        o[nt][0] = o[nt][1] = o[nt][2] = o[nt][3] = 0.f;
    float l0 = 0.f, l1 = 0.f;

    const uint4* Kg = (const uint4*)g_k + (size_t)bh * N_ * 8;       // 8 uint4/key
    const uint4* Vh = (const uint4*)g_vhi + (size_t)bh * DH * (N_/8); // 512 uint4/dim
    const uint4* Vl = (const uint4*)g_vlo + (size_t)bh * DH * (N_/8);

    for (int ch = 0; ch < N_ / 64; ++ch) {
        const int key0 = ch * 64;
        __syncthreads();
        #pragma unroll
        for (int i = tid; i < 512; i += 256) {
            int key = i >> 3, part = i & 7;
            *(uint4*)(sK + key * 36 + part * 4) = Kg[(size_t)(key0 + key) * 8 + part];
        }
        {
            int dm = tid >> 3, part = tid & 7;
            if (tid < 256) {
                *(uint4*)(sV + dm * 68 + part * 4)      = Vh[(size_t)dm * (N_/8) + key0/8 + part];
                *(uint4*)(sV + dm * 68 + 32 + part * 4) = Vl[(size_t)dm * (N_/8) + key0/8 + part];
            }
        }
        __syncthreads();

        // ---- QK: S tile 16 x 64, accumulator init -C0 bakes the offset
        float p[8][4];
        #pragma unroll
        for (int nt = 0; nt < 8; ++nt)
            p[nt][0] = p[nt][1] = p[nt][2] = p[nt][3] = -C0;
        #pragma unroll
        for (int ks = 0; ks < 2; ++ks) {
            #pragma unroll
            for (int nt = 0; nt < 8; ++nt) {
                const unsigned* kr = sK + (nt*8 + quad) * 36;
                uint2 bh2 = *(const uint2*)(kr + ks*8 + 2*qr);
                uint2 bl2 = *(const uint2*)(kr + 16 + ks*8 + 2*qr);
                MMA16(p[nt], qh[ks][0], qh[ks][1], qh[ks][2], qh[ks][3], bh2.x, bh2.y);
                MMA16(p[nt], ql[ks][0], ql[ks][1], ql[ks][2], ql[ks][3], bh2.x, bh2.y);
                MMA16(p[nt], qh[ks][0], qh[ks][1], qh[ks][2], qh[ks][3], bl2.x, bl2.y);
            }
        }
        // ---- exp + row-sum (no rescale: fixed offset)
        #pragma unroll
        for (int nt = 0; nt < 8; ++nt) {
            p[nt][0] = ex2(p[nt][0]); p[nt][1] = ex2(p[nt][1]);
            p[nt][2] = ex2(p[nt][2]); p[nt][3] = ex2(p[nt][3]);
            l0 += p[nt][0] + p[nt][1];
            l1 += p[nt][2] + p[nt][3];
        }
        // ---- PV: C-frag -> A-frag is pure packing (m16n8k16 property)
        #pragma unroll
        for (int kb = 0; kb < 4; ++kb) {
            const float* pa = p[2*kb];
            const float* pb = p[2*kb + 1];
            unsigned ah0 = packbf(pa[0], pa[1]);
            unsigned ah1 = packbf(pa[2], pa[3]);
            unsigned ah2 = packbf(pb[0], pb[1]);
            unsigned ah3 = packbf(pb[2], pb[3]);
            unsigned al0 = packbf(pa[0] - bf_lo(ah0), pa[1] - bf_hi(ah0));
            unsigned al1 = packbf(pa[2] - bf_lo(ah1), pa[3] - bf_hi(ah1));
            unsigned al2 = packbf(pb[0] - bf_lo(ah2), pb[1] - bf_hi(ah2));
            unsigned al3 = packbf(pb[2] - bf_lo(ah3), pb[3] - bf_hi(ah3));
            #pragma unroll
            for (int nt = 0; nt < 4; ++nt) {
                const unsigned* vr = sV + (nt*8 + quad) * 68;
                uint2 vh2 = *(const uint2*)(vr + kb*8 + 2*qr);
                uint2 vl2 = *(const uint2*)(vr + 32 + kb*8 + 2*qr);
                MMA16(o[nt], ah0, ah1, ah2, ah3, vh2.x, vh2.y);
                MMA16(o[nt], al0, al1, al2, al3, vh2.x, vh2.y);
                MMA16(o[nt], ah0, ah1, ah2, ah3, vl2.x, vl2.y);
            }
        }
    }

    // final: reduce row sums across quad threads, normalize, write
    l0 += __shfl_xor_sync(0xffffffffu, l0, 1);
    l0 += __shfl_xor_sync(0xffffffffu, l0, 2);
    l1 += __shfl_xor_sync(0xffffffffu, l1, 1);
    l1 += __shfl_xor_sync(0xffffffffu, l1, 2);
    const float i0 = 1.0f / l0, i1 = 1.0f / l1;
    const int b = bh >> 2, hh = bh & 3;
    float* op = g_ao + ((size_t)b * N_ + qb + quad) * DIM + hh * DH;
    #pragma unroll
    for (int nt = 0; nt < 4; ++nt) {
        *(float2*)(op + nt*8 + qr*2)         = make_float2(o[nt][0]*i0, o[nt][1]*i0);
        *(float2*)(op + 8*DIM + nt*8 + qr*2) = make_float2(o[nt][2]*i1, o[nt][3]*i1);
    }
}

// ---------------------------------------------------------------------------
// Kernel C: out = g_ao @ w_out + b_out. 256 blocks x 128 threads, 32 rows each.
// ---------------------------------------------------------------------------
__global__ void __launch_bounds__(128) out_kernel(const float* __restrict__ wout,
                                                  const float* __restrict__ bout,
                                                  float* __restrict__ out) {
    extern __shared__ float smC[];
    float* ws = smC;                  // [c][128]
    float* xs = smC + DIM * DIM;      // [8][128]

    const int tid = threadIdx.x;
    for (int i = tid; i < (DIM*DIM)/4; i += 128)
        ((float4*)ws)[i] = ((const float4*)wout)[i];
    const float bj = bout[tid];

    for (int bt = 0; bt < 4; ++bt) {
        const int row0 = blockIdx.x * 32 + bt * 8;
        __syncthreads();
        for (int i = tid; i < 256; i += 128) {
            int r = i >> 5, c4 = i & 31;
            ((float4*)(xs + r * 128))[c4] =
                ((const float4*)(g_ao + (size_t)(row0 + r) * DIM))[c4];
        }
        __syncthreads();
        float acc[8];
        #pragma unroll
        for (int r = 0; r < 8; ++r) acc[r] = bj;
        #pragma unroll 4
        for (int c4 = 0; c4 < 32; ++c4) {
            float wa = ws[(c4*4 + 0) * DIM + tid];
            float wb = ws[(c4*4 + 1) * DIM + tid];
            float wc = ws[(c4*4 + 2) * DIM + tid];
            float wd = ws[(c4*4 + 3) * DIM + tid];
            #pragma unroll
            for (int r = 0; r < 8; ++r) {
                float4 xv = ((const float4*)(xs + r * 128))[c4];
                acc[r] = fmaf(xv.x, wa, acc[r]);
                acc[r] = fmaf(xv.y, wb, acc[r]);
                acc[r] = fmaf(xv.z, wc, acc[r]);
                acc[r] = fmaf(xv.w, wd, acc[r]);
            }
        }
        #pragma unroll
        for (int r = 0; r < 8; ++r)
            out[(size_t)(row0 + r) * DIM + tid] = acc[r];
    }
}

// ---------------------------------------------------------------------------
extern "C" void kernel_launch(void* const* d_in, const int* in_sizes, int n_in,
                              void* d_out, int out_size) {
    const float *x = nullptr, *wqkv = nullptr, *wout = nullptr, *bout = nullptr;
    for (int i = 0; i < n_in; ++i) {
        switch (in_sizes[i]) {
            case ROWS_TOT * C_: x    = (const float*)d_in[i]; break;
            case C_ * QKV:      wqkv = (const float*)d_in[i]; break;
            case DIM * C_:      wout = (const float*)d_in[i]; break;
            case C_:            bout = (const float*)d_in[i]; break;
        }
    }
    float* out = (float*)d_out;

    const int smA = C_ * QKV * 4 + 8 * 128 * 8;    // 204800 B
    const int smC = DIM * DIM * 4 + 8 * 128 * 4;   // 69632 B
    cudaFuncSetAttribute(qkv_kernel, cudaFuncAttributeMaxDynamicSharedMemorySize, smA);
    cudaFuncSetAttribute(out_kernel, cudaFuncAttributeMaxDynamicSharedMemorySize, smC);

    qkv_kernel<<<128, 192, smA>>>(x, wqkv);
    attn_kernel<<<dim3(32, 8), 256>>>();
    out_kernel<<<256, 128, smC>>>(wout, bout, out);
}

// round 5
// speedup vs baseline: 3.4645x; 1.1511x over previous
#include <cuda_runtime.h>
#include <cuda_fp16.h>

#define B_   2
#define N_   4096
#define C_   128
#define NH   4
#define DH   32
#define DIM  128
#define QKV  384
#define ROWS_TOT (B_*N_)
#define C0 14.4269504088896340736f

// ---------------- scratch ---------------------------------------------------
// q/k: per row 16 uints bf16x2 hi + 16 lo (k dim-pair permuted for b-frags)
__device__ __align__(16) unsigned g_q[8*N_*32];
__device__ __align__(16) unsigned g_k[8*N_*32];
// v: [bh][dim][key] single fp16, key-permuted within 16-key blocks
__device__ __align__(16) unsigned short g_v[8*DH*N_];
__device__ __align__(16) float g_ao[B_*N_*DIM];

// ---------------- helpers ----------------------------------------------------
__device__ __forceinline__ unsigned long long pack2(float a, float b) {
    unsigned long long r;
    asm("mov.b64 %0, {%1,%2};" : "=l"(r) : "f"(a), "f"(b));
    return r;
}
__device__ __forceinline__ float2 unpack2(unsigned long long v) {
    float2 f;
    asm("mov.b64 {%0,%1}, %2;" : "=f"(f.x), "=f"(f.y) : "l"(v));
    return f;
}
__device__ __forceinline__ unsigned long long ffma2(unsigned long long a,
                                                    unsigned long long b,
                                                    unsigned long long c) {
    unsigned long long d;
    asm("fma.rn.f32x2 %0, %1, %2, %3;" : "=l"(d) : "l"(a), "l"(b), "l"(c));
    return d;
}
__device__ __forceinline__ float ex2(float x) {
    float r;
    asm("ex2.approx.ftz.f32 %0, %1;" : "=f"(r) : "f"(x));
    return r;
}
// pack two floats to bf16x2 (lo -> lower half)
__device__ __forceinline__ unsigned packbf(float lo, float hi) {
    unsigned d;
    asm("cvt.rn.bf16x2.f32 %0, %1, %2;" : "=r"(d) : "f"(hi), "f"(lo));
    return d;
}
__device__ __forceinline__ float bf_lo(unsigned u) { return __uint_as_float(u << 16); }
__device__ __forceinline__ float bf_hi(unsigned u) { return __uint_as_float(u & 0xffff0000u); }
// pack two floats to fp16x2 (lo -> lower half)
__device__ __forceinline__ unsigned packh(float lo, float hi) {
    unsigned d;
    asm("cvt.rn.f16x2.f32 %0, %1, %2;" : "=r"(d) : "f"(hi), "f"(lo));
    return d;
}
__device__ __forceinline__ float h_lo(unsigned u) {
    return __half2float(__ushort_as_half((unsigned short)(u & 0xffffu)));
}
__device__ __forceinline__ float h_hi(unsigned u) {
    return __half2float(__ushort_as_half((unsigned short)(u >> 16)));
}

// m16n8k16 bf16 mma, fp32 accumulate
#define MMA16(c, a0,a1,a2,a3, b0, b1)                                          \
    asm volatile("mma.sync.aligned.m16n8k16.row.col.f32.bf16.bf16.f32 "        \
                 "{%0,%1,%2,%3},{%4,%5,%6,%7},{%8,%9},{%0,%1,%2,%3};"          \
                 : "+f"(c[0]), "+f"(c[1]), "+f"(c[2]), "+f"(c[3])              \
                 : "r"(a0), "r"(a1), "r"(a2), "r"(a3), "r"(b0), "r"(b1))
// m16n8k16 fp16 mma, fp32 accumulate
#define MMA16H(c, a0,a1,a2,a3, b0, b1)                                         \
    asm volatile("mma.sync.aligned.m16n8k16.row.col.f32.f16.f16.f32 "          \
                 "{%0,%1,%2,%3},{%4,%5,%6,%7},{%8,%9},{%0,%1,%2,%3};"          \
                 : "+f"(c[0]), "+f"(c[1]), "+f"(c[2]), "+f"(c[3])              \
                 : "r"(a0), "r"(a1), "r"(a2), "r"(a3), "r"(b0), "r"(b1))

// dim/key-pair permutation within an 8-slot block: (t, t+4) adjacent
__device__ __forceinline__ int perm8(int t) { return (t < 4) ? 2*t : 2*(t-4)+1; }

// ---------------------------------------------------------------------------
// Kernel A: qkv = x @ w_qkv, L2-norm q,k, mma-ready packed layouts.
// 128 blocks x 384 threads (thread = col-pair x 4-row half) for latency hiding.
// ---------------------------------------------------------------------------
__global__ void __launch_bounds__(384) qkv_kernel(const float* __restrict__ x,
                                                  const float* __restrict__ w) {
    extern __shared__ float smA[];
    unsigned long long* ws = (unsigned long long*)smA;              // [c2][192][2]
    unsigned long long* xs = (unsigned long long*)(smA + C_*QKV);   // [8][128] dup pairs

    const int tid = threadIdx.x;
    const int j   = tid % 192;       // column pair
    const int rh  = tid / 192;       // row half (0: rows 0-3, 1: rows 4-7)

    // stage w: global [c][192 pairs] -> smem [(c>>1)*384 + j*2 + (c&1)]
    const unsigned long long* wg = (const unsigned long long*)w;
    for (int c = rh; c < C_; c += 2)
        ws[(c >> 1) * 384 + j * 2 + (c & 1)] = wg[c * 192 + j];

    for (int bt = 0; bt < 8; ++bt) {
        const int row0 = blockIdx.x * 64 + bt * 8;
        __syncthreads();
        if (tid < 256) {
            int r = tid >> 5, c4 = tid & 31;
            float4 v = ((const float4*)(x + (size_t)(row0 + r) * C_))[c4];
            unsigned long long* d = xs + r * 128 + c4 * 4;
            d[0] = pack2(v.x, v.x); d[1] = pack2(v.y, v.y);
            d[2] = pack2(v.z, v.z); d[3] = pack2(v.w, v.w);
        }
        __syncthreads();

        unsigned long long acc[4] = {0ULL, 0ULL, 0ULL, 0ULL};
        #pragma unroll 4
        for (int c2 = 0; c2 < 64; ++c2) {
            ulonglong2 wv = ((const ulonglong2*)ws)[c2 * 192 + j];
            #pragma unroll
            for (int rr = 0; rr < 4; ++rr) {
                ulonglong2 xv = ((const ulonglong2*)(xs + (rh * 4 + rr) * 128))[c2];
                acc[rr] = ffma2(xv.x, wv.x, acc[rr]);
                acc[rr] = ffma2(xv.y, wv.y, acc[rr]);
            }
        }

        #pragma unroll
        for (int rr = 0; rr < 4; ++rr) {
            float2 a = unpack2(acc[rr]);
            const int row = row0 + rh * 4 + rr, b = row >> 12, n = row & (N_ - 1);
            if (j < 128) {          // q or k: L2 norm over 16-lane head group
                float ss = a.x * a.x + a.y * a.y;
                #pragma unroll
                for (int o = 8; o; o >>= 1)
                    ss += __shfl_xor_sync(0xffffffffu, ss, o, 16);
                float inv = 1.0f / fmaxf(sqrtf(ss), 1e-12f);
                if (j < 64) inv *= C0;           // bake SCALE*log2e into q
                float vx = a.x * inv, vy = a.y * inv;
                unsigned hi = packbf(vx, vy);
                unsigned lo = packbf(vx - bf_lo(hi), vy - bf_hi(hi));
                if (j < 64) {                    // q: natural dp order
                    const int h = j >> 4, dp = j & 15;
                    unsigned* base = g_q + (((size_t)(b*NH + h) * N_ + n) * 32);
                    base[dp] = hi; base[16 + dp] = lo;
                } else {                         // k: (t,t+4)-paired dp order
                    const int jj = j - 64, h = jj >> 4, dp = jj & 15;
                    const int pos = (dp >> 3) * 8 + perm8(dp & 7);
                    unsigned* base = g_k + (((size_t)(b*NH + h) * N_ + n) * 32);
                    base[pos] = hi; base[16 + pos] = lo;
                }
            } else {                // v: [dim][key] single fp16, key-permuted
                const int jj = j - 128, h = jj >> 4, d = (jj & 15) * 2;
                const int t = (n >> 1) & 7;
                const int posn = (n & ~15) + perm8(t) * 2 + (n & 1);
                size_t vb = ((size_t)(b*NH + h) * DH + d) * N_ + posn;
                g_v[vb]      = __half_as_ushort(__float2half_rn(a.x));
                g_v[vb + N_] = __half_as_ushort(__float2half_rn(a.y));
            }
        }
    }
}

// ---------------------------------------------------------------------------
// Kernel B: flash attention. QK: bf16 3-product m16n8k16. PV: fp16 2-product
// (p hi/lo x single-fp16 v). Fixed softmax offset (scores bounded by SCALE).
// grid (32, 8), 256 threads (8 warps x 16 q rows), 64-key chunks.
// ---------------------------------------------------------------------------
__global__ void __launch_bounds__(256, 2) attn_kernel() {
    __shared__ __align__(16) unsigned sK[64 * 36];   // per key: 16 hi + 16 lo bf16x2
    __shared__ __align__(16) unsigned sV[32 * 36];   // per dim: 32 fp16x2 words

    const int bh = blockIdx.y, tid = threadIdx.x;
    const int warp = tid >> 5, lane = tid & 31, quad = lane >> 2, qr = lane & 3;
    const int qb = blockIdx.x * 128 + warp * 16;

    // Q A-fragments (hi/lo) straight from global
    unsigned qh[2][4], ql[2][4];
    {
        const unsigned* Q0 = g_q + ((size_t)bh * N_ + qb + quad) * 32;
        const unsigned* Q8 = Q0 + 8 * 32;
        #pragma unroll
        for (int ks = 0; ks < 2; ++ks) {
            qh[ks][0] = Q0[ks*8 + qr];      qh[ks][1] = Q8[ks*8 + qr];
            qh[ks][2] = Q0[ks*8 + qr + 4];  qh[ks][3] = Q8[ks*8 + qr + 4];
            ql[ks][0] = Q0[16 + ks*8 + qr];     ql[ks][1] = Q8[16 + ks*8 + qr];
            ql[ks][2] = Q0[16 + ks*8 + qr + 4]; ql[ks][3] = Q8[16 + ks*8 + qr + 4];
        }
    }

    float o[4][4];
    #pragma unroll
    for (int nt = 0; nt < 4; ++nt)
        o[nt][0] = o[nt][1] = o[nt][2] = o[nt][3] = 0.f;
    float l0 = 0.f, l1 = 0.f;

    const uint4* Kg = (const uint4*)g_k + (size_t)bh * N_ * 8;       // 8 uint4/key
    const uint4* Vg = (const uint4*)g_v + (size_t)bh * DH * (N_/8);  // 512 uint4/dim

    for (int ch = 0; ch < N_ / 64; ++ch) {
        const int key0 = ch * 64;
        __syncthreads();
        #pragma unroll
        for (int i = tid; i < 512; i += 256) {
            int key = i >> 3, part = i & 7;
            *(uint4*)(sK + key * 36 + part * 4) = Kg[(size_t)(key0 + key) * 8 + part];
        }
        {
            int dm = tid >> 3, part = tid & 7;   // 32 dims x 8 uint4 = 256 threads
            *(uint4*)(sV + dm * 36 + part * 4) = Vg[(size_t)dm * (N_/8) + key0/8 + part];
        }
        __syncthreads();

        // ---- QK: S tile 16 x 64, accumulator init -C0 bakes the offset
        float p[8][4];
        #pragma unroll
        for (int nt = 0; nt < 8; ++nt)
            p[nt][0] = p[nt][1] = p[nt][2] = p[nt][3] = -C0;
        #pragma unroll
        for (int ks = 0; ks < 2; ++ks) {
            #pragma unroll
            for (int nt = 0; nt < 8; ++nt) {
                const unsigned* kr = sK + (nt*8 + quad) * 36;
                uint2 bh2 = *(const uint2*)(kr + ks*8 + 2*qr);
                uint2 bl2 = *(const uint2*)(kr + 16 + ks*8 + 2*qr);
                MMA16(p[nt], qh[ks][0], qh[ks][1], qh[ks][2], qh[ks][3], bh2.x, bh2.y);
                MMA16(p[nt], ql[ks][0], ql[ks][1], ql[ks][2], ql[ks][3], bh2.x, bh2.y);
                MMA16(p[nt], qh[ks][0], qh[ks][1], qh[ks][2], qh[ks][3], bl2.x, bl2.y);
            }
        }
        // ---- exp + row-sum (no rescale: fixed offset)
        #pragma unroll
        for (int nt = 0; nt < 8; ++nt) {
            p[nt][0] = ex2(p[nt][0]); p[nt][1] = ex2(p[nt][1]);
            p[nt][2] = ex2(p[nt][2]); p[nt][3] = ex2(p[nt][3]);
            l0 += p[nt][0] + p[nt][1];
            l1 += p[nt][2] + p[nt][3];
        }
        // ---- PV: fp16 2-product; P C-frag -> A-frag is pure packing
        #pragma unroll
        for (int kb = 0; kb < 4; ++kb) {
            const float* pa = p[2*kb];
            const float* pb = p[2*kb + 1];
            unsigned ah0 = packh(pa[0], pa[1]);
            unsigned ah1 = packh(pa[2], pa[3]);
            unsigned ah2 = packh(pb[0], pb[1]);
            unsigned ah3 = packh(pb[2], pb[3]);
            unsigned al0 = packh(pa[0] - h_lo(ah0), pa[1] - h_hi(ah0));
            unsigned al1 = packh(pa[2] - h_lo(ah1), pa[3] - h_hi(ah1));
            unsigned al2 = packh(pb[0] - h_lo(ah2), pb[1] - h_hi(ah2));
            unsigned al3 = packh(pb[2] - h_lo(ah3), pb[3] - h_hi(ah3));
            #pragma unroll
            for (int nt = 0; nt < 4; ++nt) {
                const unsigned* vr = sV + (nt*8 + quad) * 36;
                uint2 vv = *(const uint2*)(vr + kb*8 + 2*qr);
                MMA16H(o[nt], ah0, ah1, ah2, ah3, vv.x, vv.y);
                MMA16H(o[nt], al0, al1, al2, al3, vv.x, vv.y);
            }
        }
    }

    // final: reduce row sums across quad threads, normalize, write
    l0 += __shfl_xor_sync(0xffffffffu, l0, 1);
    l0 += __shfl_xor_sync(0xffffffffu, l0, 2);
    l1 += __shfl_xor_sync(0xffffffffu, l1, 1);
    l1 += __shfl_xor_sync(0xffffffffu, l1, 2);
    const float i0 = 1.0f / l0, i1 = 1.0f / l1;
    const int b = bh >> 2, hh = bh & 3;
    float* op = g_ao + ((size_t)b * N_ + qb + quad) * DIM + hh * DH;
    #pragma unroll
    for (int nt = 0; nt < 4; ++nt) {
        *(float2*)(op + nt*8 + qr*2)         = make_float2(o[nt][0]*i0, o[nt][1]*i0);
        *(float2*)(op + 8*DIM + nt*8 + qr*2) = make_float2(o[nt][2]*i1, o[nt][3]*i1);
    }
}

// ---------------------------------------------------------------------------
// Kernel C: out = g_ao @ w_out + b_out. 256 blocks x 128 threads, 32 rows each.
// ---------------------------------------------------------------------------
__global__ void __launch_bounds__(128) out_kernel(const float* __restrict__ wout,
                                                  const float* __restrict__ bout,
                                                  float* __restrict__ out) {
    extern __shared__ float smC[];
    float* ws = smC;                  // [c][128]
    float* xs = smC + DIM * DIM;      // [8][128]

    const int tid = threadIdx.x;
    for (int i = tid; i < (DIM*DIM)/4; i += 128)
        ((float4*)ws)[i] = ((const float4*)wout)[i];
    const float bj = bout[tid];

    for (int bt = 0; bt < 4; ++bt) {
        const int row0 = blockIdx.x * 32 + bt * 8;
        __syncthreads();
        for (int i = tid; i < 256; i += 128) {
            int r = i >> 5, c4 = i & 31;
            ((float4*)(xs + r * 128))[c4] =
                ((const float4*)(g_ao + (size_t)(row0 + r) * DIM))[c4];
        }
        __syncthreads();
        float acc[8];
        #pragma unroll
        for (int r = 0; r < 8; ++r) acc[r] = bj;
        #pragma unroll 4
        for (int c4 = 0; c4 < 32; ++c4) {
            float wa = ws[(c4*4 + 0) * DIM + tid];
            float wb = ws[(c4*4 + 1) * DIM + tid];
            float wc = ws[(c4*4 + 2) * DIM + tid];
            float wd = ws[(c4*4 + 3) * DIM + tid];
            #pragma unroll
            for (int r = 0; r < 8; ++r) {
                float4 xv = ((const float4*)(xs + r * 128))[c4];
                acc[r] = fmaf(xv.x, wa, acc[r]);
                acc[r] = fmaf(xv.y, wb, acc[r]);
                acc[r] = fmaf(xv.z, wc, acc[r]);
                acc[r] = fmaf(xv.w, wd, acc[r]);
            }
        }
        #pragma unroll
        for (int r = 0; r < 8; ++r)
            out[(size_t)(row0 + r) * DIM + tid] = acc[r];
    }
}

// ---------------------------------------------------------------------------
extern "C" void kernel_launch(void* const* d_in, const int* in_sizes, int n_in,
                              void* d_out, int out_size) {
    const float *x = nullptr, *wqkv = nullptr, *wout = nullptr, *bout = nullptr;
    for (int i = 0; i < n_in; ++i) {
        switch (in_sizes[i]) {
            case ROWS_TOT * C_: x    = (const float*)d_in[i]; break;
            case C_ * QKV:      wqkv = (const float*)d_in[i]; break;
            case DIM * C_:      wout = (const float*)d_in[i]; break;
            case C_:            bout = (const float*)d_in[i]; break;
        }
    }
    float* out = (float*)d_out;

    const int smA = C_ * QKV * 4 + 8 * 128 * 8;    // 204800 B
    const int smC = DIM * DIM * 4 + 8 * 128 * 4;   // 69632 B
    cudaFuncSetAttribute(qkv_kernel, cudaFuncAttributeMaxDynamicSharedMemorySize, smA);
    cudaFuncSetAttribute(out_kernel, cudaFuncAttributeMaxDynamicSharedMemorySize, smC);

    qkv_kernel<<<128, 384, smA>>>(x, wqkv);
    attn_kernel<<<dim3(32, 8), 256>>>();
    out_kernel<<<256, 128, smC>>>(wout, bout, out);
}

// round 6
// speedup vs baseline: 3.8667x; 1.1161x over previous
#include <cuda_runtime.h>
#include <cuda_fp16.h>

#define B_   2
#define N_   4096
#define C_   128
#define NH   4
#define DH   32
#define DIM  128
#define QKV  384
#define ROWS_TOT (B_*N_)
#define C0 14.4269504088896340736f

// ---------------- scratch ---------------------------------------------------
// q/k: per row 16 uints bf16x2 hi + 16 lo (k dim-pair permuted for b-frags)
__device__ __align__(16) unsigned g_q[8*N_*32];
__device__ __align__(16) unsigned g_k[8*N_*32];
// v: [bh][dim][key] single fp16, key-permuted within 16-key blocks
__device__ __align__(16) unsigned short g_v[8*DH*N_];
__device__ __align__(16) float g_ao[B_*N_*DIM];

// ---------------- helpers ----------------------------------------------------
__device__ __forceinline__ float ex2(float x) {
    float r;
    asm("ex2.approx.ftz.f32 %0, %1;" : "=f"(r) : "f"(x));
    return r;
}
// pack two floats to bf16x2 (first arg -> lower half)
__device__ __forceinline__ unsigned packbf(float lo, float hi) {
    unsigned d;
    asm("cvt.rn.bf16x2.f32 %0, %1, %2;" : "=r"(d) : "f"(hi), "f"(lo));
    return d;
}
__device__ __forceinline__ float bf_lo(unsigned u) { return __uint_as_float(u << 16); }
__device__ __forceinline__ float bf_hi(unsigned u) { return __uint_as_float(u & 0xffff0000u); }
// pack two floats to fp16x2 (first arg -> lower half)
__device__ __forceinline__ unsigned packh(float lo, float hi) {
    unsigned d;
    asm("cvt.rn.f16x2.f32 %0, %1, %2;" : "=r"(d) : "f"(hi), "f"(lo));
    return d;
}
__device__ __forceinline__ float h_lo(unsigned u) {
    return __half2float(__ushort_as_half((unsigned short)(u & 0xffffu)));
}
__device__ __forceinline__ float h_hi(unsigned u) {
    return __half2float(__ushort_as_half((unsigned short)(u >> 16)));
}

// m16n8k16 bf16 mma, fp32 accumulate
#define MMA16(c, a0,a1,a2,a3, b0, b1)                                          \
    asm volatile("mma.sync.aligned.m16n8k16.row.col.f32.bf16.bf16.f32 "        \
                 "{%0,%1,%2,%3},{%4,%5,%6,%7},{%8,%9},{%0,%1,%2,%3};"          \
                 : "+f"(c[0]), "+f"(c[1]), "+f"(c[2]), "+f"(c[3])              \
                 : "r"(a0), "r"(a1), "r"(a2), "r"(a3), "r"(b0), "r"(b1))
// m16n8k16 fp16 mma, fp32 accumulate
#define MMA16H(c, a0,a1,a2,a3, b0, b1)                                         \
    asm volatile("mma.sync.aligned.m16n8k16.row.col.f32.f16.f16.f32 "          \
                 "{%0,%1,%2,%3},{%4,%5,%6,%7},{%8,%9},{%0,%1,%2,%3};"          \
                 : "+f"(c[0]), "+f"(c[1]), "+f"(c[2]), "+f"(c[3])              \
                 : "r"(a0), "r"(a1), "r"(a2), "r"(a3), "r"(b0), "r"(b1))

// pair permutation within an 8-slot block: word t -> pos so (t, t+4) adjacent
__device__ __forceinline__ int perm8(int t) { return (t < 4) ? 2*t : 2*(t-4)+1; }
// word index W (k-pair) -> permuted smem word position
__device__ __forceinline__ int pw(int W) { return (W & ~7) + perm8(W & 7); }

// ---------------------------------------------------------------------------
// Kernel A: qkv = x @ w_qkv via bf16 3-product m16n8k16 mma.
// grid (64 m, 4 n), 256 threads. Block: 128 rows x 96 cols, K=128.
// Epilogue: per-head L2 norm of q,k (quad shuffles) + packed layout stores.
// ---------------------------------------------------------------------------
__global__ void __launch_bounds__(256) qkv_kernel(const float* __restrict__ x,
                                                  const float* __restrict__ w) {
    extern __shared__ unsigned smQ[];
    unsigned* As = smQ;                 // [128 rows][132 words] (64 hi | 64 lo | pad)
    unsigned* Bs = smQ + 128 * 132;     // [96 n][132 words]
    unsigned short* Bs16 = (unsigned short*)Bs;

    const int tid  = threadIdx.x;
    const int row0 = blockIdx.x * 128;
    const int n0   = blockIdx.y * 96;

    // ---- stage A (x tile) as hi/lo bf16, permuted words ----
    for (int i = tid; i < 128 * 32; i += 256) {
        int r = i >> 5, c4 = i & 31;
        float4 v = ((const float4*)(x + (size_t)(row0 + r) * C_))[c4];
        unsigned h0 = packbf(v.x, v.y);
        unsigned h1 = packbf(v.z, v.w);
        unsigned l0 = packbf(v.x - bf_lo(h0), v.y - bf_hi(h0));
        unsigned l1 = packbf(v.z - bf_lo(h1), v.w - bf_hi(h1));
        unsigned* Ar = As + r * 132;
        int W0 = c4 * 2, W1 = W0 + 1;
        Ar[pw(W0)] = h0;      Ar[pw(W1)] = h1;
        Ar[64 + pw(W0)] = l0; Ar[64 + pw(W1)] = l1;
    }
    // ---- stage B (w slice, transposed) as hi/lo bf16 ushort planes ----
    for (int i = tid; i < 128 * 24; i += 256) {
        int c = i / 24, nq = i % 24;
        float4 v = *(const float4*)(w + (size_t)c * QKV + n0 + nq * 4);
        int ph = pw(c >> 1) * 2 + (c & 1);
        int pl = 128 + ph;
        float vals[4] = {v.x, v.y, v.z, v.w};
        #pragma unroll
        for (int jj = 0; jj < 4; ++jj) {
            unsigned hb = packbf(vals[jj], 0.f) & 0xffffu;
            float res = vals[jj] - __uint_as_float(hb << 16);
            unsigned lb = packbf(res, 0.f) & 0xffffu;
            unsigned short* Bn = Bs16 + (size_t)(nq * 4 + jj) * 264;
            Bn[ph] = (unsigned short)hb;
            Bn[pl] = (unsigned short)lb;
        }
    }
    __syncthreads();

    const int wp = tid >> 5, lane = tid & 31, quad = lane >> 2, qr = lane & 3;
    const int r0 = row0 + wp * 16 + quad;          // rows r0, r0+8
    const int b  = r0 >> 12;
    const int nn0 = r0 & (N_ - 1), nn1 = (r0 + 8) & (N_ - 1);

    #pragma unroll
    for (int c = 0; c < 3; ++c) {
        float o[4][4];
        #pragma unroll
        for (int nt = 0; nt < 4; ++nt)
            o[nt][0] = o[nt][1] = o[nt][2] = o[nt][3] = 0.f;

        #pragma unroll
        for (int ks = 0; ks < 8; ++ks) {
            const unsigned* ar = As + (wp * 16 + quad) * 132 + ks * 8 + qr * 2;
            uint2 ah0 = *(const uint2*)ar;                   // row quad : (klo, khi)
            uint2 ah1 = *(const uint2*)(ar + 8 * 132);       // row quad+8
            uint2 al0 = *(const uint2*)(ar + 64);
            uint2 al1 = *(const uint2*)(ar + 8 * 132 + 64);
            #pragma unroll
            for (int nt = 0; nt < 4; ++nt) {
                const unsigned* br = Bs + (c * 32 + nt * 8 + quad) * 132 + ks * 8 + qr * 2;
                uint2 bh2 = *(const uint2*)br;
                uint2 bl2 = *(const uint2*)(br + 64);
                MMA16(o[nt], ah0.x, ah1.x, ah0.y, ah1.y, bh2.x, bh2.y);
                MMA16(o[nt], al0.x, al1.x, al0.y, al1.y, bh2.x, bh2.y);
                MMA16(o[nt], ah0.x, ah1.x, ah0.y, ah1.y, bl2.x, bl2.y);
            }
        }

        // ---- epilogue ----
        const int col0 = n0 + c * 32;
        const int seg  = col0 >> 7;           // 0=q, 1=k, 2=v
        const int head = (col0 >> 5) & 3;
        const size_t bh = (size_t)(b * NH + head);

        if (seg < 2) {
            float ss0 = 0.f, ss1 = 0.f;
            #pragma unroll
            for (int nt = 0; nt < 4; ++nt) {
                ss0 += o[nt][0]*o[nt][0] + o[nt][1]*o[nt][1];
                ss1 += o[nt][2]*o[nt][2] + o[nt][3]*o[nt][3];
            }
            ss0 += __shfl_xor_sync(0xffffffffu, ss0, 1);
            ss0 += __shfl_xor_sync(0xffffffffu, ss0, 2);
            ss1 += __shfl_xor_sync(0xffffffffu, ss1, 1);
            ss1 += __shfl_xor_sync(0xffffffffu, ss1, 2);
            float inv0 = 1.0f / fmaxf(sqrtf(ss0), 1e-12f);
            float inv1 = 1.0f / fmaxf(sqrtf(ss1), 1e-12f);
            if (seg == 0) { inv0 *= C0; inv1 *= C0; }
            unsigned* base0 = (seg ? g_k : g_q) + (bh * N_ + nn0) * 32;
            unsigned* base1 = (seg ? g_k : g_q) + (bh * N_ + nn1) * 32;
            #pragma unroll
            for (int nt = 0; nt < 4; ++nt) {
                int dp  = nt * 4 + qr;
                int pos = seg ? ((dp >> 3) * 8 + perm8(dp & 7)) : dp;
                float v0 = o[nt][0] * inv0, v1 = o[nt][1] * inv0;
                unsigned hi = packbf(v0, v1);
                unsigned lo = packbf(v0 - bf_lo(hi), v1 - bf_hi(hi));
                base0[pos] = hi; base0[16 + pos] = lo;
                float v2 = o[nt][2] * inv1, v3 = o[nt][3] * inv1;
                hi = packbf(v2, v3);
                lo = packbf(v2 - bf_lo(hi), v3 - bf_hi(hi));
                base1[pos] = hi; base1[16 + pos] = lo;
            }
        } else {
            const int pk0 = (nn0 & ~15) + perm8((nn0 >> 1) & 7) * 2 + (nn0 & 1);
            const int pk1 = (nn1 & ~15) + perm8((nn1 >> 1) & 7) * 2 + (nn1 & 1);
            #pragma unroll
            for (int nt = 0; nt < 4; ++nt) {
                int d = nt * 8 + qr * 2;
                unsigned short* vb = g_v + (bh * DH + d) * N_;
                vb[pk0]      = __half_as_ushort(__float2half_rn(o[nt][0]));
                vb[N_ + pk0] = __half_as_ushort(__float2half_rn(o[nt][1]));
                vb[pk1]      = __half_as_ushort(__float2half_rn(o[nt][2]));
                vb[N_ + pk1] = __half_as_ushort(__float2half_rn(o[nt][3]));
            }
        }
    }
}

// ---------------------------------------------------------------------------
// Kernel B: flash attention. QK: bf16 3-product m16n8k16. PV: fp16 2-product
// (p hi/lo x single-fp16 v). Fixed softmax offset (scores bounded by SCALE).
// grid (32, 8), 256 threads (8 warps x 16 q rows), 64-key chunks.
// ---------------------------------------------------------------------------
__global__ void __launch_bounds__(256, 2) attn_kernel() {
    __shared__ __align__(16) unsigned sK[64 * 36];   // per key: 16 hi + 16 lo bf16x2
    __shared__ __align__(16) unsigned sV[32 * 36];   // per dim: 32 fp16x2 words

    const int bh = blockIdx.y, tid = threadIdx.x;
    const int warp = tid >> 5, lane = tid & 31, quad = lane >> 2, qr = lane & 3;
    const int qb = blockIdx.x * 128 + warp * 16;

    // Q A-fragments (hi/lo) straight from global
    unsigned qh[2][4], ql[2][4];
    {
        const unsigned* Q0 = g_q + ((size_t)bh * N_ + qb + quad) * 32;
        const unsigned* Q8 = Q0 + 8 * 32;
        #pragma unroll
        for (int ks = 0; ks < 2; ++ks) {
            qh[ks][0] = Q0[ks*8 + qr];      qh[ks][1] = Q8[ks*8 + qr];
            qh[ks][2] = Q0[ks*8 + qr + 4];  qh[ks][3] = Q8[ks*8 + qr + 4];
            ql[ks][0] = Q0[16 + ks*8 + qr];     ql[ks][1] = Q8[16 + ks*8 + qr];
            ql[ks][2] = Q0[16 + ks*8 + qr + 4]; ql[ks][3] = Q8[16 + ks*8 + qr + 4];
        }
    }

    float o[4][4];
    #pragma unroll
    for (int nt = 0; nt < 4; ++nt)
        o[nt][0] = o[nt][1] = o[nt][2] = o[nt][3] = 0.f;
    float l0 = 0.f, l1 = 0.f;

    const uint4* Kg = (const uint4*)g_k + (size_t)bh * N_ * 8;       // 8 uint4/key
    const uint4* Vg = (const uint4*)g_v + (size_t)bh * DH * (N_/8);  // 512 uint4/dim

    for (int ch = 0; ch < N_ / 64; ++ch) {
        const int key0 = ch * 64;
        __syncthreads();
        #pragma unroll
        for (int i = tid; i < 512; i += 256) {
            int key = i >> 3, part = i & 7;
            *(uint4*)(sK + key * 36 + part * 4) = Kg[(size_t)(key0 + key) * 8 + part];
        }
        {
            int dm = tid >> 3, part = tid & 7;   // 32 dims x 8 uint4 = 256 threads
            *(uint4*)(sV + dm * 36 + part * 4) = Vg[(size_t)dm * (N_/8) + key0/8 + part];
        }
        __syncthreads();

        // ---- QK: S tile 16 x 64, accumulator init -C0 bakes the offset
        float p[8][4];
        #pragma unroll
        for (int nt = 0; nt < 8; ++nt)
            p[nt][0] = p[nt][1] = p[nt][2] = p[nt][3] = -C0;
        #pragma unroll
        for (int ks = 0; ks < 2; ++ks) {
            #pragma unroll
            for (int nt = 0; nt < 8; ++nt) {
                const unsigned* kr = sK + (nt*8 + quad) * 36;
                uint2 bh2 = *(const uint2*)(kr + ks*8 + 2*qr);
                uint2 bl2 = *(const uint2*)(kr + 16 + ks*8 + 2*qr);
                MMA16(p[nt], qh[ks][0], qh[ks][1], qh[ks][2], qh[ks][3], bh2.x, bh2.y);
                MMA16(p[nt], ql[ks][0], ql[ks][1], ql[ks][2], ql[ks][3], bh2.x, bh2.y);
                MMA16(p[nt], qh[ks][0], qh[ks][1], qh[ks][2], qh[ks][3], bl2.x, bl2.y);
            }
        }
        // ---- exp + row-sum (no rescale: fixed offset)
        #pragma unroll
        for (int nt = 0; nt < 8; ++nt) {
            p[nt][0] = ex2(p[nt][0]); p[nt][1] = ex2(p[nt][1]);
            p[nt][2] = ex2(p[nt][2]); p[nt][3] = ex2(p[nt][3]);
            l0 += p[nt][0] + p[nt][1];
            l1 += p[nt][2] + p[nt][3];
        }
        // ---- PV: fp16 2-product; P C-frag -> A-frag is pure packing
        #pragma unroll
        for (int kb = 0; kb < 4; ++kb) {
            const float* pa = p[2*kb];
            const float* pb = p[2*kb + 1];
            unsigned ah0 = packh(pa[0], pa[1]);
            unsigned ah1 = packh(pa[2], pa[3]);
            unsigned ah2 = packh(pb[0], pb[1]);
            unsigned ah3 = packh(pb[2], pb[3]);
            unsigned al0 = packh(pa[0] - h_lo(ah0), pa[1] - h_hi(ah0));
            unsigned al1 = packh(pa[2] - h_lo(ah1), pa[3] - h_hi(ah1));
            unsigned al2 = packh(pb[0] - h_lo(ah2), pb[1] - h_hi(ah2));
            unsigned al3 = packh(pb[2] - h_lo(ah3), pb[3] - h_hi(ah3));
            #pragma unroll
            for (int nt = 0; nt < 4; ++nt) {
                const unsigned* vr = sV + (nt*8 + quad) * 36;
                uint2 vv = *(const uint2*)(vr + kb*8 + 2*qr);
                MMA16H(o[nt], ah0, ah1, ah2, ah3, vv.x, vv.y);
                MMA16H(o[nt], al0, al1, al2, al3, vv.x, vv.y);
            }
        }
    }

    // final: reduce row sums across quad threads, normalize, write
    l0 += __shfl_xor_sync(0xffffffffu, l0, 1);
    l0 += __shfl_xor_sync(0xffffffffu, l0, 2);
    l1 += __shfl_xor_sync(0xffffffffu, l1, 1);
    l1 += __shfl_xor_sync(0xffffffffu, l1, 2);
    const float i0 = 1.0f / l0, i1 = 1.0f / l1;
    const int b = bh >> 2, hh = bh & 3;
    float* op = g_ao + ((size_t)b * N_ + qb + quad) * DIM + hh * DH;
    #pragma unroll
    for (int nt = 0; nt < 4; ++nt) {
        *(float2*)(op + nt*8 + qr*2)         = make_float2(o[nt][0]*i0, o[nt][1]*i0);
        *(float2*)(op + 8*DIM + nt*8 + qr*2) = make_float2(o[nt][2]*i1, o[nt][3]*i1);
    }
}

// ---------------------------------------------------------------------------
// Kernel C: out = g_ao @ w_out + b_out. 256 blocks x 128 threads, 32 rows each.
// ---------------------------------------------------------------------------
__global__ void __launch_bounds__(128) out_kernel(const float* __restrict__ wout,
                                                  const float* __restrict__ bout,
                                                  float* __restrict__ out) {
    extern __shared__ float smC[];
    float* ws = smC;                  // [c][128]
    float* xs = smC + DIM * DIM;      // [8][128]

    const int tid = threadIdx.x;
    for (int i = tid; i < (DIM*DIM)/4; i += 128)
        ((float4*)ws)[i] = ((const float4*)wout)[i];
    const float bj = bout[tid];

    for (int bt = 0; bt < 4; ++bt) {
        const int row0 = blockIdx.x * 32 + bt * 8;
        __syncthreads();
        for (int i = tid; i < 256; i += 128) {
            int r = i >> 5, c4 = i & 31;
            ((float4*)(xs + r * 128))[c4] =
                ((const float4*)(g_ao + (size_t)(row0 + r) * DIM))[c4];
        }
        __syncthreads();
        float acc[8];
        #pragma unroll
        for (int r = 0; r < 8; ++r) acc[r] = bj;
        #pragma unroll 4
        for (int c4 = 0; c4 < 32; ++c4) {
            float wa = ws[(c4*4 + 0) * DIM + tid];
            float wb = ws[(c4*4 + 1) * DIM + tid];
            float wc = ws[(c4*4 + 2) * DIM + tid];
            float wd = ws[(c4*4 + 3) * DIM + tid];
            #pragma unroll
            for (int r = 0; r < 8; ++r) {
                float4 xv = ((const float4*)(xs + r * 128))[c4];
                acc[r] = fmaf(xv.x, wa, acc[r]);
                acc[r] = fmaf(xv.y, wb, acc[r]);
                acc[r] = fmaf(xv.z, wc, acc[r]);
                acc[r] = fmaf(xv.w, wd, acc[r]);
            }
        }
        #pragma unroll
        for (int r = 0; r < 8; ++r)
            out[(size_t)(row0 + r) * DIM + tid] = acc[r];
    }
}

// ---------------------------------------------------------------------------
extern "C" void kernel_launch(void* const* d_in, const int* in_sizes, int n_in,
                              void* d_out, int out_size) {
    const float *x = nullptr, *wqkv = nullptr, *wout = nullptr, *bout = nullptr;
    for (int i = 0; i < n_in; ++i) {
        switch (in_sizes[i]) {
            case ROWS_TOT * C_: x    = (const float*)d_in[i]; break;
            case C_ * QKV:      wqkv = (const float*)d_in[i]; break;
            case DIM * C_:      wout = (const float*)d_in[i]; break;
            case C_:            bout = (const float*)d_in[i]; break;
        }
    }
    float* out = (float*)d_out;

    const int smA = (128 * 132 + 96 * 132) * 4;    // 118272 B
    const int smC = DIM * DIM * 4 + 8 * 128 * 4;   // 69632 B
    cudaFuncSetAttribute(qkv_kernel, cudaFuncAttributeMaxDynamicSharedMemorySize, smA);
    cudaFuncSetAttribute(out_kernel, cudaFuncAttributeMaxDynamicSharedMemorySize, smC);

    qkv_kernel<<<dim3(64, 4), 256, smA>>>(x, wqkv);
    attn_kernel<<<dim3(32, 8), 256>>>();
    out_kernel<<<256, 128, smC>>>(wout, bout, out);
}

// round 8
// speedup vs baseline: 3.9423x; 1.0195x over previous
#include <cuda_runtime.h>
#include <cuda_fp16.h>
#include <cstdint>

#define B_   2
#define N_   4096
#define C_   128
#define NH   4
#define DH   32
#define DIM  128
#define QKV  384
#define ROWS_TOT (B_*N_)
#define C0 14.4269504088896340736f

// ---------------- scratch ---------------------------------------------------
// q/k: per row 16 uints bf16x2 hi + 16 lo (k dim-pair permuted for b-frags)
__device__ __align__(16) unsigned g_q[8*N_*32];
__device__ __align__(16) unsigned g_k[8*N_*32];
// v: [bh][dim][key] single fp16, key-permuted within 16-key blocks
__device__ __align__(16) unsigned short g_v[8*DH*N_];
__device__ __align__(16) float g_ao[B_*N_*DIM];

// ---------------- helpers ----------------------------------------------------
__device__ __forceinline__ float ex2(float x) {
    float r; asm("ex2.approx.ftz.f32 %0, %1;" : "=f"(r) : "f"(x)); return r;
}
__device__ __forceinline__ unsigned packbf(float lo, float hi) {
    unsigned d; asm("cvt.rn.bf16x2.f32 %0, %1, %2;" : "=r"(d) : "f"(hi), "f"(lo)); return d;
}
__device__ __forceinline__ float bf_lo(unsigned u) { return __uint_as_float(u << 16); }
__device__ __forceinline__ float bf_hi(unsigned u) { return __uint_as_float(u & 0xffff0000u); }
__device__ __forceinline__ unsigned packh(float lo, float hi) {
    unsigned d; asm("cvt.rn.f16x2.f32 %0, %1, %2;" : "=r"(d) : "f"(hi), "f"(lo)); return d;
}
__device__ __forceinline__ float h_lo(unsigned u) {
    return __half2float(__ushort_as_half((unsigned short)(u & 0xffffu)));
}
__device__ __forceinline__ float h_hi(unsigned u) {
    return __half2float(__ushort_as_half((unsigned short)(u >> 16)));
}
__device__ __forceinline__ uint32_t smem_u32(const void* p) {
    uint32_t a;
    asm("{ .reg .u64 t; cvta.to.shared.u64 t, %1; cvt.u32.u64 %0, t; }" : "=r"(a) : "l"(p));
    return a;
}
__device__ __forceinline__ void cpa16(uint32_t dst, const void* src) {
    asm volatile("cp.async.cg.shared.global [%0], [%1], 16;" :: "r"(dst), "l"(src));
}
#define CPA_COMMIT() asm volatile("cp.async.commit_group;" ::: "memory")
#define CPA_WAIT1()  asm volatile("cp.async.wait_group 1;" ::: "memory")
#define CPA_WAIT0()  asm volatile("cp.async.wait_group 0;" ::: "memory")

// m16n8k16 bf16 mma, fp32 accumulate
#define MMA16(c, a0,a1,a2,a3, b0, b1)                                          \
    asm volatile("mma.sync.aligned.m16n8k16.row.col.f32.bf16.bf16.f32 "        \
                 "{%0,%1,%2,%3},{%4,%5,%6,%7},{%8,%9},{%0,%1,%2,%3};"          \
                 : "+f"(c[0]), "+f"(c[1]), "+f"(c[2]), "+f"(c[3])              \
                 : "r"(a0), "r"(a1), "r"(a2), "r"(a3), "r"(b0), "r"(b1))
// m16n8k16 fp16 mma, fp32 accumulate
#define MMA16H(c, a0,a1,a2,a3, b0, b1)                                         \
    asm volatile("mma.sync.aligned.m16n8k16.row.col.f32.f16.f16.f32 "          \
                 "{%0,%1,%2,%3},{%4,%5,%6,%7},{%8,%9},{%0,%1,%2,%3};"          \
                 : "+f"(c[0]), "+f"(c[1]), "+f"(c[2]), "+f"(c[3])              \
                 : "r"(a0), "r"(a1), "r"(a2), "r"(a3), "r"(b0), "r"(b1))

// pair permutation within an 8-slot block: (t, t+4) adjacent
__device__ __forceinline__ int perm8(int t) { return (t < 4) ? 2*t : 2*(t-4)+1; }
__device__ __forceinline__ int pw(int W) { return (W & ~7) + perm8(W & 7); }

// ---------------------------------------------------------------------------
// Kernel A: qkv = x @ w_qkv via bf16 3-product m16n8k16 mma.
// grid (64 m, 6 n), 256 threads. Block: 128 rows x 64 cols, K=128.
// 101KB smem -> 2 CTAs/SM. Epilogue: L2 norm + attn-ready packed layouts.
// ---------------------------------------------------------------------------
__global__ void __launch_bounds__(256) qkv_kernel(const float* __restrict__ x,
                                                  const float* __restrict__ w) {
    extern __shared__ unsigned smQ[];
    unsigned* As = smQ;                 // [128 rows][132 words]
    unsigned* Bs = smQ + 128 * 132;     // [64 n][132 words]
    unsigned short* Bs16 = (unsigned short*)Bs;

    const int tid  = threadIdx.x;
    const int row0 = blockIdx.x * 128;
    const int n0   = blockIdx.y * 64;

    // ---- stage A (x tile) as hi/lo bf16, permuted words ----
    for (int i = tid; i < 128 * 32; i += 256) {
        int r = i >> 5, c4 = i & 31;
        float4 v = ((const float4*)(x + (size_t)(row0 + r) * C_))[c4];
        unsigned h0 = packbf(v.x, v.y);
        unsigned h1 = packbf(v.z, v.w);
        unsigned l0 = packbf(v.x - bf_lo(h0), v.y - bf_hi(h0));
        unsigned l1 = packbf(v.z - bf_lo(h1), v.w - bf_hi(h1));
        unsigned* Ar = As + r * 132;
        int W0 = c4 * 2, W1 = W0 + 1;
        Ar[pw(W0)] = h0;      Ar[pw(W1)] = h1;
        Ar[64 + pw(W0)] = l0; Ar[64 + pw(W1)] = l1;
    }
    // ---- stage B (w slice, transposed) as hi/lo bf16 ushort planes ----
    for (int i = tid; i < 128 * 16; i += 256) {
        int c = i >> 4, nq = i & 15;
        float4 v = *(const float4*)(w + (size_t)c * QKV + n0 + nq * 4);
        int ph = pw(c >> 1) * 2 + (c & 1);
        int pl = 128 + ph;
        float vals[4] = {v.x, v.y, v.z, v.w};
        #pragma unroll
        for (int jj = 0; jj < 4; ++jj) {
            unsigned hb = packbf(vals[jj], 0.f) & 0xffffu;
            float res = vals[jj] - __uint_as_float(hb << 16);
            unsigned lb = packbf(res, 0.f) & 0xffffu;
            unsigned short* Bn = Bs16 + (size_t)(nq * 4 + jj) * 264;
            Bn[ph] = (unsigned short)hb;
            Bn[pl] = (unsigned short)lb;
        }
    }
    __syncthreads();

    const int wp = tid >> 5, lane = tid & 31, quad = lane >> 2, qr = lane & 3;
    const int r0 = row0 + wp * 16 + quad;
    const int b  = r0 >> 12;
    const int nn0 = r0 & (N_ - 1), nn1 = (r0 + 8) & (N_ - 1);

    #pragma unroll
    for (int c = 0; c < 2; ++c) {
        float o[4][4];
        #pragma unroll
        for (int nt = 0; nt < 4; ++nt)
            o[nt][0] = o[nt][1] = o[nt][2] = o[nt][3] = 0.f;

        #pragma unroll
        for (int ks = 0; ks < 8; ++ks) {
            const unsigned* ar = As + (wp * 16 + quad) * 132 + ks * 8 + qr * 2;
            uint2 ah0 = *(const uint2*)ar;
            uint2 ah1 = *(const uint2*)(ar + 8 * 132);
            uint2 al0 = *(const uint2*)(ar + 64);
            uint2 al1 = *(const uint2*)(ar + 8 * 132 + 64);
            #pragma unroll
            for (int nt = 0; nt < 4; ++nt) {
                const unsigned* br = Bs + (c * 32 + nt * 8 + quad) * 132 + ks * 8 + qr * 2;
                uint2 bh2 = *(const uint2*)br;
                uint2 bl2 = *(const uint2*)(br + 64);
                MMA16(o[nt], ah0.x, ah1.x, ah0.y, ah1.y, bh2.x, bh2.y);
                MMA16(o[nt], al0.x, al1.x, al0.y, al1.y, bh2.x, bh2.y);
                MMA16(o[nt], ah0.x, ah1.x, ah0.y, ah1.y, bl2.x, bl2.y);
            }
        }

        const int col0 = n0 + c * 32;
        const int seg  = col0 >> 7;           // 0=q, 1=k, 2=v
        const int head = (col0 >> 5) & 3;
        const size_t bh = (size_t)(b * NH + head);

        if (seg < 2) {
            float ss0 = 0.f, ss1 = 0.f;
            #pragma unroll
            for (int nt = 0; nt < 4; ++nt) {
                ss0 += o[nt][0]*o[nt][0] + o[nt][1]*o[nt][1];
                ss1 += o[nt][2]*o[nt][2] + o[nt][3]*o[nt][3];
            }
            ss0 += __shfl_xor_sync(0xffffffffu, ss0, 1);
            ss0 += __shfl_xor_sync(0xffffffffu, ss0, 2);
            ss1 += __shfl_xor_sync(0xffffffffu, ss1, 1);
            ss1 += __shfl_xor_sync(0xffffffffu, ss1, 2);
            float inv0 = 1.0f / fmaxf(sqrtf(ss0), 1e-12f);
            float inv1 = 1.0f / fmaxf(sqrtf(ss1), 1e-12f);
            if (seg == 0) { inv0 *= C0; inv1 *= C0; }
            unsigned* base0 = (seg ? g_k : g_q) + (bh * N_ + nn0) * 32;
            unsigned* base1 = (seg ? g_k : g_q) + (bh * N_ + nn1) * 32;
            #pragma unroll
            for (int nt = 0; nt < 4; ++nt) {
                int dp  = nt * 4 + qr;
                int pos = seg ? ((dp >> 3) * 8 + perm8(dp & 7)) : dp;
                float v0 = o[nt][0] * inv0, v1 = o[nt][1] * inv0;
                unsigned hi = packbf(v0, v1);
                unsigned lo = packbf(v0 - bf_lo(hi), v1 - bf_hi(hi));
                base0[pos] = hi; base0[16 + pos] = lo;
                float v2 = o[nt][2] * inv1, v3 = o[nt][3] * inv1;
                hi = packbf(v2, v3);
                lo = packbf(v2 - bf_lo(hi), v3 - bf_hi(hi));
                base1[pos] = hi; base1[16 + pos] = lo;
            }
        } else {
            const int pk0 = (nn0 & ~15) + perm8((nn0 >> 1) & 7) * 2 + (nn0 & 1);
            const int pk1 = (nn1 & ~15) + perm8((nn1 >> 1) & 7) * 2 + (nn1 & 1);
            #pragma unroll
            for (int nt = 0; nt < 4; ++nt) {
                int d = nt * 8 + qr * 2;
                unsigned short* vb = g_v + (bh * DH + d) * N_;
                vb[pk0]      = __half_as_ushort(__float2half_rn(o[nt][0]));
                vb[N_ + pk0] = __half_as_ushort(__float2half_rn(o[nt][1]));
                vb[pk1]      = __half_as_ushort(__float2half_rn(o[nt][2]));
                vb[N_ + pk1] = __half_as_ushort(__float2half_rn(o[nt][3]));
            }
        }
    }
}

// ---------------------------------------------------------------------------
// Kernel B: flash attention, cp.async double-buffered. QK bf16 3-product,
// PV fp16 2-product, fixed softmax offset. grid (64, 8), 128 threads
// (4 warps x 16 q rows), 64-key chunks processed in two 32-key halves.
// ---------------------------------------------------------------------------
__global__ void __launch_bounds__(128, 6) attn_kernel() {
    __shared__ __align__(16) unsigned sK[2][64 * 36];
    __shared__ __align__(16) unsigned sV[2][32 * 36];

    const int bh = blockIdx.y, tid = threadIdx.x;
    const int warp = tid >> 5, lane = tid & 31, quad = lane >> 2, qr = lane & 3;
    const int qb = blockIdx.x * 64 + warp * 16;

    // Q A-fragments (hi/lo) straight from global
    unsigned qh[2][4], ql[2][4];
    {
        const unsigned* Q0 = g_q + ((size_t)bh * N_ + qb + quad) * 32;
        const unsigned* Q8 = Q0 + 8 * 32;
        #pragma unroll
        for (int ks = 0; ks < 2; ++ks) {
            qh[ks][0] = Q0[ks*8 + qr];      qh[ks][1] = Q8[ks*8 + qr];
            qh[ks][2] = Q0[ks*8 + qr + 4];  qh[ks][3] = Q8[ks*8 + qr + 4];
            ql[ks][0] = Q0[16 + ks*8 + qr];     ql[ks][1] = Q8[16 + ks*8 + qr];
            ql[ks][2] = Q0[16 + ks*8 + qr + 4]; ql[ks][3] = Q8[16 + ks*8 + qr + 4];
        }
    }

    float o[4][4];
    #pragma unroll
    for (int nt = 0; nt < 4; ++nt)
        o[nt][0] = o[nt][1] = o[nt][2] = o[nt][3] = 0.f;
    float l0 = 0.f, l1 = 0.f;

    const uint4* Kg = (const uint4*)g_k + (size_t)bh * N_ * 8;       // 8 uint4/key
    const uint4* Vg = (const uint4*)g_v + (size_t)bh * DH * (N_/8);  // 512 uint4/dim
    const uint32_t sKa = smem_u32(sK), sVa = smem_u32(sV);

    // ---- cp.async staging of one 64-key chunk into buffer buf ----
    #define STAGE(ch, buf) do {                                                \
        const int _k0 = (ch) * 64;                                             \
        const uint32_t _kb = sKa + (unsigned)(buf) * 9216u;                    \
        const uint32_t _vb = sVa + (unsigned)(buf) * 4608u;                    \
        _Pragma("unroll")                                                      \
        for (int _i = tid; _i < 512; _i += 128) {                              \
            int _key = _i >> 3, _p = _i & 7;                                   \
            cpa16(_kb + (uint32_t)(_key * 144 + _p * 16),                      \
                  Kg + (size_t)(_k0 + _key) * 8 + _p);                         \
        }                                                                      \
        _Pragma("unroll")                                                      \
        for (int _i = tid; _i < 256; _i += 128) {                              \
            int _dm = _i >> 3, _p = _i & 7;                                    \
            cpa16(_vb + (uint32_t)(_dm * 144 + _p * 16),                       \
                  Vg + (size_t)_dm * (N_/8) + _k0/8 + _p);                     \
        }                                                                      \
    } while (0)

    STAGE(0, 0);
    CPA_COMMIT();

    for (int ch = 0; ch < N_ / 64; ++ch) {
        const int buf = ch & 1;
        if (ch < N_ / 64 - 1) {
            STAGE(ch + 1, buf ^ 1);
            CPA_COMMIT();
            CPA_WAIT1();
        } else {
            CPA_WAIT0();
        }
        __syncthreads();
        const unsigned* Kb = sK[buf];
        const unsigned* Vb = sV[buf];

        #pragma unroll
        for (int half = 0; half < 2; ++half) {
            // ---- QK: S sub-tile 16 x 32, accumulator init -C0 bakes offset
            float p[4][4];
            #pragma unroll
            for (int j = 0; j < 4; ++j)
                p[j][0] = p[j][1] = p[j][2] = p[j][3] = -C0;
            #pragma unroll
            for (int ks = 0; ks < 2; ++ks) {
                #pragma unroll
                for (int j = 0; j < 4; ++j) {
                    const unsigned* kr = Kb + ((half*4 + j)*8 + quad) * 36;
                    uint2 bh2 = *(const uint2*)(kr + ks*8 + 2*qr);
                    uint2 bl2 = *(const uint2*)(kr + 16 + ks*8 + 2*qr);
                    MMA16(p[j], qh[ks][0], qh[ks][1], qh[ks][2], qh[ks][3], bh2.x, bh2.y);
                    MMA16(p[j], ql[ks][0], ql[ks][1], ql[ks][2], ql[ks][3], bh2.x, bh2.y);
                    MMA16(p[j], qh[ks][0], qh[ks][1], qh[ks][2], qh[ks][3], bl2.x, bl2.y);
                }
            }
            // ---- exp + row-sum (no rescale: fixed offset)
            #pragma unroll
            for (int j = 0; j < 4; ++j) {
                p[j][0] = ex2(p[j][0]); p[j][1] = ex2(p[j][1]);
                p[j][2] = ex2(p[j][2]); p[j][3] = ex2(p[j][3]);
                l0 += p[j][0] + p[j][1];
                l1 += p[j][2] + p[j][3];
            }
            // ---- PV: fp16 2-product; P C-frag -> A-frag is pure packing
            #pragma unroll
            for (int kbl = 0; kbl < 2; ++kbl) {
                const int kbg = half * 2 + kbl;
                const float* pa = p[2*kbl];
                const float* pb = p[2*kbl + 1];
                unsigned ah0 = packh(pa[0], pa[1]);
                unsigned ah1 = packh(pa[2], pa[3]);
                unsigned ah2 = packh(pb[0], pb[1]);
                unsigned ah3 = packh(pb[2], pb[3]);
                unsigned al0 = packh(pa[0] - h_lo(ah0), pa[1] - h_hi(ah0));
                unsigned al1 = packh(pa[2] - h_lo(ah1), pa[3] - h_hi(ah1));
                unsigned al2 = packh(pb[0] - h_lo(ah2), pb[1] - h_hi(ah2));
                unsigned al3 = packh(pb[2] - h_lo(ah3), pb[3] - h_hi(ah3));
                #pragma unroll
                for (int nt = 0; nt < 4; ++nt) {
                    const unsigned* vr = Vb + (nt*8 + quad) * 36;
                    uint2 vv = *(const uint2*)(vr + kbg*8 + 2*qr);
                    MMA16H(o[nt], ah0, ah1, ah2, ah3, vv.x, vv.y);
                    MMA16H(o[nt], al0, al1, al2, al3, vv.x, vv.y);
                }
            }
        }
        __syncthreads();
    }

    // final: reduce row sums across quad threads, normalize, write
    l0 += __shfl_xor_sync(0xffffffffu, l0, 1);
    l0 += __shfl_xor_sync(0xffffffffu, l0, 2);
    l1 += __shfl_xor_sync(0xffffffffu, l1, 1);
    l1 += __shfl_xor_sync(0xffffffffu, l1, 2);
    const float i0 = 1.0f / l0, i1 = 1.0f / l1;
    const int b = bh >> 2, hh = bh & 3;
    float* op = g_ao + ((size_t)b * N_ + qb + quad) * DIM + hh * DH;
    #pragma unroll
    for (int nt = 0; nt < 4; ++nt) {
        *(float2*)(op + nt*8 + qr*2)         = make_float2(o[nt][0]*i0, o[nt][1]*i0);
        *(float2*)(op + 8*DIM + nt*8 + qr*2) = make_float2(o[nt][2]*i1, o[nt][3]*i1);
    }
}

// ---------------------------------------------------------------------------
// Kernel C: out = g_ao @ w_out + b_out. 256 blocks x 128 threads.
// ---------------------------------------------------------------------------
__global__ void __launch_bounds__(128) out_kernel(const float* __restrict__ wout,
                                                  const float* __restrict__ bout,
                                                  float* __restrict__ out) {
    extern __shared__ float smC[];
    float* ws = smC;
    float* xs = smC + DIM * DIM;

    const int tid = threadIdx.x;
    for (int i = tid; i < (DIM*DIM)/4; i += 128)
        ((float4*)ws)[i] = ((const float4*)wout)[i];
    const float bj = bout[tid];

    for (int bt = 0; bt < 4; ++bt) {
        const int row0 = blockIdx.x * 32 + bt * 8;
        __syncthreads();
        for (int i = tid; i < 256; i += 128) {
            int r = i >> 5, c4 = i & 31;
            ((float4*)(xs + r * 128))[c4] =
                ((const float4*)(g_ao + (size_t)(row0 + r) * DIM))[c4];
        }
        __syncthreads();
        float acc[8];
        #pragma unroll
        for (int r = 0; r < 8; ++r) acc[r] = bj;
        #pragma unroll 4
        for (int c4 = 0; c4 < 32; ++c4) {
            float wa = ws[(c4*4 + 0) * DIM + tid];
            float wb = ws[(c4*4 + 1) * DIM + tid];
            float wc = ws[(c4*4 + 2) * DIM + tid];
            float wd = ws[(c4*4 + 3) * DIM + tid];
            #pragma unroll
            for (int r = 0; r < 8; ++r) {
                float4 xv = ((const float4*)(xs + r * 128))[c4];
                acc[r] = fmaf(xv.x, wa, acc[r]);
                acc[r] = fmaf(xv.y, wb, acc[r]);
                acc[r] = fmaf(xv.z, wc, acc[r]);
                acc[r] = fmaf(xv.w, wd, acc[r]);
            }
        }
        #pragma unroll
        for (int r = 0; r < 8; ++r)
            out[(size_t)(row0 + r) * DIM + tid] = acc[r];
    }
}

// ---------------------------------------------------------------------------
extern "C" void kernel_launch(void* const* d_in, const int* in_sizes, int n_in,
                              void* d_out, int out_size) {
    const float *x = nullptr, *wqkv = nullptr, *wout = nullptr, *bout = nullptr;
    for (int i = 0; i < n_in; ++i) {
        switch (in_sizes[i]) {
            case ROWS_TOT * C_: x    = (const float*)d_in[i]; break;
            case C_ * QKV:      wqkv = (const float*)d_in[i]; break;
            case DIM * C_:      wout = (const float*)d_in[i]; break;
            case C_:            bout = (const float*)d_in[i]; break;
        }
    }
    float* out = (float*)d_out;

    const int smA = (128 * 132 + 64 * 132) * 4;    // 101376 B -> 2 CTAs/SM
    const int smC = DIM * DIM * 4 + 8 * 128 * 4;   // 69632 B
    cudaFuncSetAttribute(qkv_kernel, cudaFuncAttributeMaxDynamicSharedMemorySize, smA);
    cudaFuncSetAttribute(out_kernel, cudaFuncAttributeMaxDynamicSharedMemorySize, smC);

    qkv_kernel<<<dim3(64, 6), 256, smA>>>(x, wqkv);
    attn_kernel<<<dim3(64, 8), 128>>>();
    out_kernel<<<256, 128, smC>>>(wout, bout, out);
}

// round 9
// speedup vs baseline: 6.0983x; 1.5469x over previous
#include <cuda_runtime.h>
#include <cuda_fp16.h>
#include <cstdint>

#define B_   2
#define N_   4096
#define C_   128
#define NH   4
#define DH   32
#define DIM  128
#define QKV  384
#define ROWS_TOT (B_*N_)
#define C0 14.4269504088896340736f

// ---------------- scratch ---------------------------------------------------
// pre-converted x / w images (bf16 hi/lo, pair-permuted) for the qkv gemm
__device__ __align__(16) unsigned g_xc[ROWS_TOT*128];
__device__ __align__(16) unsigned g_wc[QKV*128];
// q/k: per row 16 fp16x2 words (q natural order incl. C0 scale, k pair-permuted)
__device__ __align__(16) unsigned g_q[8*N_*16];
__device__ __align__(16) unsigned g_k[8*N_*16];
// v: [bh][dim][key] fp16, key-permuted within 16-key blocks
__device__ __align__(16) unsigned short g_v[8*DH*N_];
__device__ __align__(16) float g_ao[B_*N_*DIM];

// ---------------- helpers ----------------------------------------------------
__device__ __forceinline__ float ex2(float x) {
    float r; asm("ex2.approx.ftz.f32 %0, %1;" : "=f"(r) : "f"(x)); return r;
}
__device__ __forceinline__ unsigned packbf(float lo, float hi) {
    unsigned d; asm("cvt.rn.bf16x2.f32 %0, %1, %2;" : "=r"(d) : "f"(hi), "f"(lo)); return d;
}
__device__ __forceinline__ float bf_lo(unsigned u) { return __uint_as_float(u << 16); }
__device__ __forceinline__ float bf_hi(unsigned u) { return __uint_as_float(u & 0xffff0000u); }
__device__ __forceinline__ unsigned packh(float lo, float hi) {
    unsigned d; asm("cvt.rn.f16x2.f32 %0, %1, %2;" : "=r"(d) : "f"(hi), "f"(lo)); return d;
}
__device__ __forceinline__ uint32_t smem_u32(const void* p) {
    uint32_t a;
    asm("{ .reg .u64 t; cvta.to.shared.u64 t, %1; cvt.u32.u64 %0, t; }" : "=r"(a) : "l"(p));
    return a;
}
__device__ __forceinline__ void cpa16(uint32_t dst, const void* src) {
    asm volatile("cp.async.cg.shared.global [%0], [%1], 16;" :: "r"(dst), "l"(src));
}
#define CPA_COMMIT() asm volatile("cp.async.commit_group;" ::: "memory")
#define CPA_WAIT1()  asm volatile("cp.async.wait_group 1;" ::: "memory")
#define CPA_WAIT0()  asm volatile("cp.async.wait_group 0;" ::: "memory")

// m16n8k16 bf16 mma, fp32 accumulate
#define MMA16(c, a0,a1,a2,a3, b0, b1)                                          \
    asm volatile("mma.sync.aligned.m16n8k16.row.col.f32.bf16.bf16.f32 "        \
                 "{%0,%1,%2,%3},{%4,%5,%6,%7},{%8,%9},{%0,%1,%2,%3};"          \
                 : "+f"(c[0]), "+f"(c[1]), "+f"(c[2]), "+f"(c[3])              \
                 : "r"(a0), "r"(a1), "r"(a2), "r"(a3), "r"(b0), "r"(b1))
// m16n8k16 fp16 mma, fp32 accumulate
#define MMA16H(c, a0,a1,a2,a3, b0, b1)                                         \
    asm volatile("mma.sync.aligned.m16n8k16.row.col.f32.f16.f16.f32 "          \
                 "{%0,%1,%2,%3},{%4,%5,%6,%7},{%8,%9},{%0,%1,%2,%3};"          \
                 : "+f"(c[0]), "+f"(c[1]), "+f"(c[2]), "+f"(c[3])              \
                 : "r"(a0), "r"(a1), "r"(a2), "r"(a3), "r"(b0), "r"(b1))

// pair permutation within an 8-slot block: (t, t+4) adjacent
__device__ __forceinline__ int perm8(int t) { return (t < 4) ? 2*t : 2*(t-4)+1; }
__device__ __forceinline__ int pw(int W) { return (W & ~7) + perm8(W & 7); }

// ---------------------------------------------------------------------------
// Kernel P: one-time conversion of x and w into pre-permuted bf16 hi/lo
// smem images. blocks 0..2047: x. blocks 2048..2143: w (transposed).
// ---------------------------------------------------------------------------
__global__ void __launch_bounds__(256) prep_kernel(const float* __restrict__ x,
                                                   const float* __restrict__ w) {
    const int idx = blockIdx.x * 256 + threadIdx.x;
    if (blockIdx.x < 2048) {                       // x: (row, col-pair)
        const int r = idx >> 6, W = idx & 63;
        float2 v = *(const float2*)(x + (size_t)r * C_ + W * 2);
        unsigned h = packbf(v.x, v.y);
        unsigned l = packbf(v.x - bf_lo(h), v.y - bf_hi(h));
        g_xc[(size_t)r * 128 + pw(W)]      = h;
        g_xc[(size_t)r * 128 + 64 + pw(W)] = l;
    } else {                                       // w: (n, c-pair), transpose
        const int i = idx - 2048 * 256;            // 0 .. 24575
        const int n = i >> 6, W = i & 63;
        float va = w[(size_t)(2 * W) * QKV + n];
        float vb = w[(size_t)(2 * W + 1) * QKV + n];
        unsigned h = packbf(va, vb);
        unsigned l = packbf(va - bf_lo(h), vb - bf_hi(h));
        g_wc[(size_t)n * 128 + pw(W)]      = h;
        g_wc[(size_t)n * 128 + 64 + pw(W)] = l;
    }
}

// ---------------------------------------------------------------------------
// Kernel A: qkv = x @ w_qkv via bf16 3-product m16n8k16 mma; A/B images are
// cp.async'd from the pre-converted globals. grid (64 m, 6 n), 256 threads.
// Epilogue: per-head L2 norm; q/k stored single fp16, v fp16 key-permuted.
// ---------------------------------------------------------------------------
__global__ void __launch_bounds__(256) qkv_kernel() {
    extern __shared__ unsigned smQ[];
    unsigned* As = smQ;                 // [128 rows][132 words] (64 hi | 64 lo)
    unsigned* Bs = smQ + 128 * 132;     // [64 n][132 words]

    const int tid  = threadIdx.x;
    const int row0 = blockIdx.x * 128;
    const int n0   = blockIdx.y * 64;
    const uint32_t sAa = smem_u32(As), sBa = smem_u32(Bs);

    #pragma unroll
    for (int i = tid; i < 4096; i += 256) {
        int r = i >> 5, p4 = i & 31;
        cpa16(sAa + (uint32_t)(r * 528 + p4 * 16),
              g_xc + (size_t)(row0 + r) * 128 + p4 * 4);
    }
    #pragma unroll
    for (int i = tid; i < 2048; i += 256) {
        int nq = i >> 5, p4 = i & 31;
        cpa16(sBa + (uint32_t)(nq * 528 + p4 * 16),
              g_wc + (size_t)(n0 + nq) * 128 + p4 * 4);
    }
    CPA_COMMIT();
    CPA_WAIT0();
    __syncthreads();

    const int wp = tid >> 5, lane = tid & 31, quad = lane >> 2, qr = lane & 3;
    const int r0 = row0 + wp * 16 + quad;
    const int b  = r0 >> 12;
    const int nn0 = r0 & (N_ - 1), nn1 = (r0 + 8) & (N_ - 1);

    #pragma unroll
    for (int c = 0; c < 2; ++c) {
        float o[4][4];
        #pragma unroll
        for (int nt = 0; nt < 4; ++nt)
            o[nt][0] = o[nt][1] = o[nt][2] = o[nt][3] = 0.f;

        #pragma unroll
        for (int ks = 0; ks < 8; ++ks) {
            const unsigned* ar = As + (wp * 16 + quad) * 132 + ks * 8 + qr * 2;
            uint2 ah0 = *(const uint2*)ar;
            uint2 ah1 = *(const uint2*)(ar + 8 * 132);
            uint2 al0 = *(const uint2*)(ar + 64);
            uint2 al1 = *(const uint2*)(ar + 8 * 132 + 64);
            #pragma unroll
            for (int nt = 0; nt < 4; ++nt) {
                const unsigned* br = Bs + (c * 32 + nt * 8 + quad) * 132 + ks * 8 + qr * 2;
                uint2 bh2 = *(const uint2*)br;
                uint2 bl2 = *(const uint2*)(br + 64);
                MMA16(o[nt], ah0.x, ah1.x, ah0.y, ah1.y, bh2.x, bh2.y);
                MMA16(o[nt], al0.x, al1.x, al0.y, al1.y, bh2.x, bh2.y);
                MMA16(o[nt], ah0.x, ah1.x, ah0.y, ah1.y, bl2.x, bl2.y);
            }
        }

        const int col0 = n0 + c * 32;
        const int seg  = col0 >> 7;           // 0=q, 1=k, 2=v
        const int head = (col0 >> 5) & 3;
        const size_t bhh = (size_t)(b * NH + head);

        if (seg < 2) {
            float ss0 = 0.f, ss1 = 0.f;
            #pragma unroll
            for (int nt = 0; nt < 4; ++nt) {
                ss0 += o[nt][0]*o[nt][0] + o[nt][1]*o[nt][1];
                ss1 += o[nt][2]*o[nt][2] + o[nt][3]*o[nt][3];
            }
            ss0 += __shfl_xor_sync(0xffffffffu, ss0, 1);
            ss0 += __shfl_xor_sync(0xffffffffu, ss0, 2);
            ss1 += __shfl_xor_sync(0xffffffffu, ss1, 1);
            ss1 += __shfl_xor_sync(0xffffffffu, ss1, 2);
            float inv0 = 1.0f / fmaxf(sqrtf(ss0), 1e-12f);
            float inv1 = 1.0f / fmaxf(sqrtf(ss1), 1e-12f);
            if (seg == 0) { inv0 *= C0; inv1 *= C0; }
            unsigned* base0 = (seg ? g_k : g_q) + (bhh * N_ + nn0) * 16;
            unsigned* base1 = (seg ? g_k : g_q) + (bhh * N_ + nn1) * 16;
            #pragma unroll
            for (int nt = 0; nt < 4; ++nt) {
                int dp  = nt * 4 + qr;
                int pos = seg ? ((dp >> 3) * 8 + perm8(dp & 7)) : dp;
                base0[pos] = packh(o[nt][0] * inv0, o[nt][1] * inv0);
                base1[pos] = packh(o[nt][2] * inv1, o[nt][3] * inv1);
            }
        } else {
            const int pk0 = (nn0 & ~15) + perm8((nn0 >> 1) & 7) * 2 + (nn0 & 1);
            const int pk1 = (nn1 & ~15) + perm8((nn1 >> 1) & 7) * 2 + (nn1 & 1);
            #pragma unroll
            for (int nt = 0; nt < 4; ++nt) {
                int d = nt * 8 + qr * 2;
                unsigned short* vb = g_v + (bhh * DH + d) * N_;
                vb[pk0]      = __half_as_ushort(__float2half_rn(o[nt][0]));
                vb[N_ + pk0] = __half_as_ushort(__float2half_rn(o[nt][1]));
                vb[pk1]      = __half_as_ushort(__float2half_rn(o[nt][2]));
                vb[N_ + pk1] = __half_as_ushort(__float2half_rn(o[nt][3]));
            }
        }
    }
}

// ---------------------------------------------------------------------------
// Kernel B: flash attention, all-fp16 single-product mma (32 mma / 64-key
// chunk), fixed softmax offset, cp.async double-buffered K/V.
// grid (64, 8), 128 threads (4 warps x 16 q rows).
// ---------------------------------------------------------------------------
__global__ void __launch_bounds__(128, 8) attn_kernel() {
    __shared__ __align__(16) unsigned sK[2][64 * 20];   // 16 data words/key
    __shared__ __align__(16) unsigned sV[2][32 * 36];   // 32 data words/dim

    const int bh = blockIdx.y, tid = threadIdx.x;
    const int warp = tid >> 5, lane = tid & 31, quad = lane >> 2, qr = lane & 3;
    const int qb = blockIdx.x * 64 + warp * 16;

    // Q A-fragments: single fp16, straight from global
    unsigned qf[2][4];
    {
        const unsigned* Q0 = g_q + ((size_t)bh * N_ + qb + quad) * 16;
        const unsigned* Q8 = Q0 + 8 * 16;
        #pragma unroll
        for (int ks = 0; ks < 2; ++ks) {
            qf[ks][0] = Q0[ks*8 + qr];      qf[ks][1] = Q8[ks*8 + qr];
            qf[ks][2] = Q0[ks*8 + qr + 4];  qf[ks][3] = Q8[ks*8 + qr + 4];
        }
    }

    float o[4][4];
    #pragma unroll
    for (int nt = 0; nt < 4; ++nt)
        o[nt][0] = o[nt][1] = o[nt][2] = o[nt][3] = 0.f;
    float l0 = 0.f, l1 = 0.f;

    const uint4* Kg = (const uint4*)g_k + (size_t)bh * N_ * 4;       // 4 uint4/key
    const uint4* Vg = (const uint4*)g_v + (size_t)bh * DH * (N_/8);  // 512 uint4/dim
    const uint32_t sKa = smem_u32(sK), sVa = smem_u32(sV);

    #define STAGE(ch, buf) do {                                                \
        const int _k0 = (ch) * 64;                                             \
        const uint32_t _kb = sKa + (unsigned)(buf) * 5120u;                    \
        const uint32_t _vb = sVa + (unsigned)(buf) * 4608u;                    \
        _Pragma("unroll")                                                      \
        for (int _i = tid; _i < 256; _i += 128) {                              \
            int _key = _i >> 2, _p = _i & 3;                                   \
            cpa16(_kb + (uint32_t)(_key * 80 + _p * 16),                       \
                  Kg + (size_t)(_k0 + _key) * 4 + _p);                         \
        }                                                                      \
        _Pragma("unroll")                                                      \
        for (int _i = tid; _i < 256; _i += 128) {                              \
            int _dm = _i >> 3, _p = _i & 7;                                    \
            cpa16(_vb + (uint32_t)(_dm * 144 + _p * 16),                       \
                  Vg + (size_t)_dm * (N_/8) + _k0/8 + _p);                     \
        }                                                                      \
    } while (0)

    STAGE(0, 0);
    CPA_COMMIT();

    for (int ch = 0; ch < N_ / 64; ++ch) {
        const int buf = ch & 1;
        if (ch < N_ / 64 - 1) {
            STAGE(ch + 1, buf ^ 1);
            CPA_COMMIT();
            CPA_WAIT1();
        } else {
            CPA_WAIT0();
        }
        __syncthreads();
        const unsigned* Kb = sK[buf];
        const unsigned* Vb = sV[buf];

        #pragma unroll
        for (int half = 0; half < 2; ++half) {
            // ---- QK: 16x32 sub-tile, single fp16 product, init -C0 offset
            float p[4][4];
            #pragma unroll
            for (int j = 0; j < 4; ++j)
                p[j][0] = p[j][1] = p[j][2] = p[j][3] = -C0;
            #pragma unroll
            for (int ks = 0; ks < 2; ++ks) {
                #pragma unroll
                for (int j = 0; j < 4; ++j) {
                    const unsigned* kr = Kb + ((half*4 + j)*8 + quad) * 20;
                    uint2 b2 = *(const uint2*)(kr + ks*8 + 2*qr);
                    MMA16H(p[j], qf[ks][0], qf[ks][1], qf[ks][2], qf[ks][3],
                           b2.x, b2.y);
                }
            }
            // ---- exp + row-sum (fp32, pre-rounding)
            #pragma unroll
            for (int j = 0; j < 4; ++j) {
                p[j][0] = ex2(p[j][0]); p[j][1] = ex2(p[j][1]);
                p[j][2] = ex2(p[j][2]); p[j][3] = ex2(p[j][3]);
                l0 += p[j][0] + p[j][1];
                l1 += p[j][2] + p[j][3];
            }
            // ---- PV: single fp16 product; C-frag -> A-frag is pure packing
            #pragma unroll
            for (int kbl = 0; kbl < 2; ++kbl) {
                const int kbg = half * 2 + kbl;
                const float* pa = p[2*kbl];
                const float* pb = p[2*kbl + 1];
                unsigned a0 = packh(pa[0], pa[1]);
                unsigned a1 = packh(pa[2], pa[3]);
                unsigned a2 = packh(pb[0], pb[1]);
                unsigned a3 = packh(pb[2], pb[3]);
                #pragma unroll
                for (int nt = 0; nt < 4; ++nt) {
                    const unsigned* vr = Vb + (nt*8 + quad) * 36;
                    uint2 vv = *(const uint2*)(vr + kbg*8 + 2*qr);
                    MMA16H(o[nt], a0, a1, a2, a3, vv.x, vv.y);
                }
            }
        }
        __syncthreads();
    }

    // final: reduce row sums across quad threads, normalize, write
    l0 += __shfl_xor_sync(0xffffffffu, l0, 1);
    l0 += __shfl_xor_sync(0xffffffffu, l0, 2);
    l1 += __shfl_xor_sync(0xffffffffu, l1, 1);
    l1 += __shfl_xor_sync(0xffffffffu, l1, 2);
    const float i0 = 1.0f / l0, i1 = 1.0f / l1;
    const int b = bh >> 2, hh = bh & 3;
    float* op = g_ao + ((size_t)b * N_ + qb + quad) * DIM + hh * DH;
    #pragma unroll
    for (int nt = 0; nt < 4; ++nt) {
        *(float2*)(op + nt*8 + qr*2)         = make_float2(o[nt][0]*i0, o[nt][1]*i0);
        *(float2*)(op + 8*DIM + nt*8 + qr*2) = make_float2(o[nt][2]*i1, o[nt][3]*i1);
    }
}

// ---------------------------------------------------------------------------
// Kernel C: out = g_ao @ w_out + b_out. 256 blocks x 128 threads.
// ---------------------------------------------------------------------------
__global__ void __launch_bounds__(128) out_kernel(const float* __restrict__ wout,
                                                  const float* __restrict__ bout,
                                                  float* __restrict__ out) {
    extern __shared__ float smC[];
    float* ws = smC;
    float* xs = smC + DIM * DIM;

    const int tid = threadIdx.x;
    for (int i = tid; i < (DIM*DIM)/4; i += 128)
        ((float4*)ws)[i] = ((const float4*)wout)[i];
    const float bj = bout[tid];

    for (int bt = 0; bt < 4; ++bt) {
        const int row0 = blockIdx.x * 32 + bt * 8;
        __syncthreads();
        for (int i = tid; i < 256; i += 128) {
            int r = i >> 5, c4 = i & 31;
            ((float4*)(xs + r * 128))[c4] =
                ((const float4*)(g_ao + (size_t)(row0 + r) * DIM))[c4];
        }
        __syncthreads();
        float acc[8];
        #pragma unroll
        for (int r = 0; r < 8; ++r) acc[r] = bj;
        #pragma unroll 4
        for (int c4 = 0; c4 < 32; ++c4) {
            float wa = ws[(c4*4 + 0) * DIM + tid];
            float wb = ws[(c4*4 + 1) * DIM + tid];
            float wc = ws[(c4*4 + 2) * DIM + tid];
            float wd = ws[(c4*4 + 3) * DIM + tid];
            #pragma unroll
            for (int r = 0; r < 8; ++r) {
                float4 xv = ((const float4*)(xs + r * 128))[c4];
                acc[r] = fmaf(xv.x, wa, acc[r]);
                acc[r] = fmaf(xv.y, wb, acc[r]);
                acc[r] = fmaf(xv.z, wc, acc[r]);
                acc[r] = fmaf(xv.w, wd, acc[r]);
            }
        }
        #pragma unroll
        for (int r = 0; r < 8; ++r)
            out[(size_t)(row0 + r) * DIM + tid] = acc[r];
    }
}

// ---------------------------------------------------------------------------
extern "C" void kernel_launch(void* const* d_in, const int* in_sizes, int n_in,
                              void* d_out, int out_size) {
    const float *x = nullptr, *wqkv = nullptr, *wout = nullptr, *bout = nullptr;
    for (int i = 0; i < n_in; ++i) {
        switch (in_sizes[i]) {
            case ROWS_TOT * C_: x    = (const float*)d_in[i]; break;
            case C_ * QKV:      wqkv = (const float*)d_in[i]; break;
            case DIM * C_:      wout = (const float*)d_in[i]; break;
            case C_:            bout = (const float*)d_in[i]; break;
        }
    }
    float* out = (float*)d_out;

    const int smA = (128 + 64) * 132 * 4;          // 101376 B -> 2 CTAs/SM
    const int smC = DIM * DIM * 4 + 8 * 128 * 4;   // 69632 B
    cudaFuncSetAttribute(qkv_kernel, cudaFuncAttributeMaxDynamicSharedMemorySize, smA);
    cudaFuncSetAttribute(out_kernel, cudaFuncAttributeMaxDynamicSharedMemorySize, smC);

    prep_kernel<<<2144, 256>>>(x, wqkv);
    qkv_kernel<<<dim3(64, 6), 256, smA>>>();
    attn_kernel<<<dim3(64, 8), 128>>>();
    out_kernel<<<256, 128, smC>>>(wout, bout, out);
}

// round 10
// speedup vs baseline: 6.7067x; 1.0998x over previous
#include <cuda_runtime.h>
#include <cuda_fp16.h>
#include <cstdint>

#define B_   2
#define N_   4096
#define C_   128
#define NH   4
#define DH   32
#define DIM  128
#define QKV  384
#define ROWS_TOT (B_*N_)
#define C0 14.4269504088896340736f

// ---------------- scratch ---------------------------------------------------
__device__ __align__(16) unsigned g_xc[ROWS_TOT*128];   // x as bf16 hi/lo, permuted
__device__ __align__(16) unsigned g_wc[QKV*128];        // w_qkv^T, same format
__device__ __align__(16) unsigned g_woc[DIM*128];       // w_out^T, same format
__device__ __align__(16) unsigned g_q[8*N_*16];         // fp16x2, C0-scaled
__device__ __align__(16) unsigned g_k[8*N_*16];         // fp16x2, pair-permuted
__device__ __align__(16) unsigned short g_v[8*DH*N_];   // fp16, key-permuted
// attention output as ready-to-use mma A-fragments (bf16 hi / lo planes)
__device__ __align__(16) uint4 g_aoh[512*8*32];
__device__ __align__(16) uint4 g_aol[512*8*32];

// ---------------- helpers ----------------------------------------------------
__device__ __forceinline__ float ex2(float x) {
    float r; asm("ex2.approx.ftz.f32 %0, %1;" : "=f"(r) : "f"(x)); return r;
}
__device__ __forceinline__ unsigned packbf(float lo, float hi) {
    unsigned d; asm("cvt.rn.bf16x2.f32 %0, %1, %2;" : "=r"(d) : "f"(hi), "f"(lo)); return d;
}
__device__ __forceinline__ float bf_lo(unsigned u) { return __uint_as_float(u << 16); }
__device__ __forceinline__ float bf_hi(unsigned u) { return __uint_as_float(u & 0xffff0000u); }
__device__ __forceinline__ unsigned packh(float lo, float hi) {
    unsigned d; asm("cvt.rn.f16x2.f32 %0, %1, %2;" : "=r"(d) : "f"(hi), "f"(lo)); return d;
}
__device__ __forceinline__ uint32_t smem_u32(const void* p) {
    uint32_t a;
    asm("{ .reg .u64 t; cvta.to.shared.u64 t, %1; cvt.u32.u64 %0, t; }" : "=r"(a) : "l"(p));
    return a;
}
__device__ __forceinline__ void cpa16(uint32_t dst, const void* src) {
    asm volatile("cp.async.cg.shared.global [%0], [%1], 16;" :: "r"(dst), "l"(src));
}
#define CPA_COMMIT() asm volatile("cp.async.commit_group;" ::: "memory")
#define CPA_WAIT1()  asm volatile("cp.async.wait_group 1;" ::: "memory")
#define CPA_WAIT0()  asm volatile("cp.async.wait_group 0;" ::: "memory")

#define MMA16(c, a0,a1,a2,a3, b0, b1)                                          \
    asm volatile("mma.sync.aligned.m16n8k16.row.col.f32.bf16.bf16.f32 "        \
                 "{%0,%1,%2,%3},{%4,%5,%6,%7},{%8,%9},{%0,%1,%2,%3};"          \
                 : "+f"(c[0]), "+f"(c[1]), "+f"(c[2]), "+f"(c[3])              \
                 : "r"(a0), "r"(a1), "r"(a2), "r"(a3), "r"(b0), "r"(b1))
#define MMA16H(c, a0,a1,a2,a3, b0, b1)                                         \
    asm volatile("mma.sync.aligned.m16n8k16.row.col.f32.f16.f16.f32 "          \
                 "{%0,%1,%2,%3},{%4,%5,%6,%7},{%8,%9},{%0,%1,%2,%3};"          \
                 : "+f"(c[0]), "+f"(c[1]), "+f"(c[2]), "+f"(c[3])              \
                 : "r"(a0), "r"(a1), "r"(a2), "r"(a3), "r"(b0), "r"(b1))

__device__ __forceinline__ int perm8(int t) { return (t < 4) ? 2*t : 2*(t-4)+1; }
__device__ __forceinline__ int pw(int W) { return (W & ~7) + perm8(W & 7); }

// ---------------------------------------------------------------------------
// Kernel P: one-time conversion of x, w_qkv^T, w_out^T into bf16 hi/lo images.
// ---------------------------------------------------------------------------
__global__ void __launch_bounds__(256) prep_kernel(const float* __restrict__ x,
                                                   const float* __restrict__ w,
                                                   const float* __restrict__ wo) {
    const int idx = blockIdx.x * 256 + threadIdx.x;
    if (blockIdx.x < 2048) {                       // x
        const int r = idx >> 6, W = idx & 63;
        float2 v = *(const float2*)(x + (size_t)r * C_ + W * 2);
        unsigned h = packbf(v.x, v.y);
        unsigned l = packbf(v.x - bf_lo(h), v.y - bf_hi(h));
        g_xc[(size_t)r * 128 + pw(W)]      = h;
        g_xc[(size_t)r * 128 + 64 + pw(W)] = l;
    } else if (blockIdx.x < 2144) {                // w_qkv transpose
        const int i = idx - 2048 * 256;
        const int n = i >> 6, W = i & 63;
        float va = w[(size_t)(2 * W) * QKV + n];
        float vb = w[(size_t)(2 * W + 1) * QKV + n];
        unsigned h = packbf(va, vb);
        unsigned l = packbf(va - bf_lo(h), vb - bf_hi(h));
        g_wc[(size_t)n * 128 + pw(W)]      = h;
        g_wc[(size_t)n * 128 + 64 + pw(W)] = l;
    } else {                                       // w_out transpose
        const int i = idx - 2144 * 256;
        const int n = i >> 6, W = i & 63;
        float va = wo[(size_t)(2 * W) * DIM + n];
        float vb = wo[(size_t)(2 * W + 1) * DIM + n];
        unsigned h = packbf(va, vb);
        unsigned l = packbf(va - bf_lo(h), vb - bf_hi(h));
        g_woc[(size_t)n * 128 + pw(W)]      = h;
        g_woc[(size_t)n * 128 + 64 + pw(W)] = l;
    }
}

// ---------------------------------------------------------------------------
// Kernel A: qkv = x @ w_qkv via bf16 3-product mma. grid (64 m, 6 n), 256 thr.
// ---------------------------------------------------------------------------
__global__ void __launch_bounds__(256) qkv_kernel() {
    extern __shared__ unsigned smQ[];
    unsigned* As = smQ;                 // [128 rows][132 words]
    unsigned* Bs = smQ + 128 * 132;     // [64 n][132 words]

    const int tid  = threadIdx.x;
    const int row0 = blockIdx.x * 128;
    const int n0   = blockIdx.y * 64;
    const uint32_t sAa = smem_u32(As), sBa = smem_u32(Bs);

    #pragma unroll
    for (int i = tid; i < 4096; i += 256) {
        int r = i >> 5, p4 = i & 31;
        cpa16(sAa + (uint32_t)(r * 528 + p4 * 16),
              g_xc + (size_t)(row0 + r) * 128 + p4 * 4);
    }
    #pragma unroll
    for (int i = tid; i < 2048; i += 256) {
        int nq = i >> 5, p4 = i & 31;
        cpa16(sBa + (uint32_t)(nq * 528 + p4 * 16),
              g_wc + (size_t)(n0 + nq) * 128 + p4 * 4);
    }
    CPA_COMMIT();
    CPA_WAIT0();
    __syncthreads();

    const int wp = tid >> 5, lane = tid & 31, quad = lane >> 2, qr = lane & 3;
    const int r0 = row0 + wp * 16 + quad;
    const int b  = r0 >> 12;
    const int nn0 = r0 & (N_ - 1), nn1 = (r0 + 8) & (N_ - 1);

    #pragma unroll
    for (int c = 0; c < 2; ++c) {
        float o[4][4];
        #pragma unroll
        for (int nt = 0; nt < 4; ++nt)
            o[nt][0] = o[nt][1] = o[nt][2] = o[nt][3] = 0.f;

        #pragma unroll
        for (int ks = 0; ks < 8; ++ks) {
            const unsigned* ar = As + (wp * 16 + quad) * 132 + ks * 8 + qr * 2;
            uint2 ah0 = *(const uint2*)ar;
            uint2 ah1 = *(const uint2*)(ar + 8 * 132);
            uint2 al0 = *(const uint2*)(ar + 64);
            uint2 al1 = *(const uint2*)(ar + 8 * 132 + 64);
            #pragma unroll
            for (int nt = 0; nt < 4; ++nt) {
                const unsigned* br = Bs + (c * 32 + nt * 8 + quad) * 132 + ks * 8 + qr * 2;
                uint2 bh2 = *(const uint2*)br;
                uint2 bl2 = *(const uint2*)(br + 64);
                MMA16(o[nt], ah0.x, ah1.x, ah0.y, ah1.y, bh2.x, bh2.y);
                MMA16(o[nt], al0.x, al1.x, al0.y, al1.y, bh2.x, bh2.y);
                MMA16(o[nt], ah0.x, ah1.x, ah0.y, ah1.y, bl2.x, bl2.y);
            }
        }

        const int col0 = n0 + c * 32;
        const int seg  = col0 >> 7;
        const int head = (col0 >> 5) & 3;
        const size_t bhh = (size_t)(b * NH + head);

        if (seg < 2) {
            float ss0 = 0.f, ss1 = 0.f;
            #pragma unroll
            for (int nt = 0; nt < 4; ++nt) {
                ss0 += o[nt][0]*o[nt][0] + o[nt][1]*o[nt][1];
                ss1 += o[nt][2]*o[nt][2] + o[nt][3]*o[nt][3];
            }
            ss0 += __shfl_xor_sync(0xffffffffu, ss0, 1);
            ss0 += __shfl_xor_sync(0xffffffffu, ss0, 2);
            ss1 += __shfl_xor_sync(0xffffffffu, ss1, 1);
            ss1 += __shfl_xor_sync(0xffffffffu, ss1, 2);
            float inv0 = 1.0f / fmaxf(sqrtf(ss0), 1e-12f);
            float inv1 = 1.0f / fmaxf(sqrtf(ss1), 1e-12f);
            if (seg == 0) { inv0 *= C0; inv1 *= C0; }
            unsigned* base0 = (seg ? g_k : g_q) + (bhh * N_ + nn0) * 16;
            unsigned* base1 = (seg ? g_k : g_q) + (bhh * N_ + nn1) * 16;
            #pragma unroll
            for (int nt = 0; nt < 4; ++nt) {
                int dp  = nt * 4 + qr;
                int pos = seg ? ((dp >> 3) * 8 + perm8(dp & 7)) : dp;
                base0[pos] = packh(o[nt][0] * inv0, o[nt][1] * inv0);
                base1[pos] = packh(o[nt][2] * inv1, o[nt][3] * inv1);
            }
        } else {
            const int pk0 = (nn0 & ~15) + perm8((nn0 >> 1) & 7) * 2 + (nn0 & 1);
            const int pk1 = (nn1 & ~15) + perm8((nn1 >> 1) & 7) * 2 + (nn1 & 1);
            #pragma unroll
            for (int nt = 0; nt < 4; ++nt) {
                int d = nt * 8 + qr * 2;
                unsigned short* vb = g_v + (bhh * DH + d) * N_;
                vb[pk0]      = __half_as_ushort(__float2half_rn(o[nt][0]));
                vb[N_ + pk0] = __half_as_ushort(__float2half_rn(o[nt][1]));
                vb[pk1]      = __half_as_ushort(__float2half_rn(o[nt][2]));
                vb[N_ + pk1] = __half_as_ushort(__float2half_rn(o[nt][3]));
            }
        }
    }
}

// ---------------------------------------------------------------------------
// Kernel B: flash attention, all-fp16 single-product mma, fixed softmax
// offset, cp.async double-buffered. Epilogue stores A-fragments for kernel C.
// ---------------------------------------------------------------------------
__global__ void __launch_bounds__(128, 8) attn_kernel() {
    __shared__ __align__(16) unsigned sK[2][64 * 20];
    __shared__ __align__(16) unsigned sV[2][32 * 36];

    const int bh = blockIdx.y, tid = threadIdx.x;
    const int warp = tid >> 5, lane = tid & 31, quad = lane >> 2, qr = lane & 3;
    const int qb = blockIdx.x * 64 + warp * 16;

    unsigned qf[2][4];
    {
        const unsigned* Q0 = g_q + ((size_t)bh * N_ + qb + quad) * 16;
        const unsigned* Q8 = Q0 + 8 * 16;
        #pragma unroll
        for (int ks = 0; ks < 2; ++ks) {
            qf[ks][0] = Q0[ks*8 + qr];      qf[ks][1] = Q8[ks*8 + qr];
            qf[ks][2] = Q0[ks*8 + qr + 4];  qf[ks][3] = Q8[ks*8 + qr + 4];
        }
    }

    float o[4][4];
    #pragma unroll
    for (int nt = 0; nt < 4; ++nt)
        o[nt][0] = o[nt][1] = o[nt][2] = o[nt][3] = 0.f;
    float l0 = 0.f, l1 = 0.f;

    const uint4* Kg = (const uint4*)g_k + (size_t)bh * N_ * 4;
    const uint4* Vg = (const uint4*)g_v + (size_t)bh * DH * (N_/8);
    const uint32_t sKa = smem_u32(sK), sVa = smem_u32(sV);

    #define STAGE(ch, buf) do {                                                \
        const int _k0 = (ch) * 64;                                             \
        const uint32_t _kb = sKa + (unsigned)(buf) * 5120u;                    \
        const uint32_t _vb = sVa + (unsigned)(buf) * 4608u;                    \
        _Pragma("unroll")                                                      \
        for (int _i = tid; _i < 256; _i += 128) {                              \
            int _key = _i >> 2, _p = _i & 3;                                   \
            cpa16(_kb + (uint32_t)(_key * 80 + _p * 16),                       \
                  Kg + (size_t)(_k0 + _key) * 4 + _p);                         \
        }                                                                      \
        _Pragma("unroll")                                                      \
        for (int _i = tid; _i < 256; _i += 128) {                              \
            int _dm = _i >> 3, _p = _i & 7;                                    \
            cpa16(_vb + (uint32_t)(_dm * 144 + _p * 16),                       \
                  Vg + (size_t)_dm * (N_/8) + _k0/8 + _p);                     \
        }                                                                      \
    } while (0)

    STAGE(0, 0);
    CPA_COMMIT();

    for (int ch = 0; ch < N_ / 64; ++ch) {
        const int buf = ch & 1;
        if (ch < N_ / 64 - 1) {
            STAGE(ch + 1, buf ^ 1);
            CPA_COMMIT();
            CPA_WAIT1();
        } else {
            CPA_WAIT0();
        }
        __syncthreads();
        const unsigned* Kb = sK[buf];
        const unsigned* Vb = sV[buf];

        #pragma unroll
        for (int half = 0; half < 2; ++half) {
            float p[4][4];
            #pragma unroll
            for (int j = 0; j < 4; ++j)
                p[j][0] = p[j][1] = p[j][2] = p[j][3] = -C0;
            #pragma unroll
            for (int ks = 0; ks < 2; ++ks) {
                #pragma unroll
                for (int j = 0; j < 4; ++j) {
                    const unsigned* kr = Kb + ((half*4 + j)*8 + quad) * 20;
                    uint2 b2 = *(const uint2*)(kr + ks*8 + 2*qr);
                    MMA16H(p[j], qf[ks][0], qf[ks][1], qf[ks][2], qf[ks][3],
                           b2.x, b2.y);
                }
            }
            #pragma unroll
            for (int j = 0; j < 4; ++j) {
                p[j][0] = ex2(p[j][0]); p[j][1] = ex2(p[j][1]);
                p[j][2] = ex2(p[j][2]); p[j][3] = ex2(p[j][3]);
                l0 += p[j][0] + p[j][1];
                l1 += p[j][2] + p[j][3];
            }
            #pragma unroll
            for (int kbl = 0; kbl < 2; ++kbl) {
                const int kbg = half * 2 + kbl;
                const float* pa = p[2*kbl];
                const float* pb = p[2*kbl + 1];
                unsigned a0 = packh(pa[0], pa[1]);
                unsigned a1 = packh(pa[2], pa[3]);
                unsigned a2 = packh(pb[0], pb[1]);
                unsigned a3 = packh(pb[2], pb[3]);
                #pragma unroll
                for (int nt = 0; nt < 4; ++nt) {
                    const unsigned* vr = Vb + (nt*8 + quad) * 36;
                    uint2 vv = *(const uint2*)(vr + kbg*8 + 2*qr);
                    MMA16H(o[nt], a0, a1, a2, a3, vv.x, vv.y);
                }
            }
        }
        __syncthreads();
    }

    // final: row sums, normalize, store as out-GEMM A-fragments (bf16 hi/lo)
    l0 += __shfl_xor_sync(0xffffffffu, l0, 1);
    l0 += __shfl_xor_sync(0xffffffffu, l0, 2);
    l1 += __shfl_xor_sync(0xffffffffu, l1, 1);
    l1 += __shfl_xor_sync(0xffffffffu, l1, 2);
    const float i0 = 1.0f / l0, i1 = 1.0f / l1;
    const int b = bh >> 2, hh = bh & 3;
    const int rbg = ((b << 12) + qb) >> 4;       // 16-row block index (0..511)
    #pragma unroll
    for (int nt = 0; nt < 4; ++nt) {
        const int ks = 2 * hh + (nt >> 1);
        float v0 = o[nt][0] * i0, v1 = o[nt][1] * i0;
        float v2 = o[nt][2] * i1, v3 = o[nt][3] * i1;
        unsigned h0 = packbf(v0, v1), h1 = packbf(v2, v3);
        unsigned u0 = packbf(v0 - bf_lo(h0), v1 - bf_hi(h0));
        unsigned u1 = packbf(v2 - bf_lo(h1), v3 - bf_hi(h1));
        size_t idx = (size_t)(rbg * 8 + ks) * 32 + lane;
        ((uint2*)&g_aoh[idx])[nt & 1] = make_uint2(h0, h1);
        ((uint2*)&g_aol[idx])[nt & 1] = make_uint2(u0, u1);
    }
}

// ---------------------------------------------------------------------------
// Kernel C: out = ao @ w_out + b_out via bf16 3-product mma; A-fragments come
// straight from global (written by attn). grid 128, 128 threads (4 warps).
// ---------------------------------------------------------------------------
__global__ void __launch_bounds__(128) out_kernel(const float* __restrict__ bout,
                                                  float* __restrict__ out) {
    extern __shared__ unsigned smO[];
    unsigned* Bs = smO;                       // [128 n][132 words]
    float* bs = (float*)(smO + 128 * 132);    // bias

    const int tid = threadIdx.x;
    const uint32_t sBa = smem_u32(Bs);
    #pragma unroll
    for (int i = tid; i < 4096; i += 128) {
        int n = i >> 5, p4 = i & 31;
        cpa16(sBa + (uint32_t)(n * 528 + p4 * 16),
              g_woc + (size_t)n * 128 + p4 * 4);
    }
    bs[tid] = bout[tid];
    CPA_COMMIT();
    CPA_WAIT0();
    __syncthreads();

    const int wp = tid >> 5, lane = tid & 31, quad = lane >> 2, qr = lane & 3;
    const int rbg = blockIdx.x * 4 + wp;

    float o[16][4];
    #pragma unroll
    for (int j = 0; j < 16; ++j) {
        float b0 = bs[j*8 + qr*2], b1 = bs[j*8 + qr*2 + 1];
        o[j][0] = b0; o[j][1] = b1; o[j][2] = b0; o[j][3] = b1;
    }

    #pragma unroll
    for (int ks = 0; ks < 8; ++ks) {
        uint4 fh = g_aoh[(size_t)(rbg * 8 + ks) * 32 + lane];
        uint4 fl = g_aol[(size_t)(rbg * 8 + ks) * 32 + lane];
        #pragma unroll
        for (int j = 0; j < 16; ++j) {
            const unsigned* br = Bs + (j*8 + quad) * 132 + ks*8 + qr*2;
            uint2 bh2 = *(const uint2*)br;
            uint2 bl2 = *(const uint2*)(br + 64);
            MMA16(o[j], fh.x, fh.y, fh.z, fh.w, bh2.x, bh2.y);
            MMA16(o[j], fl.x, fl.y, fl.z, fl.w, bh2.x, bh2.y);
            MMA16(o[j], fh.x, fh.y, fh.z, fh.w, bl2.x, bl2.y);
        }
    }

    const int r0 = rbg * 16 + quad;
    #pragma unroll
    for (int j = 0; j < 16; ++j) {
        *(float2*)(out + (size_t)r0 * DIM + j*8 + qr*2) =
            make_float2(o[j][0], o[j][1]);
        *(float2*)(out + (size_t)(r0 + 8) * DIM + j*8 + qr*2) =
            make_float2(o[j][2], o[j][3]);
    }
}

// ---------------------------------------------------------------------------
extern "C" void kernel_launch(void* const* d_in, const int* in_sizes, int n_in,
                              void* d_out, int out_size) {
    const float *x = nullptr, *wqkv = nullptr, *wout = nullptr, *bout = nullptr;
    for (int i = 0; i < n_in; ++i) {
        switch (in_sizes[i]) {
            case ROWS_TOT * C_: x    = (const float*)d_in[i]; break;
            case C_ * QKV:      wqkv = (const float*)d_in[i]; break;
            case DIM * C_:      wout = (const float*)d_in[i]; break;
            case C_:            bout = (const float*)d_in[i]; break;
        }
    }
    float* out = (float*)d_out;

    const int smA = (128 + 64) * 132 * 4;          // 101376 B
    const int smO = 128 * 132 * 4 + 512;           // 68096 B
    cudaFuncSetAttribute(qkv_kernel, cudaFuncAttributeMaxDynamicSharedMemorySize, smA);
    cudaFuncSetAttribute(out_kernel, cudaFuncAttributeMaxDynamicSharedMemorySize, smO);

    prep_kernel<<<2176, 256>>>(x, wqkv, wout);
    qkv_kernel<<<dim3(64, 6), 256, smA>>>();
    attn_kernel<<<dim3(64, 8), 128>>>();
    out_kernel<<<128, 128, smO>>>(bout, out);
}

// round 11
// speedup vs baseline: 7.4157x; 1.1057x over previous
#include <cuda_runtime.h>
#include <cuda_fp16.h>
#include <cstdint>

#define B_   2
#define N_   4096
#define C_   128
#define NH   4
#define DH   32
#define DIM  128
#define QKV  384
#define ROWS_TOT (B_*N_)
#define C0 14.4269504088896340736f

// ---------------- scratch ---------------------------------------------------
__device__ __align__(16) unsigned g_xc[ROWS_TOT*128];   // x as bf16 hi/lo, permuted
__device__ __align__(16) unsigned g_wc[QKV*128];        // w_qkv^T, same format
__device__ __align__(16) unsigned g_woc[DIM*128];       // w_out^T, same format
__device__ __align__(16) unsigned g_q[8*N_*16];         // fp16x2, C0-scaled
__device__ __align__(16) unsigned g_k[8*N_*16];         // fp16x2, pair-permuted
__device__ __align__(16) unsigned short g_v[8*DH*N_];   // fp16, key-permuted
// split-K partials: o fragments (fp32) and row sums
__device__ __align__(16) float4 g_po[2*8*256*4*32];
__device__ __align__(16) float2 g_pl[2*8*256*32];
// attention output as ready-to-use mma A-fragments (bf16 hi / lo planes)
__device__ __align__(16) uint4 g_aoh[512*8*32];
__device__ __align__(16) uint4 g_aol[512*8*32];

// ---------------- helpers ----------------------------------------------------
__device__ __forceinline__ float ex2(float x) {
    float r; asm("ex2.approx.ftz.f32 %0, %1;" : "=f"(r) : "f"(x)); return r;
}
__device__ __forceinline__ unsigned packbf(float lo, float hi) {
    unsigned d; asm("cvt.rn.bf16x2.f32 %0, %1, %2;" : "=r"(d) : "f"(hi), "f"(lo)); return d;
}
__device__ __forceinline__ float bf_lo(unsigned u) { return __uint_as_float(u << 16); }
__device__ __forceinline__ float bf_hi(unsigned u) { return __uint_as_float(u & 0xffff0000u); }
__device__ __forceinline__ unsigned packh(float lo, float hi) {
    unsigned d; asm("cvt.rn.f16x2.f32 %0, %1, %2;" : "=r"(d) : "f"(hi), "f"(lo)); return d;
}
__device__ __forceinline__ uint32_t smem_u32(const void* p) {
    uint32_t a;
    asm("{ .reg .u64 t; cvta.to.shared.u64 t, %1; cvt.u32.u64 %0, t; }" : "=r"(a) : "l"(p));
    return a;
}
__device__ __forceinline__ void cpa16(uint32_t dst, const void* src) {
    asm volatile("cp.async.cg.shared.global [%0], [%1], 16;" :: "r"(dst), "l"(src));
}
#define CPA_COMMIT() asm volatile("cp.async.commit_group;" ::: "memory")
#define CPA_WAIT1()  asm volatile("cp.async.wait_group 1;" ::: "memory")
#define CPA_WAIT0()  asm volatile("cp.async.wait_group 0;" ::: "memory")

#define MMA16(c, a0,a1,a2,a3, b0, b1)                                          \
    asm volatile("mma.sync.aligned.m16n8k16.row.col.f32.bf16.bf16.f32 "        \
                 "{%0,%1,%2,%3},{%4,%5,%6,%7},{%8,%9},{%0,%1,%2,%3};"          \
                 : "+f"(c[0]), "+f"(c[1]), "+f"(c[2]), "+f"(c[3])              \
                 : "r"(a0), "r"(a1), "r"(a2), "r"(a3), "r"(b0), "r"(b1))
#define MMA16H(c, a0,a1,a2,a3, b0, b1)                                         \
    asm volatile("mma.sync.aligned.m16n8k16.row.col.f32.f16.f16.f32 "          \
                 "{%0,%1,%2,%3},{%4,%5,%6,%7},{%8,%9},{%0,%1,%2,%3};"          \
                 : "+f"(c[0]), "+f"(c[1]), "+f"(c[2]), "+f"(c[3])              \
                 : "r"(a0), "r"(a1), "r"(a2), "r"(a3), "r"(b0), "r"(b1))

__device__ __forceinline__ int perm8(int t) { return (t < 4) ? 2*t : 2*(t-4)+1; }
__device__ __forceinline__ int pw(int W) { return (W & ~7) + perm8(W & 7); }

// ---------------------------------------------------------------------------
// Kernel P: one-time conversion of x, w_qkv^T, w_out^T into bf16 hi/lo images.
// ---------------------------------------------------------------------------
__global__ void __launch_bounds__(256) prep_kernel(const float* __restrict__ x,
                                                   const float* __restrict__ w,
                                                   const float* __restrict__ wo) {
    const int idx = blockIdx.x * 256 + threadIdx.x;
    if (blockIdx.x < 2048) {                       // x
        const int r = idx >> 6, W = idx & 63;
        float2 v = *(const float2*)(x + (size_t)r * C_ + W * 2);
        unsigned h = packbf(v.x, v.y);
        unsigned l = packbf(v.x - bf_lo(h), v.y - bf_hi(h));
        g_xc[(size_t)r * 128 + pw(W)]      = h;
        g_xc[(size_t)r * 128 + 64 + pw(W)] = l;
    } else if (blockIdx.x < 2144) {                // w_qkv transpose
        const int i = idx - 2048 * 256;
        const int n = i >> 6, W = i & 63;
        float va = w[(size_t)(2 * W) * QKV + n];
        float vb = w[(size_t)(2 * W + 1) * QKV + n];
        unsigned h = packbf(va, vb);
        unsigned l = packbf(va - bf_lo(h), vb - bf_hi(h));
        g_wc[(size_t)n * 128 + pw(W)]      = h;
        g_wc[(size_t)n * 128 + 64 + pw(W)] = l;
    } else {                                       // w_out transpose
        const int i = idx - 2144 * 256;
        const int n = i >> 6, W = i & 63;
        float va = wo[(size_t)(2 * W) * DIM + n];
        float vb = wo[(size_t)(2 * W + 1) * DIM + n];
        unsigned h = packbf(va, vb);
        unsigned l = packbf(va - bf_lo(h), vb - bf_hi(h));
        g_woc[(size_t)n * 128 + pw(W)]      = h;
        g_woc[(size_t)n * 128 + 64 + pw(W)] = l;
    }
}

// ---------------------------------------------------------------------------
// Kernel A: qkv = x @ w_qkv via bf16 3-product mma. grid (64 m, 6 n), 256 thr.
// ---------------------------------------------------------------------------
__global__ void __launch_bounds__(256) qkv_kernel() {
    extern __shared__ unsigned smQ[];
    unsigned* As = smQ;                 // [128 rows][132 words]
    unsigned* Bs = smQ + 128 * 132;     // [64 n][132 words]

    const int tid  = threadIdx.x;
    const int row0 = blockIdx.x * 128;
    const int n0   = blockIdx.y * 64;
    const uint32_t sAa = smem_u32(As), sBa = smem_u32(Bs);

    #pragma unroll
    for (int i = tid; i < 4096; i += 256) {
        int r = i >> 5, p4 = i & 31;
        cpa16(sAa + (uint32_t)(r * 528 + p4 * 16),
              g_xc + (size_t)(row0 + r) * 128 + p4 * 4);
    }
    #pragma unroll
    for (int i = tid; i < 2048; i += 256) {
        int nq = i >> 5, p4 = i & 31;
        cpa16(sBa + (uint32_t)(nq * 528 + p4 * 16),
              g_wc + (size_t)(n0 + nq) * 128 + p4 * 4);
    }
    CPA_COMMIT();
    CPA_WAIT0();
    __syncthreads();

    const int wp = tid >> 5, lane = tid & 31, quad = lane >> 2, qr = lane & 3;
    const int r0 = row0 + wp * 16 + quad;
    const int b  = r0 >> 12;
    const int nn0 = r0 & (N_ - 1), nn1 = (r0 + 8) & (N_ - 1);

    #pragma unroll
    for (int c = 0; c < 2; ++c) {
        float o[4][4];
        #pragma unroll
        for (int nt = 0; nt < 4; ++nt)
            o[nt][0] = o[nt][1] = o[nt][2] = o[nt][3] = 0.f;

        #pragma unroll
        for (int ks = 0; ks < 8; ++ks) {
            const unsigned* ar = As + (wp * 16 + quad) * 132 + ks * 8 + qr * 2;
            uint2 ah0 = *(const uint2*)ar;
            uint2 ah1 = *(const uint2*)(ar + 8 * 132);
            uint2 al0 = *(const uint2*)(ar + 64);
            uint2 al1 = *(const uint2*)(ar + 8 * 132 + 64);
            #pragma unroll
            for (int nt = 0; nt < 4; ++nt) {
                const unsigned* br = Bs + (c * 32 + nt * 8 + quad) * 132 + ks * 8 + qr * 2;
                uint2 bh2 = *(const uint2*)br;
                uint2 bl2 = *(const uint2*)(br + 64);
                MMA16(o[nt], ah0.x, ah1.x, ah0.y, ah1.y, bh2.x, bh2.y);
                MMA16(o[nt], al0.x, al1.x, al0.y, al1.y, bh2.x, bh2.y);
                MMA16(o[nt], ah0.x, ah1.x, ah0.y, ah1.y, bl2.x, bl2.y);
            }
        }

        const int col0 = n0 + c * 32;
        const int seg  = col0 >> 7;
        const int head = (col0 >> 5) & 3;
        const size_t bhh = (size_t)(b * NH + head);

        if (seg < 2) {
            float ss0 = 0.f, ss1 = 0.f;
            #pragma unroll
            for (int nt = 0; nt < 4; ++nt) {
                ss0 += o[nt][0]*o[nt][0] + o[nt][1]*o[nt][1];
                ss1 += o[nt][2]*o[nt][2] + o[nt][3]*o[nt][3];
            }
            ss0 += __shfl_xor_sync(0xffffffffu, ss0, 1);
            ss0 += __shfl_xor_sync(0xffffffffu, ss0, 2);
            ss1 += __shfl_xor_sync(0xffffffffu, ss1, 1);
            ss1 += __shfl_xor_sync(0xffffffffu, ss1, 2);
            float inv0 = 1.0f / fmaxf(sqrtf(ss0), 1e-12f);
            float inv1 = 1.0f / fmaxf(sqrtf(ss1), 1e-12f);
            if (seg == 0) { inv0 *= C0; inv1 *= C0; }
            unsigned* base0 = (seg ? g_k : g_q) + (bhh * N_ + nn0) * 16;
            unsigned* base1 = (seg ? g_k : g_q) + (bhh * N_ + nn1) * 16;
            #pragma unroll
            for (int nt = 0; nt < 4; ++nt) {
                int dp  = nt * 4 + qr;
                int pos = seg ? ((dp >> 3) * 8 + perm8(dp & 7)) : dp;
                base0[pos] = packh(o[nt][0] * inv0, o[nt][1] * inv0);
                base1[pos] = packh(o[nt][2] * inv1, o[nt][3] * inv1);
            }
        } else {
            const int pk0 = (nn0 & ~15) + perm8((nn0 >> 1) & 7) * 2 + (nn0 & 1);
            const int pk1 = (nn1 & ~15) + perm8((nn1 >> 1) & 7) * 2 + (nn1 & 1);
            #pragma unroll
            for (int nt = 0; nt < 4; ++nt) {
                int d = nt * 8 + qr * 2;
                unsigned short* vb = g_v + (bhh * DH + d) * N_;
                vb[pk0]      = __half_as_ushort(__float2half_rn(o[nt][0]));
                vb[N_ + pk0] = __half_as_ushort(__float2half_rn(o[nt][1]));
                vb[pk1]      = __half_as_ushort(__float2half_rn(o[nt][2]));
                vb[N_ + pk1] = __half_as_ushort(__float2half_rn(o[nt][3]));
            }
        }
    }
}

// ---------------------------------------------------------------------------
// Kernel B: split-K flash attention (2 splits x 2048 keys). Fixed softmax
// offset makes partials exactly additive: each split stores fp32 partial o
// (fragment-shaped) + quad-reduced partial l.
// grid (64, 8, 2), 128 threads (4 warps x 16 q rows).
// ---------------------------------------------------------------------------
__global__ void __launch_bounds__(128, 8) attn_kernel() {
    __shared__ __align__(16) unsigned sK[2][64 * 20];
    __shared__ __align__(16) unsigned sV[2][32 * 36];

    const int bh = blockIdx.y, sp = blockIdx.z, tid = threadIdx.x;
    const int warp = tid >> 5, lane = tid & 31, quad = lane >> 2, qr = lane & 3;
    const int qb = blockIdx.x * 64 + warp * 16;
    const int wt = qb >> 4;                        // warp-tile id 0..255

    unsigned qf[2][4];
    {
        const unsigned* Q0 = g_q + ((size_t)bh * N_ + qb + quad) * 16;
        const unsigned* Q8 = Q0 + 8 * 16;
        #pragma unroll
        for (int ks = 0; ks < 2; ++ks) {
            qf[ks][0] = Q0[ks*8 + qr];      qf[ks][1] = Q8[ks*8 + qr];
            qf[ks][2] = Q0[ks*8 + qr + 4];  qf[ks][3] = Q8[ks*8 + qr + 4];
        }
    }

    float o[4][4];
    #pragma unroll
    for (int nt = 0; nt < 4; ++nt)
        o[nt][0] = o[nt][1] = o[nt][2] = o[nt][3] = 0.f;
    float l0 = 0.f, l1 = 0.f;

    const uint4* Kg = (const uint4*)g_k + (size_t)bh * N_ * 4;
    const uint4* Vg = (const uint4*)g_v + (size_t)bh * DH * (N_/8);
    const uint32_t sKa = smem_u32(sK), sVa = smem_u32(sV);

    #define STAGE(ch, buf) do {                                                \
        const int _k0 = (ch) * 64;                                             \
        const uint32_t _kb = sKa + (unsigned)(buf) * 5120u;                    \
        const uint32_t _vb = sVa + (unsigned)(buf) * 4608u;                    \
        _Pragma("unroll")                                                      \
        for (int _i = tid; _i < 256; _i += 128) {                              \
            int _key = _i >> 2, _p = _i & 3;                                   \
            cpa16(_kb + (uint32_t)(_key * 80 + _p * 16),                       \
                  Kg + (size_t)(_k0 + _key) * 4 + _p);                         \
        }                                                                      \
        _Pragma("unroll")                                                      \
        for (int _i = tid; _i < 256; _i += 128) {                              \
            int _dm = _i >> 3, _p = _i & 7;                                    \
            cpa16(_vb + (uint32_t)(_dm * 144 + _p * 16),                       \
                  Vg + (size_t)_dm * (N_/8) + _k0/8 + _p);                     \
        }                                                                      \
    } while (0)

    const int ch0 = sp * 32, chN = ch0 + 32;
    STAGE(ch0, 0);
    CPA_COMMIT();

    for (int ch = ch0; ch < chN; ++ch) {
        const int buf = ch & 1;
        if (ch < chN - 1) {
            STAGE(ch + 1, buf ^ 1);
            CPA_COMMIT();
            CPA_WAIT1();
        } else {
            CPA_WAIT0();
        }
        __syncthreads();
        const unsigned* Kb = sK[buf];
        const unsigned* Vb = sV[buf];

        #pragma unroll
        for (int half = 0; half < 2; ++half) {
            float p[4][4];
            #pragma unroll
            for (int j = 0; j < 4; ++j)
                p[j][0] = p[j][1] = p[j][2] = p[j][3] = -C0;
            #pragma unroll
            for (int ks = 0; ks < 2; ++ks) {
                #pragma unroll
                for (int j = 0; j < 4; ++j) {
                    const unsigned* kr = Kb + ((half*4 + j)*8 + quad) * 20;
                    uint2 b2 = *(const uint2*)(kr + ks*8 + 2*qr);
                    MMA16H(p[j], qf[ks][0], qf[ks][1], qf[ks][2], qf[ks][3],
                           b2.x, b2.y);
                }
            }
            #pragma unroll
            for (int j = 0; j < 4; ++j) {
                p[j][0] = ex2(p[j][0]); p[j][1] = ex2(p[j][1]);
                p[j][2] = ex2(p[j][2]); p[j][3] = ex2(p[j][3]);
                l0 += p[j][0] + p[j][1];
                l1 += p[j][2] + p[j][3];
            }
            #pragma unroll
            for (int kbl = 0; kbl < 2; ++kbl) {
                const int kbg = half * 2 + kbl;
                const float* pa = p[2*kbl];
                const float* pb = p[2*kbl + 1];
                unsigned a0 = packh(pa[0], pa[1]);
                unsigned a1 = packh(pa[2], pa[3]);
                unsigned a2 = packh(pb[0], pb[1]);
                unsigned a3 = packh(pb[2], pb[3]);
                #pragma unroll
                for (int nt = 0; nt < 4; ++nt) {
                    const unsigned* vr = Vb + (nt*8 + quad) * 36;
                    uint2 vv = *(const uint2*)(vr + kbg*8 + 2*qr);
                    MMA16H(o[nt], a0, a1, a2, a3, vv.x, vv.y);
                }
            }
        }
        __syncthreads();
    }

    // store split partials (no normalization)
    l0 += __shfl_xor_sync(0xffffffffu, l0, 1);
    l0 += __shfl_xor_sync(0xffffffffu, l0, 2);
    l1 += __shfl_xor_sync(0xffffffffu, l1, 1);
    l1 += __shfl_xor_sync(0xffffffffu, l1, 2);
    const size_t job = (size_t)(sp * 8 + bh) * 256 + wt;
    #pragma unroll
    for (int nt = 0; nt < 4; ++nt)
        g_po[(job * 4 + nt) * 32 + lane] =
            make_float4(o[nt][0], o[nt][1], o[nt][2], o[nt][3]);
    g_pl[job * 32 + lane] = make_float2(l0, l1);
}

// ---------------------------------------------------------------------------
// Kernel M: combine the two key-splits, normalize, emit bf16 A-fragments.
// grid 512 x 128 threads; one warp per (bh, warp-tile).
// ---------------------------------------------------------------------------
__global__ void __launch_bounds__(128) combine_kernel() {
    const int tid = threadIdx.x, warp = tid >> 5, lane = tid & 31;
    const int job = blockIdx.x * 4 + warp;        // 0..2047
    const int bh = job >> 8, wt = job & 255;
    const size_t j0 = (size_t)bh * 256 + wt;          // split 0
    const size_t j1 = (size_t)(8 + bh) * 256 + wt;    // split 1

    float2 la = g_pl[j0 * 32 + lane];
    float2 lb = g_pl[j1 * 32 + lane];
    const float i0 = 1.0f / (la.x + lb.x);
    const float i1 = 1.0f / (la.y + lb.y);

    const int b = bh >> 2, hh = bh & 3;
    const int rbg = ((b << 12) + (wt << 4)) >> 4;
    #pragma unroll
    for (int nt = 0; nt < 4; ++nt) {
        float4 a = g_po[(j0 * 4 + nt) * 32 + lane];
        float4 c = g_po[(j1 * 4 + nt) * 32 + lane];
        float v0 = (a.x + c.x) * i0, v1 = (a.y + c.y) * i0;
        float v2 = (a.z + c.z) * i1, v3 = (a.w + c.w) * i1;
        unsigned h0 = packbf(v0, v1), h1 = packbf(v2, v3);
        unsigned u0 = packbf(v0 - bf_lo(h0), v1 - bf_hi(h0));
        unsigned u1 = packbf(v2 - bf_lo(h1), v3 - bf_hi(h1));
        const int ks = 2 * hh + (nt >> 1);
        size_t idx = (size_t)(rbg * 8 + ks) * 32 + lane;
        ((uint2*)&g_aoh[idx])[nt & 1] = make_uint2(h0, h1);
        ((uint2*)&g_aol[idx])[nt & 1] = make_uint2(u0, u1);
    }
}

// ---------------------------------------------------------------------------
// Kernel C: out = ao @ w_out + b_out via bf16 3-product mma; A-fragments come
// straight from global. grid 128, 128 threads (4 warps).
// ---------------------------------------------------------------------------
__global__ void __launch_bounds__(128) out_kernel(const float* __restrict__ bout,
                                                  float* __restrict__ out) {
    extern __shared__ unsigned smO[];
    unsigned* Bs = smO;                       // [128 n][132 words]
    float* bs = (float*)(smO + 128 * 132);    // bias

    const int tid = threadIdx.x;
    const uint32_t sBa = smem_u32(Bs);
    #pragma unroll
    for (int i = tid; i < 4096; i += 128) {
        int n = i >> 5, p4 = i & 31;
        cpa16(sBa + (uint32_t)(n * 528 + p4 * 16),
              g_woc + (size_t)n * 128 + p4 * 4);
    }
    bs[tid] = bout[tid];
    CPA_COMMIT();
    CPA_WAIT0();
    __syncthreads();

    const int wp = tid >> 5, lane = tid & 31, quad = lane >> 2, qr = lane & 3;
    const int rbg = blockIdx.x * 4 + wp;

    float o[16][4];
    #pragma unroll
    for (int j = 0; j < 16; ++j) {
        float b0 = bs[j*8 + qr*2], b1 = bs[j*8 + qr*2 + 1];
        o[j][0] = b0; o[j][1] = b1; o[j][2] = b0; o[j][3] = b1;
    }

    #pragma unroll
    for (int ks = 0; ks < 8; ++ks) {
        uint4 fh = g_aoh[(size_t)(rbg * 8 + ks) * 32 + lane];
        uint4 fl = g_aol[(size_t)(rbg * 8 + ks) * 32 + lane];
        #pragma unroll
        for (int j = 0; j < 16; ++j) {
            const unsigned* br = Bs + (j*8 + quad) * 132 + ks*8 + qr*2;
            uint2 bh2 = *(const uint2*)br;
            uint2 bl2 = *(const uint2*)(br + 64);
            MMA16(o[j], fh.x, fh.y, fh.z, fh.w, bh2.x, bh2.y);
            MMA16(o[j], fl.x, fl.y, fl.z, fl.w, bh2.x, bh2.y);
            MMA16(o[j], fh.x, fh.y, fh.z, fh.w, bl2.x, bl2.y);
        }
    }

    const int r0 = rbg * 16 + quad;
    #pragma unroll
    for (int j = 0; j < 16; ++j) {
        *(float2*)(out + (size_t)r0 * DIM + j*8 + qr*2) =
            make_float2(o[j][0], o[j][1]);
        *(float2*)(out + (size_t)(r0 + 8) * DIM + j*8 + qr*2) =
            make_float2(o[j][2], o[j][3]);
    }
}

// ---------------------------------------------------------------------------
extern "C" void kernel_launch(void* const* d_in, const int* in_sizes, int n_in,
                              void* d_out, int out_size) {
    const float *x = nullptr, *wqkv = nullptr, *wout = nullptr, *bout = nullptr;
    for (int i = 0; i < n_in; ++i) {
        switch (in_sizes[i]) {
            case ROWS_TOT * C_: x    = (const float*)d_in[i]; break;
            case C_ * QKV:      wqkv = (const float*)d_in[i]; break;
            case DIM * C_:      wout = (const float*)d_in[i]; break;
            case C_:            bout = (const float*)d_in[i]; break;
        }
    }
    float* out = (float*)d_out;

    const int smA = (128 + 64) * 132 * 4;          // 101376 B
    const int smO = 128 * 132 * 4 + 512;           // 68096 B
    cudaFuncSetAttribute(qkv_kernel, cudaFuncAttributeMaxDynamicSharedMemorySize, smA);
    cudaFuncSetAttribute(out_kernel, cudaFuncAttributeMaxDynamicSharedMemorySize, smO);

    prep_kernel<<<2176, 256>>>(x, wqkv, wout);
    qkv_kernel<<<dim3(64, 6), 256, smA>>>();
    attn_kernel<<<dim3(64, 8, 2), 128>>>();
    combine_kernel<<<512, 128>>>();
    out_kernel<<<128, 128, smO>>>(bout, out);
}

// round 12
// speedup vs baseline: 7.5590x; 1.0193x over previous
#include <cuda_runtime.h>
#include <cuda_fp16.h>
#include <cstdint>

#define B_   2
#define N_   4096
#define C_   128
#define NH   4
#define DH   32
#define DIM  128
#define QKV  384
#define ROWS_TOT (B_*N_)
#define C0 14.4269504088896340736f

// ---------------- scratch ---------------------------------------------------
__device__ __align__(16) unsigned g_xc[ROWS_TOT*128];   // x as bf16 hi/lo, permuted
__device__ __align__(16) unsigned g_wc[QKV*128];        // w_qkv^T, same format
__device__ __align__(16) unsigned g_woc[DIM*128];       // w_out^T, same format
__device__ __align__(16) unsigned g_q[8*N_*16];         // fp16x2, C0-scaled
__device__ __align__(16) unsigned g_k[8*N_*16];         // fp16x2, pair-permuted
__device__ __align__(16) unsigned short g_v[8*DH*N_];   // fp16, key-permuted
// split-K partials: o fragments (fp32) and row sums
__device__ __align__(16) float4 g_po[2*8*256*4*32];
__device__ __align__(16) float2 g_pl[2*8*256*32];

// ---------------- helpers ----------------------------------------------------
__device__ __forceinline__ float ex2(float x) {
    float r; asm("ex2.approx.ftz.f32 %0, %1;" : "=f"(r) : "f"(x)); return r;
}
__device__ __forceinline__ unsigned packbf(float lo, float hi) {
    unsigned d; asm("cvt.rn.bf16x2.f32 %0, %1, %2;" : "=r"(d) : "f"(hi), "f"(lo)); return d;
}
__device__ __forceinline__ float bf_lo(unsigned u) { return __uint_as_float(u << 16); }
__device__ __forceinline__ float bf_hi(unsigned u) { return __uint_as_float(u & 0xffff0000u); }
__device__ __forceinline__ unsigned packh(float lo, float hi) {
    unsigned d; asm("cvt.rn.f16x2.f32 %0, %1, %2;" : "=r"(d) : "f"(hi), "f"(lo)); return d;
}
__device__ __forceinline__ uint32_t smem_u32(const void* p) {
    uint32_t a;
    asm("{ .reg .u64 t; cvta.to.shared.u64 t, %1; cvt.u32.u64 %0, t; }" : "=r"(a) : "l"(p));
    return a;
}
__device__ __forceinline__ void cpa16(uint32_t dst, const void* src) {
    asm volatile("cp.async.cg.shared.global [%0], [%1], 16;" :: "r"(dst), "l"(src));
}
#define CPA_COMMIT() asm volatile("cp.async.commit_group;" ::: "memory")
#define CPA_WAIT1()  asm volatile("cp.async.wait_group 1;" ::: "memory")
#define CPA_WAIT0()  asm volatile("cp.async.wait_group 0;" ::: "memory")

#define MMA16(c, a0,a1,a2,a3, b0, b1)                                          \
    asm volatile("mma.sync.aligned.m16n8k16.row.col.f32.bf16.bf16.f32 "        \
                 "{%0,%1,%2,%3},{%4,%5,%6,%7},{%8,%9},{%0,%1,%2,%3};"          \
                 : "+f"(c[0]), "+f"(c[1]), "+f"(c[2]), "+f"(c[3])              \
                 : "r"(a0), "r"(a1), "r"(a2), "r"(a3), "r"(b0), "r"(b1))
#define MMA16H(c, a0,a1,a2,a3, b0, b1)                                         \
    asm volatile("mma.sync.aligned.m16n8k16.row.col.f32.f16.f16.f32 "          \
                 "{%0,%1,%2,%3},{%4,%5,%6,%7},{%8,%9},{%0,%1,%2,%3};"          \
                 : "+f"(c[0]), "+f"(c[1]), "+f"(c[2]), "+f"(c[3])              \
                 : "r"(a0), "r"(a1), "r"(a2), "r"(a3), "r"(b0), "r"(b1))

__device__ __forceinline__ int perm8(int t) { return (t < 4) ? 2*t : 2*(t-4)+1; }
__device__ __forceinline__ int pw(int W) { return (W & ~7) + perm8(W & 7); }

// ---------------------------------------------------------------------------
// Kernel P: one-time conversion of x, w_qkv^T, w_out^T into bf16 hi/lo images.
// ---------------------------------------------------------------------------
__global__ void __launch_bounds__(256) prep_kernel(const float* __restrict__ x,
                                                   const float* __restrict__ w,
                                                   const float* __restrict__ wo) {
    const int idx = blockIdx.x * 256 + threadIdx.x;
    if (blockIdx.x < 2048) {                       // x
        const int r = idx >> 6, W = idx & 63;
        float2 v = *(const float2*)(x + (size_t)r * C_ + W * 2);
        unsigned h = packbf(v.x, v.y);
        unsigned l = packbf(v.x - bf_lo(h), v.y - bf_hi(h));
        g_xc[(size_t)r * 128 + pw(W)]      = h;
        g_xc[(size_t)r * 128 + 64 + pw(W)] = l;
    } else if (blockIdx.x < 2144) {                // w_qkv transpose
        const int i = idx - 2048 * 256;
        const int n = i >> 6, W = i & 63;
        float va = w[(size_t)(2 * W) * QKV + n];
        float vb = w[(size_t)(2 * W + 1) * QKV + n];
        unsigned h = packbf(va, vb);
        unsigned l = packbf(va - bf_lo(h), vb - bf_hi(h));
        g_wc[(size_t)n * 128 + pw(W)]      = h;
        g_wc[(size_t)n * 128 + 64 + pw(W)] = l;
    } else {                                       // w_out transpose
        const int i = idx - 2144 * 256;
        const int n = i >> 6, W = i & 63;
        float va = wo[(size_t)(2 * W) * DIM + n];
        float vb = wo[(size_t)(2 * W + 1) * DIM + n];
        unsigned h = packbf(va, vb);
        unsigned l = packbf(va - bf_lo(h), vb - bf_hi(h));
        g_woc[(size_t)n * 128 + pw(W)]      = h;
        g_woc[(size_t)n * 128 + 64 + pw(W)] = l;
    }
}

// ---------------------------------------------------------------------------
// Kernel A: qkv = x @ w_qkv via bf16 3-product mma. grid (128 m, 6 n),
// 256 threads, 64-row x 64-col blocks, 67.6KB smem -> 3 CTAs/SM.
// ---------------------------------------------------------------------------
__global__ void __launch_bounds__(256, 3) qkv_kernel() {
    extern __shared__ unsigned smQ[];
    unsigned* As = smQ;                 // [64 rows][132 words]
    unsigned* Bs = smQ + 64 * 132;      // [64 n][132 words]

    const int tid  = threadIdx.x;
    const int row0 = blockIdx.x * 64;
    const int n0   = blockIdx.y * 64;
    const uint32_t sAa = smem_u32(As), sBa = smem_u32(Bs);

    #pragma unroll
    for (int i = tid; i < 2048; i += 256) {
        int r = i >> 5, p4 = i & 31;
        cpa16(sAa + (uint32_t)(r * 528 + p4 * 16),
              g_xc + (size_t)(row0 + r) * 128 + p4 * 4);
    }
    #pragma unroll
    for (int i = tid; i < 2048; i += 256) {
        int nq = i >> 5, p4 = i & 31;
        cpa16(sBa + (uint32_t)(nq * 528 + p4 * 16),
              g_wc + (size_t)(n0 + nq) * 128 + p4 * 4);
    }
    CPA_COMMIT();
    CPA_WAIT0();
    __syncthreads();

    const int warp = tid >> 5, lane = tid & 31, quad = lane >> 2, qr = lane & 3;
    const int mt = warp >> 1;            // m-tile 0..3 (16 rows each)
    const int c  = warp & 1;             // n-half  0..1 (32 cols each)
    const int r0 = row0 + mt * 16 + quad;
    const int b  = r0 >> 12;
    const int nn0 = r0 & (N_ - 1), nn1 = (r0 + 8) & (N_ - 1);

    float o[4][4];
    #pragma unroll
    for (int nt = 0; nt < 4; ++nt)
        o[nt][0] = o[nt][1] = o[nt][2] = o[nt][3] = 0.f;

    #pragma unroll
    for (int ks = 0; ks < 8; ++ks) {
        const unsigned* ar = As + (mt * 16 + quad) * 132 + ks * 8 + qr * 2;
        uint2 ah0 = *(const uint2*)ar;
        uint2 ah1 = *(const uint2*)(ar + 8 * 132);
        uint2 al0 = *(const uint2*)(ar + 64);
        uint2 al1 = *(const uint2*)(ar + 8 * 132 + 64);
        #pragma unroll
        for (int nt = 0; nt < 4; ++nt) {
            const unsigned* br = Bs + (c * 32 + nt * 8 + quad) * 132 + ks * 8 + qr * 2;
            uint2 bh2 = *(const uint2*)br;
            uint2 bl2 = *(const uint2*)(br + 64);
            MMA16(o[nt], ah0.x, ah1.x, ah0.y, ah1.y, bh2.x, bh2.y);
            MMA16(o[nt], al0.x, al1.x, al0.y, al1.y, bh2.x, bh2.y);
            MMA16(o[nt], ah0.x, ah1.x, ah0.y, ah1.y, bl2.x, bl2.y);
        }
    }

    const int col0 = n0 + c * 32;
    const int seg  = col0 >> 7;           // 0=q, 1=k, 2=v
    const int head = (col0 >> 5) & 3;
    const size_t bhh = (size_t)(b * NH + head);

    if (seg < 2) {
        float ss0 = 0.f, ss1 = 0.f;
        #pragma unroll
        for (int nt = 0; nt < 4; ++nt) {
            ss0 += o[nt][0]*o[nt][0] + o[nt][1]*o[nt][1];
            ss1 += o[nt][2]*o[nt][2] + o[nt][3]*o[nt][3];
        }
        ss0 += __shfl_xor_sync(0xffffffffu, ss0, 1);
        ss0 += __shfl_xor_sync(0xffffffffu, ss0, 2);
        ss1 += __shfl_xor_sync(0xffffffffu, ss1, 1);
        ss1 += __shfl_xor_sync(0xffffffffu, ss1, 2);
        float inv0 = 1.0f / fmaxf(sqrtf(ss0), 1e-12f);
        float inv1 = 1.0f / fmaxf(sqrtf(ss1), 1e-12f);
        if (seg == 0) { inv0 *= C0; inv1 *= C0; }
        unsigned* base0 = (seg ? g_k : g_q) + (bhh * N_ + nn0) * 16;
        unsigned* base1 = (seg ? g_k : g_q) + (bhh * N_ + nn1) * 16;
        #pragma unroll
        for (int nt = 0; nt < 4; ++nt) {
            int dp  = nt * 4 + qr;
            int pos = seg ? ((dp >> 3) * 8 + perm8(dp & 7)) : dp;
            base0[pos] = packh(o[nt][0] * inv0, o[nt][1] * inv0);
            base1[pos] = packh(o[nt][2] * inv1, o[nt][3] * inv1);
        }
    } else {
        const int pk0 = (nn0 & ~15) + perm8((nn0 >> 1) & 7) * 2 + (nn0 & 1);
        const int pk1 = (nn1 & ~15) + perm8((nn1 >> 1) & 7) * 2 + (nn1 & 1);
        #pragma unroll
        for (int nt = 0; nt < 4; ++nt) {
            int d = nt * 8 + qr * 2;
            unsigned short* vb = g_v + (bhh * DH + d) * N_;
            vb[pk0]      = __half_as_ushort(__float2half_rn(o[nt][0]));
            vb[N_ + pk0] = __half_as_ushort(__float2half_rn(o[nt][1]));
            vb[pk1]      = __half_as_ushort(__float2half_rn(o[nt][2]));
            vb[N_ + pk1] = __half_as_ushort(__float2half_rn(o[nt][3]));
        }
    }
}

// ---------------------------------------------------------------------------
// Kernel B: split-K flash attention (2 splits x 2048 keys). Fixed softmax
// offset makes partials exactly additive. grid (64, 8, 2), 128 threads.
// ---------------------------------------------------------------------------
__global__ void __launch_bounds__(128, 8) attn_kernel() {
    __shared__ __align__(16) unsigned sK[2][64 * 20];
    __shared__ __align__(16) unsigned sV[2][32 * 36];

    const int bh = blockIdx.y, sp = blockIdx.z, tid = threadIdx.x;
    const int warp = tid >> 5, lane = tid & 31, quad = lane >> 2, qr = lane & 3;
    const int qb = blockIdx.x * 64 + warp * 16;
    const int wt = qb >> 4;

    unsigned qf[2][4];
    {
        const unsigned* Q0 = g_q + ((size_t)bh * N_ + qb + quad) * 16;
        const unsigned* Q8 = Q0 + 8 * 16;
        #pragma unroll
        for (int ks = 0; ks < 2; ++ks) {
            qf[ks][0] = Q0[ks*8 + qr];      qf[ks][1] = Q8[ks*8 + qr];
            qf[ks][2] = Q0[ks*8 + qr + 4];  qf[ks][3] = Q8[ks*8 + qr + 4];
        }
    }

    float o[4][4];
    #pragma unroll
    for (int nt = 0; nt < 4; ++nt)
        o[nt][0] = o[nt][1] = o[nt][2] = o[nt][3] = 0.f;
    float l0 = 0.f, l1 = 0.f;

    const uint4* Kg = (const uint4*)g_k + (size_t)bh * N_ * 4;
    const uint4* Vg = (const uint4*)g_v + (size_t)bh * DH * (N_/8);
    const uint32_t sKa = smem_u32(sK), sVa = smem_u32(sV);

    #define STAGE(ch, buf) do {                                                \
        const int _k0 = (ch) * 64;                                             \
        const uint32_t _kb = sKa + (unsigned)(buf) * 5120u;                    \
        const uint32_t _vb = sVa + (unsigned)(buf) * 4608u;                    \
        _Pragma("unroll")                                                      \
        for (int _i = tid; _i < 256; _i += 128) {                              \
            int _key = _i >> 2, _p = _i & 3;                                   \
            cpa16(_kb + (uint32_t)(_key * 80 + _p * 16),                       \
                  Kg + (size_t)(_k0 + _key) * 4 + _p);                         \
        }                                                                      \
        _Pragma("unroll")                                                      \
        for (int _i = tid; _i < 256; _i += 128) {                              \
            int _dm = _i >> 3, _p = _i & 7;                                    \
            cpa16(_vb + (uint32_t)(_dm * 144 + _p * 16),                       \
                  Vg + (size_t)_dm * (N_/8) + _k0/8 + _p);                     \
        }                                                                      \
    } while (0)

    const int ch0 = sp * 32, chN = ch0 + 32;
    STAGE(ch0, 0);
    CPA_COMMIT();

    for (int ch = ch0; ch < chN; ++ch) {
        const int buf = ch & 1;
        if (ch < chN - 1) {
            STAGE(ch + 1, buf ^ 1);
            CPA_COMMIT();
            CPA_WAIT1();
        } else {
            CPA_WAIT0();
        }
        __syncthreads();
        const unsigned* Kb = sK[buf];
        const unsigned* Vb = sV[buf];

        #pragma unroll
        for (int half = 0; half < 2; ++half) {
            float p[4][4];
            #pragma unroll
            for (int j = 0; j < 4; ++j)
                p[j][0] = p[j][1] = p[j][2] = p[j][3] = -C0;
            #pragma unroll
            for (int ks = 0; ks < 2; ++ks) {
                #pragma unroll
                for (int j = 0; j < 4; ++j) {
                    const unsigned* kr = Kb + ((half*4 + j)*8 + quad) * 20;
                    uint2 b2 = *(const uint2*)(kr + ks*8 + 2*qr);
                    MMA16H(p[j], qf[ks][0], qf[ks][1], qf[ks][2], qf[ks][3],
                           b2.x, b2.y);
                }
            }
            #pragma unroll
            for (int j = 0; j < 4; ++j) {
                p[j][0] = ex2(p[j][0]); p[j][1] = ex2(p[j][1]);
                p[j][2] = ex2(p[j][2]); p[j][3] = ex2(p[j][3]);
                l0 += p[j][0] + p[j][1];
                l1 += p[j][2] + p[j][3];
            }
            #pragma unroll
            for (int kbl = 0; kbl < 2; ++kbl) {
                const int kbg = half * 2 + kbl;
                const float* pa = p[2*kbl];
                const float* pb = p[2*kbl + 1];
                unsigned a0 = packh(pa[0], pa[1]);
                unsigned a1 = packh(pa[2], pa[3]);
                unsigned a2 = packh(pb[0], pb[1]);
                unsigned a3 = packh(pb[2], pb[3]);
                #pragma unroll
                for (int nt = 0; nt < 4; ++nt) {
                    const unsigned* vr = Vb + (nt*8 + quad) * 36;
                    uint2 vv = *(const uint2*)(vr + kbg*8 + 2*qr);
                    MMA16H(o[nt], a0, a1, a2, a3, vv.x, vv.y);
                }
            }
        }
        __syncthreads();
    }

    l0 += __shfl_xor_sync(0xffffffffu, l0, 1);
    l0 += __shfl_xor_sync(0xffffffffu, l0, 2);
    l1 += __shfl_xor_sync(0xffffffffu, l1, 1);
    l1 += __shfl_xor_sync(0xffffffffu, l1, 2);
    const size_t job = (size_t)(sp * 8 + bh) * 256 + wt;
    #pragma unroll
    for (int nt = 0; nt < 4; ++nt)
        g_po[(job * 4 + nt) * 32 + lane] =
            make_float4(o[nt][0], o[nt][1], o[nt][2], o[nt][3]);
    g_pl[job * 32 + lane] = make_float2(l0, l1);
}

// ---------------------------------------------------------------------------
// Kernel C: combine splits + normalize + out-GEMM in one pass.
// grid 128, 256 threads (8 warps = 4 row-blocks x 2 col-halves).
// ---------------------------------------------------------------------------
__global__ void __launch_bounds__(256) out_kernel(const float* __restrict__ bout,
                                                  float* __restrict__ out) {
    extern __shared__ unsigned smO[];
    unsigned* Bs = smO;                       // [128 n][132 words]
    float* bs = (float*)(smO + 128 * 132);    // bias

    const int tid = threadIdx.x;
    const uint32_t sBa = smem_u32(Bs);
    #pragma unroll
    for (int i = tid; i < 4096; i += 256) {
        int n = i >> 5, p4 = i & 31;
        cpa16(sBa + (uint32_t)(n * 528 + p4 * 16),
              g_woc + (size_t)n * 128 + p4 * 4);
    }
    if (tid < 128) bs[tid] = bout[tid];
    CPA_COMMIT();
    CPA_WAIT0();
    __syncthreads();

    const int warp = tid >> 5, lane = tid & 31, quad = lane >> 2, qr = lane & 3;
    const int rbg = blockIdx.x * 4 + (warp >> 1);    // 16-row block
    const int jh  = warp & 1;                        // column half (64 cols)
    const int b = rbg >> 8, wt = rbg & 255;

    // per-head inverse row sums for this thread's rows
    float i0h[4], i1h[4];
    #pragma unroll
    for (int hh = 0; hh < 4; ++hh) {
        const int bh = b * 4 + hh;
        float2 la = g_pl[((size_t)bh * 256 + wt) * 32 + lane];
        float2 lb = g_pl[((size_t)(8 + bh) * 256 + wt) * 32 + lane];
        i0h[hh] = 1.0f / (la.x + lb.x);
        i1h[hh] = 1.0f / (la.y + lb.y);
    }

    float o[8][4];
    #pragma unroll
    for (int j = 0; j < 8; ++j) {
        float b0 = bs[(jh*8 + j)*8 + qr*2], b1 = bs[(jh*8 + j)*8 + qr*2 + 1];
        o[j][0] = b0; o[j][1] = b1; o[j][2] = b0; o[j][3] = b1;
    }

    #pragma unroll
    for (int ks = 0; ks < 8; ++ks) {
        const int hh = ks >> 1, sel = ks & 1;
        const int bh = b * 4 + hh;
        const size_t j0 = ((size_t)bh * 256 + wt) * 4;
        const size_t j1 = ((size_t)(8 + bh) * 256 + wt) * 4;
        const float i0 = i0h[hh], i1 = i1h[hh];
        unsigned fh[4], fl[4];
        #pragma unroll
        for (int s = 0; s < 2; ++s) {
            const int nt = 2 * sel + s;
            float4 a = g_po[(j0 + nt) * 32 + lane];
            float4 c = g_po[(j1 + nt) * 32 + lane];
            float v0 = (a.x + c.x) * i0, v1 = (a.y + c.y) * i0;
            float v2 = (a.z + c.z) * i1, v3 = (a.w + c.w) * i1;
            unsigned h0 = packbf(v0, v1), h1 = packbf(v2, v3);
            fh[2*s]   = h0;
            fh[2*s+1] = h1;
            fl[2*s]   = packbf(v0 - bf_lo(h0), v1 - bf_hi(h0));
            fl[2*s+1] = packbf(v2 - bf_lo(h1), v3 - bf_hi(h1));
        }
        #pragma unroll
        for (int j = 0; j < 8; ++j) {
            const unsigned* br = Bs + ((jh*8 + j)*8 + quad) * 132 + ks*8 + qr*2;
            uint2 bh2 = *(const uint2*)br;
            uint2 bl2 = *(const uint2*)(br + 64);
            MMA16(o[j], fh[0], fh[1], fh[2], fh[3], bh2.x, bh2.y);
            MMA16(o[j], fl[0], fl[1], fl[2], fl[3], bh2.x, bh2.y);
            MMA16(o[j], fh[0], fh[1], fh[2], fh[3], bl2.x, bl2.y);
        }
    }

    const int r0 = rbg * 16 + quad;
    #pragma unroll
    for (int j = 0; j < 8; ++j) {
        *(float2*)(out + (size_t)r0 * DIM + (jh*8 + j)*8 + qr*2) =
            make_float2(o[j][0], o[j][1]);
        *(float2*)(out + (size_t)(r0 + 8) * DIM + (jh*8 + j)*8 + qr*2) =
            make_float2(o[j][2], o[j][3]);
    }
}

// ---------------------------------------------------------------------------
extern "C" void kernel_launch(void* const* d_in, const int* in_sizes, int n_in,
                              void* d_out, int out_size) {
    const float *x = nullptr, *wqkv = nullptr, *wout = nullptr, *bout = nullptr;
    for (int i = 0; i < n_in; ++i) {
        switch (in_sizes[i]) {
            case ROWS_TOT * C_: x    = (const float*)d_in[i]; break;
            case C_ * QKV:      wqkv = (const float*)d_in[i]; break;
            case DIM * C_:      wout = (const float*)d_in[i]; break;
            case C_:            bout = (const float*)d_in[i]; break;
        }
    }
    float* out = (float*)d_out;

    const int smA = (64 + 64) * 132 * 4;           // 67584 B -> 3 CTAs/SM
    const int smO = 128 * 132 * 4 + 512;           // 68096 B
    cudaFuncSetAttribute(qkv_kernel, cudaFuncAttributeMaxDynamicSharedMemorySize, smA);
    cudaFuncSetAttribute(out_kernel, cudaFuncAttributeMaxDynamicSharedMemorySize, smO);

    prep_kernel<<<2176, 256>>>(x, wqkv, wout);
    qkv_kernel<<<dim3(128, 6), 256, smA>>>();
    attn_kernel<<<dim3(64, 8, 2), 128>>>();
    out_kernel<<<128, 256, smO>>>(bout, out);
}

// round 13
// speedup vs baseline: 7.5968x; 1.0050x over previous
#include <cuda_runtime.h>
#include <cuda_fp16.h>
#include <cstdint>

#define B_   2
#define N_   4096
#define C_   128
#define NH   4
#define DH   32
#define DIM  128
#define QKV  384
#define ROWS_TOT (B_*N_)
#define C0 14.4269504088896340736f

// ---------------- scratch ---------------------------------------------------
__device__ __align__(16) unsigned g_xc[ROWS_TOT*128];   // x as bf16 hi/lo, permuted
__device__ __align__(16) unsigned g_wc[QKV*128];        // w_qkv^T, same format
__device__ __align__(16) unsigned g_woc[DIM*128];       // w_out^T, same format
__device__ __align__(16) unsigned g_q[8*N_*16];         // fp16x2, C0-scaled
__device__ __align__(16) unsigned g_k[8*N_*16];         // fp16x2, pair-permuted
__device__ __align__(16) unsigned short g_v[8*DH*N_];   // fp16, key-permuted
// split-K partials: o fragments (fp32) and row sums
__device__ __align__(16) float4 g_po[2*8*256*4*32];
__device__ __align__(16) float2 g_pl[2*8*256*32];

// ---------------- helpers ----------------------------------------------------
__device__ __forceinline__ float ex2(float x) {
    float r; asm("ex2.approx.ftz.f32 %0, %1;" : "=f"(r) : "f"(x)); return r;
}
__device__ __forceinline__ unsigned packbf(float lo, float hi) {
    unsigned d; asm("cvt.rn.bf16x2.f32 %0, %1, %2;" : "=r"(d) : "f"(hi), "f"(lo)); return d;
}
__device__ __forceinline__ float bf_lo(unsigned u) { return __uint_as_float(u << 16); }
__device__ __forceinline__ float bf_hi(unsigned u) { return __uint_as_float(u & 0xffff0000u); }
__device__ __forceinline__ unsigned packh(float lo, float hi) {
    unsigned d; asm("cvt.rn.f16x2.f32 %0, %1, %2;" : "=r"(d) : "f"(hi), "f"(lo)); return d;
}
__device__ __forceinline__ uint32_t smem_u32(const void* p) {
    uint32_t a;
    asm("{ .reg .u64 t; cvta.to.shared.u64 t, %1; cvt.u32.u64 %0, t; }" : "=r"(a) : "l"(p));
    return a;
}
__device__ __forceinline__ void cpa16(uint32_t dst, const void* src) {
    asm volatile("cp.async.cg.shared.global [%0], [%1], 16;" :: "r"(dst), "l"(src));
}
#define CPA_COMMIT() asm volatile("cp.async.commit_group;" ::: "memory")
#define CPA_WAIT1()  asm volatile("cp.async.wait_group 1;" ::: "memory")
#define CPA_WAIT0()  asm volatile("cp.async.wait_group 0;" ::: "memory")

#define MMA16(c, a0,a1,a2,a3, b0, b1)                                          \
    asm volatile("mma.sync.aligned.m16n8k16.row.col.f32.bf16.bf16.f32 "        \
                 "{%0,%1,%2,%3},{%4,%5,%6,%7},{%8,%9},{%0,%1,%2,%3};"          \
                 : "+f"(c[0]), "+f"(c[1]), "+f"(c[2]), "+f"(c[3])              \
                 : "r"(a0), "r"(a1), "r"(a2), "r"(a3), "r"(b0), "r"(b1))
#define MMA16H(c, a0,a1,a2,a3, b0, b1)                                         \
    asm volatile("mma.sync.aligned.m16n8k16.row.col.f32.f16.f16.f32 "          \
                 "{%0,%1,%2,%3},{%4,%5,%6,%7},{%8,%9},{%0,%1,%2,%3};"          \
                 : "+f"(c[0]), "+f"(c[1]), "+f"(c[2]), "+f"(c[3])              \
                 : "r"(a0), "r"(a1), "r"(a2), "r"(a3), "r"(b0), "r"(b1))

__device__ __forceinline__ int perm8(int t) { return (t < 4) ? 2*t : 2*(t-4)+1; }
__device__ __forceinline__ int pw(int W) { return (W & ~7) + perm8(W & 7); }

// ---------------------------------------------------------------------------
// Kernel P: one-time conversion of x, w_qkv^T, w_out^T into bf16 hi/lo images.
// ---------------------------------------------------------------------------
__global__ void __launch_bounds__(256) prep_kernel(const float* __restrict__ x,
                                                   const float* __restrict__ w,
                                                   const float* __restrict__ wo) {
    const int idx = blockIdx.x * 256 + threadIdx.x;
    if (blockIdx.x < 2048) {                       // x
        const int r = idx >> 6, W = idx & 63;
        float2 v = *(const float2*)(x + (size_t)r * C_ + W * 2);
        unsigned h = packbf(v.x, v.y);
        unsigned l = packbf(v.x - bf_lo(h), v.y - bf_hi(h));
        g_xc[(size_t)r * 128 + pw(W)]      = h;
        g_xc[(size_t)r * 128 + 64 + pw(W)] = l;
    } else if (blockIdx.x < 2144) {                // w_qkv transpose
        const int i = idx - 2048 * 256;
        const int n = i >> 6, W = i & 63;
        float va = w[(size_t)(2 * W) * QKV + n];
        float vb = w[(size_t)(2 * W + 1) * QKV + n];
        unsigned h = packbf(va, vb);
        unsigned l = packbf(va - bf_lo(h), vb - bf_hi(h));
        g_wc[(size_t)n * 128 + pw(W)]      = h;
        g_wc[(size_t)n * 128 + 64 + pw(W)] = l;
    } else {                                       // w_out transpose
        const int i = idx - 2144 * 256;
        const int n = i >> 6, W = i & 63;
        float va = wo[(size_t)(2 * W) * DIM + n];
        float vb = wo[(size_t)(2 * W + 1) * DIM + n];
        unsigned h = packbf(va, vb);
        unsigned l = packbf(va - bf_lo(h), vb - bf_hi(h));
        g_woc[(size_t)n * 128 + pw(W)]      = h;
        g_woc[(size_t)n * 128 + 64 + pw(W)] = l;
    }
}

// ---------------------------------------------------------------------------
// Kernel A: qkv = x @ w_qkv via bf16 3-product mma. grid (128 m, 6 n),
// 256 threads, 64-row x 64-col blocks, 67.6KB smem -> 3 CTAs/SM.
// ---------------------------------------------------------------------------
__global__ void __launch_bounds__(256, 3) qkv_kernel() {
    extern __shared__ unsigned smQ[];
    unsigned* As = smQ;                 // [64 rows][132 words]
    unsigned* Bs = smQ + 64 * 132;      // [64 n][132 words]

    const int tid  = threadIdx.x;
    const int row0 = blockIdx.x * 64;
    const int n0   = blockIdx.y * 64;
    const uint32_t sAa = smem_u32(As), sBa = smem_u32(Bs);

    #pragma unroll
    for (int i = tid; i < 2048; i += 256) {
        int r = i >> 5, p4 = i & 31;
        cpa16(sAa + (uint32_t)(r * 528 + p4 * 16),
              g_xc + (size_t)(row0 + r) * 128 + p4 * 4);
    }
    #pragma unroll
    for (int i = tid; i < 2048; i += 256) {
        int nq = i >> 5, p4 = i & 31;
        cpa16(sBa + (uint32_t)(nq * 528 + p4 * 16),
              g_wc + (size_t)(n0 + nq) * 128 + p4 * 4);
    }
    CPA_COMMIT();
    CPA_WAIT0();
    __syncthreads();

    const int warp = tid >> 5, lane = tid & 31, quad = lane >> 2, qr = lane & 3;
    const int mt = warp >> 1;
    const int c  = warp & 1;
    const int r0 = row0 + mt * 16 + quad;
    const int b  = r0 >> 12;
    const int nn0 = r0 & (N_ - 1), nn1 = (r0 + 8) & (N_ - 1);

    float o[4][4];
    #pragma unroll
    for (int nt = 0; nt < 4; ++nt)
        o[nt][0] = o[nt][1] = o[nt][2] = o[nt][3] = 0.f;

    #pragma unroll
    for (int ks = 0; ks < 8; ++ks) {
        const unsigned* ar = As + (mt * 16 + quad) * 132 + ks * 8 + qr * 2;
        uint2 ah0 = *(const uint2*)ar;
        uint2 ah1 = *(const uint2*)(ar + 8 * 132);
        uint2 al0 = *(const uint2*)(ar + 64);
        uint2 al1 = *(const uint2*)(ar + 8 * 132 + 64);
        #pragma unroll
        for (int nt = 0; nt < 4; ++nt) {
            const unsigned* br = Bs + (c * 32 + nt * 8 + quad) * 132 + ks * 8 + qr * 2;
            uint2 bh2 = *(const uint2*)br;
            uint2 bl2 = *(const uint2*)(br + 64);
            MMA16(o[nt], ah0.x, ah1.x, ah0.y, ah1.y, bh2.x, bh2.y);
            MMA16(o[nt], al0.x, al1.x, al0.y, al1.y, bh2.x, bh2.y);
            MMA16(o[nt], ah0.x, ah1.x, ah0.y, ah1.y, bl2.x, bl2.y);
        }
    }

    const int col0 = n0 + c * 32;
    const int seg  = col0 >> 7;
    const int head = (col0 >> 5) & 3;
    const size_t bhh = (size_t)(b * NH + head);

    if (seg < 2) {
        float ss0 = 0.f, ss1 = 0.f;
        #pragma unroll
        for (int nt = 0; nt < 4; ++nt) {
            ss0 += o[nt][0]*o[nt][0] + o[nt][1]*o[nt][1];
            ss1 += o[nt][2]*o[nt][2] + o[nt][3]*o[nt][3];
        }
        ss0 += __shfl_xor_sync(0xffffffffu, ss0, 1);
        ss0 += __shfl_xor_sync(0xffffffffu, ss0, 2);
        ss1 += __shfl_xor_sync(0xffffffffu, ss1, 1);
        ss1 += __shfl_xor_sync(0xffffffffu, ss1, 2);
        float inv0 = 1.0f / fmaxf(sqrtf(ss0), 1e-12f);
        float inv1 = 1.0f / fmaxf(sqrtf(ss1), 1e-12f);
        if (seg == 0) { inv0 *= C0; inv1 *= C0; }
        unsigned* base0 = (seg ? g_k : g_q) + (bhh * N_ + nn0) * 16;
        unsigned* base1 = (seg ? g_k : g_q) + (bhh * N_ + nn1) * 16;
        #pragma unroll
        for (int nt = 0; nt < 4; ++nt) {
            int dp  = nt * 4 + qr;
            int pos = seg ? ((dp >> 3) * 8 + perm8(dp & 7)) : dp;
            base0[pos] = packh(o[nt][0] * inv0, o[nt][1] * inv0);
            base1[pos] = packh(o[nt][2] * inv1, o[nt][3] * inv1);
        }
    } else {
        const int pk0 = (nn0 & ~15) + perm8((nn0 >> 1) & 7) * 2 + (nn0 & 1);
        const int pk1 = (nn1 & ~15) + perm8((nn1 >> 1) & 7) * 2 + (nn1 & 1);
        #pragma unroll
        for (int nt = 0; nt < 4; ++nt) {
            int d = nt * 8 + qr * 2;
            unsigned short* vb = g_v + (bhh * DH + d) * N_;
            vb[pk0]      = __half_as_ushort(__float2half_rn(o[nt][0]));
            vb[N_ + pk0] = __half_as_ushort(__float2half_rn(o[nt][1]));
            vb[pk1]      = __half_as_ushort(__float2half_rn(o[nt][2]));
            vb[N_ + pk1] = __half_as_ushort(__float2half_rn(o[nt][3]));
        }
    }
}

// ---------------------------------------------------------------------------
// Kernel B: split-K flash attention (2 splits x 2048 keys). Fixed softmax
// offset makes partials exactly additive. grid (64, 8, 2), 128 threads.
// ---------------------------------------------------------------------------
__global__ void __launch_bounds__(128, 8) attn_kernel() {
    __shared__ __align__(16) unsigned sK[2][64 * 20];
    __shared__ __align__(16) unsigned sV[2][32 * 36];

    const int bh = blockIdx.y, sp = blockIdx.z, tid = threadIdx.x;
    const int warp = tid >> 5, lane = tid & 31, quad = lane >> 2, qr = lane & 3;
    const int qb = blockIdx.x * 64 + warp * 16;
    const int wt = qb >> 4;

    unsigned qf[2][4];
    {
        const unsigned* Q0 = g_q + ((size_t)bh * N_ + qb + quad) * 16;
        const unsigned* Q8 = Q0 + 8 * 16;
        #pragma unroll
        for (int ks = 0; ks < 2; ++ks) {
            qf[ks][0] = Q0[ks*8 + qr];      qf[ks][1] = Q8[ks*8 + qr];
            qf[ks][2] = Q0[ks*8 + qr + 4];  qf[ks][3] = Q8[ks*8 + qr + 4];
        }
    }

    float o[4][4];
    #pragma unroll
    for (int nt = 0; nt < 4; ++nt)
        o[nt][0] = o[nt][1] = o[nt][2] = o[nt][3] = 0.f;
    float l0 = 0.f, l1 = 0.f;

    const uint4* Kg = (const uint4*)g_k + (size_t)bh * N_ * 4;
    const uint4* Vg = (const uint4*)g_v + (size_t)bh * DH * (N_/8);
    const uint32_t sKa = smem_u32(sK), sVa = smem_u32(sV);

    #define STAGE(ch, buf) do {                                                \
        const int _k0 = (ch) * 64;                                             \
        const uint32_t _kb = sKa + (unsigned)(buf) * 5120u;                    \
        const uint32_t _vb = sVa + (unsigned)(buf) * 4608u;                    \
        _Pragma("unroll")                                                      \
        for (int _i = tid; _i < 256; _i += 128) {                              \
            int _key = _i >> 2, _p = _i & 3;                                   \
            cpa16(_kb + (uint32_t)(_key * 80 + _p * 16),                       \
                  Kg + (size_t)(_k0 + _key) * 4 + _p);                         \
        }                                                                      \
        _Pragma("unroll")                                                      \
        for (int _i = tid; _i < 256; _i += 128) {                              \
            int _dm = _i >> 3, _p = _i & 7;                                    \
            cpa16(_vb + (uint32_t)(_dm * 144 + _p * 16),                       \
                  Vg + (size_t)_dm * (N_/8) + _k0/8 + _p);                     \
        }                                                                      \
    } while (0)

    const int ch0 = sp * 32, chN = ch0 + 32;
    STAGE(ch0, 0);
    CPA_COMMIT();

    for (int ch = ch0; ch < chN; ++ch) {
        const int buf = ch & 1;
        if (ch < chN - 1) {
            STAGE(ch + 1, buf ^ 1);
            CPA_COMMIT();
            CPA_WAIT1();
        } else {
            CPA_WAIT0();
        }
        __syncthreads();
        const unsigned* Kb = sK[buf];
        const unsigned* Vb = sV[buf];

        #pragma unroll
        for (int half = 0; half < 2; ++half) {
            float p[4][4];
            #pragma unroll
            for (int j = 0; j < 4; ++j)
                p[j][0] = p[j][1] = p[j][2] = p[j][3] = -C0;
            #pragma unroll
            for (int ks = 0; ks < 2; ++ks) {
                #pragma unroll
                for (int j = 0; j < 4; ++j) {
                    const unsigned* kr = Kb + ((half*4 + j)*8 + quad) * 20;
                    uint2 b2 = *(const uint2*)(kr + ks*8 + 2*qr);
                    MMA16H(p[j], qf[ks][0], qf[ks][1], qf[ks][2], qf[ks][3],
                           b2.x, b2.y);
                }
            }
            #pragma unroll
            for (int j = 0; j < 4; ++j) {
                p[j][0] = ex2(p[j][0]); p[j][1] = ex2(p[j][1]);
                p[j][2] = ex2(p[j][2]); p[j][3] = ex2(p[j][3]);
                l0 += p[j][0] + p[j][1];
                l1 += p[j][2] + p[j][3];
            }
            #pragma unroll
            for (int kbl = 0; kbl < 2; ++kbl) {
                const int kbg = half * 2 + kbl;
                const float* pa = p[2*kbl];
                const float* pb = p[2*kbl + 1];
                unsigned a0 = packh(pa[0], pa[1]);
                unsigned a1 = packh(pa[2], pa[3]);
                unsigned a2 = packh(pb[0], pb[1]);
                unsigned a3 = packh(pb[2], pb[3]);
                #pragma unroll
                for (int nt = 0; nt < 4; ++nt) {
                    const unsigned* vr = Vb + (nt*8 + quad) * 36;
                    uint2 vv = *(const uint2*)(vr + kbg*8 + 2*qr);
                    MMA16H(o[nt], a0, a1, a2, a3, vv.x, vv.y);
                }
            }
        }
        __syncthreads();
    }

    l0 += __shfl_xor_sync(0xffffffffu, l0, 1);
    l0 += __shfl_xor_sync(0xffffffffu, l0, 2);
    l1 += __shfl_xor_sync(0xffffffffu, l1, 1);
    l1 += __shfl_xor_sync(0xffffffffu, l1, 2);
    const size_t job = (size_t)(sp * 8 + bh) * 256 + wt;
    #pragma unroll
    for (int nt = 0; nt < 4; ++nt)
        g_po[(job * 4 + nt) * 32 + lane] =
            make_float4(o[nt][0], o[nt][1], o[nt][2], o[nt][3]);
    g_pl[job * 32 + lane] = make_float2(l0, l1);
}

// ---------------------------------------------------------------------------
// Kernel C: combine splits + normalize + out-GEMM in one pass.
// grid 256, 128 threads (4 warps = 2 row-blocks x 2 col-halves); g_po loads
// software-pipelined one ks ahead of the mma stream.
// ---------------------------------------------------------------------------
__global__ void __launch_bounds__(128, 3) out_kernel(const float* __restrict__ bout,
                                                     float* __restrict__ out) {
    extern __shared__ unsigned smO[];
    unsigned* Bs = smO;                       // [128 n][132 words]
    float* bs = (float*)(smO + 128 * 132);    // bias

    const int tid = threadIdx.x;
    const uint32_t sBa = smem_u32(Bs);
    #pragma unroll
    for (int i = tid; i < 4096; i += 128) {
        int n = i >> 5, p4 = i & 31;
        cpa16(sBa + (uint32_t)(n * 528 + p4 * 16),
              g_woc + (size_t)n * 128 + p4 * 4);
    }
    if (tid < 128) bs[tid] = bout[tid];
    CPA_COMMIT();

    const int warp = tid >> 5, lane = tid & 31, quad = lane >> 2, qr = lane & 3;
    const int rbg = blockIdx.x * 2 + (warp >> 1);    // 16-row block (0..511)
    const int jh  = warp & 1;                        // column half (64 cols)
    const int b = rbg >> 8, wt = rbg & 255;

    // per-head inverse row sums (issued before smem wait: overlaps staging)
    float i0h[4], i1h[4];
    #pragma unroll
    for (int hh = 0; hh < 4; ++hh) {
        const int bh = b * 4 + hh;
        float2 la = g_pl[((size_t)bh * 256 + wt) * 32 + lane];
        float2 lb = g_pl[((size_t)(8 + bh) * 256 + wt) * 32 + lane];
        i0h[hh] = 1.0f / (la.x + lb.x);
        i1h[hh] = 1.0f / (la.y + lb.y);
    }

    // prefetch machinery: partial loads for step ks land one iteration early
    float4 pa[2], pc[2];
    #define LOAD_PART(ks_) do {                                               \
        const int _hh = (ks_) >> 1, _sel = (ks_) & 1;                         \
        const int _bh = b * 4 + _hh;                                          \
        const size_t _j0 = ((size_t)_bh * 256 + wt) * 4;                      \
        const size_t _j1 = ((size_t)(8 + _bh) * 256 + wt) * 4;                \
        _Pragma("unroll")                                                     \
        for (int _s = 0; _s < 2; ++_s) {                                      \
            pa[_s] = g_po[(_j0 + 2 * _sel + _s) * 32 + lane];                 \
            pc[_s] = g_po[(_j1 + 2 * _sel + _s) * 32 + lane];                 \
        }                                                                     \
    } while (0)

    LOAD_PART(0);

    CPA_WAIT0();
    __syncthreads();

    float o[8][4];
    #pragma unroll
    for (int j = 0; j < 8; ++j) {
        float b0 = bs[(jh*8 + j)*8 + qr*2], b1 = bs[(jh*8 + j)*8 + qr*2 + 1];
        o[j][0] = b0; o[j][1] = b1; o[j][2] = b0; o[j][3] = b1;
    }

    #pragma unroll
    for (int ks = 0; ks < 8; ++ks) {
        const int hh = ks >> 1;
        const float i0 = i0h[hh], i1 = i1h[hh];
        // consume prefetched partials into bf16 hi/lo fragments
        unsigned fh[4], fl[4];
        #pragma unroll
        for (int s = 0; s < 2; ++s) {
            float v0 = (pa[s].x + pc[s].x) * i0, v1 = (pa[s].y + pc[s].y) * i0;
            float v2 = (pa[s].z + pc[s].z) * i1, v3 = (pa[s].w + pc[s].w) * i1;
            unsigned h0 = packbf(v0, v1), h1 = packbf(v2, v3);
            fh[2*s]   = h0;
            fh[2*s+1] = h1;
            fl[2*s]   = packbf(v0 - bf_lo(h0), v1 - bf_hi(h0));
            fl[2*s+1] = packbf(v2 - bf_lo(h1), v3 - bf_hi(h1));
        }
        // issue next step's loads before this step's mma chain
        if (ks < 7) LOAD_PART(ks + 1);
        #pragma unroll
        for (int j = 0; j < 8; ++j) {
            const unsigned* br = Bs + ((jh*8 + j)*8 + quad) * 132 + ks*8 + qr*2;
            uint2 bh2 = *(const uint2*)br;
            uint2 bl2 = *(const uint2*)(br + 64);
            MMA16(o[j], fh[0], fh[1], fh[2], fh[3], bh2.x, bh2.y);
            MMA16(o[j], fl[0], fl[1], fl[2], fl[3], bh2.x, bh2.y);
            MMA16(o[j], fh[0], fh[1], fh[2], fh[3], bl2.x, bl2.y);
        }
    }

    const int r0 = rbg * 16 + quad;
    #pragma unroll
    for (int j = 0; j < 8; ++j) {
        *(float2*)(out + (size_t)r0 * DIM + (jh*8 + j)*8 + qr*2) =
            make_float2(o[j][0], o[j][1]);
        *(float2*)(out + (size_t)(r0 + 8) * DIM + (jh*8 + j)*8 + qr*2) =
            make_float2(o[j][2], o[j][3]);
    }
}

// ---------------------------------------------------------------------------
extern "C" void kernel_launch(void* const* d_in, const int* in_sizes, int n_in,
                              void* d_out, int out_size) {
    const float *x = nullptr, *wqkv = nullptr, *wout = nullptr, *bout = nullptr;
    for (int i = 0; i < n_in; ++i) {
        switch (in_sizes[i]) {
            case ROWS_TOT * C_: x    = (const float*)d_in[i]; break;
            case C_ * QKV:      wqkv = (const float*)d_in[i]; break;
            case DIM * C_:      wout = (const float*)d_in[i]; break;
            case C_:            bout = (const float*)d_in[i]; break;
        }
    }
    float* out = (float*)d_out;

    const int smA = (64 + 64) * 132 * 4;           // 67584 B -> 3 CTAs/SM
    const int smO = 128 * 132 * 4 + 512;           // 68096 B -> 3 CTAs/SM
    cudaFuncSetAttribute(qkv_kernel, cudaFuncAttributeMaxDynamicSharedMemorySize, smA);
    cudaFuncSetAttribute(out_kernel, cudaFuncAttributeMaxDynamicSharedMemorySize, smO);

    prep_kernel<<<2176, 256>>>(x, wqkv, wout);
    qkv_kernel<<<dim3(128, 6), 256, smA>>>();
    attn_kernel<<<dim3(64, 8, 2), 128>>>();
    out_kernel<<<256, 128, smO>>>(bout, out);
}

// round 15
// speedup vs baseline: 7.6531x; 1.0074x over previous
#include <cuda_runtime.h>
#include <cuda_fp16.h>
#include <cstdint>

#define B_   2
#define N_   4096
#define C_   128
#define NH   4
#define DH   32
#define DIM  128
#define QKV  384
#define ROWS_TOT (B_*N_)
#define C0 14.4269504088896340736f

// ---------------- scratch ---------------------------------------------------
__device__ __align__(16) unsigned g_xc[ROWS_TOT*128];   // x as bf16 hi/lo, permuted
__device__ __align__(16) unsigned g_wc[QKV*128];        // w_qkv^T, same format
__device__ __align__(16) unsigned g_woc[DIM*128];       // w_out^T, same format
__device__ __align__(16) unsigned g_q[8*N_*16];         // fp16x2, C0-scaled
__device__ __align__(16) unsigned g_k[8*N_*16];         // fp16x2, pair-permuted
__device__ __align__(16) unsigned short g_v[8*DH*N_];   // fp16, key-permuted
// split-K partials: o fragments (fp32) and row sums
__device__ __align__(16) float4 g_po[2*8*256*4*32];
__device__ __align__(16) float2 g_pl[2*8*256*32];

// ---------------- helpers ----------------------------------------------------
__device__ __forceinline__ float ex2(float x) {
    float r; asm("ex2.approx.ftz.f32 %0, %1;" : "=f"(r) : "f"(x)); return r;
}
__device__ __forceinline__ unsigned packbf(float lo, float hi) {
    unsigned d; asm("cvt.rn.bf16x2.f32 %0, %1, %2;" : "=r"(d) : "f"(hi), "f"(lo)); return d;
}
__device__ __forceinline__ float bf_lo(unsigned u) { return __uint_as_float(u << 16); }
__device__ __forceinline__ float bf_hi(unsigned u) { return __uint_as_float(u & 0xffff0000u); }
__device__ __forceinline__ unsigned packh(float lo, float hi) {
    unsigned d; asm("cvt.rn.f16x2.f32 %0, %1, %2;" : "=r"(d) : "f"(hi), "f"(lo)); return d;
}
__device__ __forceinline__ uint32_t smem_u32(const void* p) {
    uint32_t a;
    asm("{ .reg .u64 t; cvta.to.shared.u64 t, %1; cvt.u32.u64 %0, t; }" : "=r"(a) : "l"(p));
    return a;
}
__device__ __forceinline__ void cpa16(uint32_t dst, const void* src) {
    asm volatile("cp.async.cg.shared.global [%0], [%1], 16;" :: "r"(dst), "l"(src));
}
#define CPA_COMMIT() asm volatile("cp.async.commit_group;" ::: "memory")
#define CPA_WAIT1()  asm volatile("cp.async.wait_group 1;" ::: "memory")
#define CPA_WAIT0()  asm volatile("cp.async.wait_group 0;" ::: "memory")

#define MMA16(c, a0,a1,a2,a3, b0, b1)                                          \
    asm volatile("mma.sync.aligned.m16n8k16.row.col.f32.bf16.bf16.f32 "        \
                 "{%0,%1,%2,%3},{%4,%5,%6,%7},{%8,%9},{%0,%1,%2,%3};"          \
                 : "+f"(c[0]), "+f"(c[1]), "+f"(c[2]), "+f"(c[3])              \
                 : "r"(a0), "r"(a1), "r"(a2), "r"(a3), "r"(b0), "r"(b1))
#define MMA16H(c, a0,a1,a2,a3, b0, b1)                                         \
    asm volatile("mma.sync.aligned.m16n8k16.row.col.f32.f16.f16.f32 "          \
                 "{%0,%1,%2,%3},{%4,%5,%6,%7},{%8,%9},{%0,%1,%2,%3};"          \
                 : "+f"(c[0]), "+f"(c[1]), "+f"(c[2]), "+f"(c[3])              \
                 : "r"(a0), "r"(a1), "r"(a2), "r"(a3), "r"(b0), "r"(b1))

__device__ __forceinline__ int perm8(int t) { return (t < 4) ? 2*t : 2*(t-4)+1; }
__device__ __forceinline__ int pw(int W) { return (W & ~7) + perm8(W & 7); }

// ---------------------------------------------------------------------------
// Kernel P: one-time conversion of x, w_qkv^T, w_out^T into bf16 hi/lo images.
// ---------------------------------------------------------------------------
__global__ void __launch_bounds__(256) prep_kernel(const float* __restrict__ x,
                                                   const float* __restrict__ w,
                                                   const float* __restrict__ wo) {
    const int idx = blockIdx.x * 256 + threadIdx.x;
    if (blockIdx.x < 2048) {                       // x
        const int r = idx >> 6, W = idx & 63;
        float2 v = *(const float2*)(x + (size_t)r * C_ + W * 2);
        unsigned h = packbf(v.x, v.y);
        unsigned l = packbf(v.x - bf_lo(h), v.y - bf_hi(h));
        g_xc[(size_t)r * 128 + pw(W)]      = h;
        g_xc[(size_t)r * 128 + 64 + pw(W)] = l;
    } else if (blockIdx.x < 2144) {                // w_qkv transpose
        const int i = idx - 2048 * 256;
        const int n = i >> 6, W = i & 63;
        float va = w[(size_t)(2 * W) * QKV + n];
        float vb = w[(size_t)(2 * W + 1) * QKV + n];
        unsigned h = packbf(va, vb);
        unsigned l = packbf(va - bf_lo(h), vb - bf_hi(h));
        g_wc[(size_t)n * 128 + pw(W)]      = h;
        g_wc[(size_t)n * 128 + 64 + pw(W)] = l;
    } else {                                       // w_out transpose
        const int i = idx - 2144 * 256;
        const int n = i >> 6, W = i & 63;
        float va = wo[(size_t)(2 * W) * DIM + n];
        float vb = wo[(size_t)(2 * W + 1) * DIM + n];
        unsigned h = packbf(va, vb);
        unsigned l = packbf(va - bf_lo(h), vb - bf_hi(h));
        g_woc[(size_t)n * 128 + pw(W)]      = h;
        g_woc[(size_t)n * 128 + 64 + pw(W)] = l;
    }
}

// ---------------------------------------------------------------------------
// Kernel A: qkv = x @ w_qkv via bf16 3-product mma. grid (128 m, 6 n),
// 256 threads, 64x64 blocks, 67.6KB smem -> 3 CTAs/SM.
// ---------------------------------------------------------------------------
__global__ void __launch_bounds__(256, 3) qkv_kernel() {
    extern __shared__ unsigned smQ[];
    unsigned* As = smQ;                 // [64 rows][132 words]
    unsigned* Bs = smQ + 64 * 132;      // [64 n][132 words]

    const int tid  = threadIdx.x;
    const int row0 = blockIdx.x * 64;
    const int n0   = blockIdx.y * 64;
    const uint32_t sAa = smem_u32(As), sBa = smem_u32(Bs);

    #pragma unroll
    for (int i = tid; i < 2048; i += 256) {
        int r = i >> 5, p4 = i & 31;
        cpa16(sAa + (uint32_t)(r * 528 + p4 * 16),
              g_xc + (size_t)(row0 + r) * 128 + p4 * 4);
    }
    #pragma unroll
    for (int i = tid; i < 2048; i += 256) {
        int nq = i >> 5, p4 = i & 31;
        cpa16(sBa + (uint32_t)(nq * 528 + p4 * 16),
              g_wc + (size_t)(n0 + nq) * 128 + p4 * 4);
    }
    CPA_COMMIT();
    CPA_WAIT0();
    __syncthreads();

    const int warp = tid >> 5, lane = tid & 31, quad = lane >> 2, qr = lane & 3;
    const int mt = warp >> 1;
    const int c  = warp & 1;
    const int r0 = row0 + mt * 16 + quad;
    const int b  = r0 >> 12;
    const int nn0 = r0 & (N_ - 1), nn1 = (r0 + 8) & (N_ - 1);

    float o[4][4];
    #pragma unroll
    for (int nt = 0; nt < 4; ++nt)
        o[nt][0] = o[nt][1] = o[nt][2] = o[nt][3] = 0.f;

    #pragma unroll
    for (int ks = 0; ks < 8; ++ks) {
        const unsigned* ar = As + (mt * 16 + quad) * 132 + ks * 8 + qr * 2;
        uint2 ah0 = *(const uint2*)ar;
        uint2 ah1 = *(const uint2*)(ar + 8 * 132);
        uint2 al0 = *(const uint2*)(ar + 64);
        uint2 al1 = *(const uint2*)(ar + 8 * 132 + 64);
        #pragma unroll
        for (int nt = 0; nt < 4; ++nt) {
            const unsigned* br = Bs + (c * 32 + nt * 8 + quad) * 132 + ks * 8 + qr * 2;
            uint2 bh2 = *(const uint2*)br;
            uint2 bl2 = *(const uint2*)(br + 64);
            MMA16(o[nt], ah0.x, ah1.x, ah0.y, ah1.y, bh2.x, bh2.y);
            MMA16(o[nt], al0.x, al1.x, al0.y, al1.y, bh2.x, bh2.y);
            MMA16(o[nt], ah0.x, ah1.x, ah0.y, ah1.y, bl2.x, bl2.y);
        }
    }

    const int col0 = n0 + c * 32;
    const int seg  = col0 >> 7;
    const int head = (col0 >> 5) & 3;
    const size_t bhh = (size_t)(b * NH + head);

    if (seg < 2) {
        float ss0 = 0.f, ss1 = 0.f;
        #pragma unroll
        for (int nt = 0; nt < 4; ++nt) {
            ss0 += o[nt][0]*o[nt][0] + o[nt][1]*o[nt][1];
            ss1 += o[nt][2]*o[nt][2] + o[nt][3]*o[nt][3];
        }
        ss0 += __shfl_xor_sync(0xffffffffu, ss0, 1);
        ss0 += __shfl_xor_sync(0xffffffffu, ss0, 2);
        ss1 += __shfl_xor_sync(0xffffffffu, ss1, 1);
        ss1 += __shfl_xor_sync(0xffffffffu, ss1, 2);
        float inv0 = 1.0f / fmaxf(sqrtf(ss0), 1e-12f);
        float inv1 = 1.0f / fmaxf(sqrtf(ss1), 1e-12f);
        if (seg == 0) { inv0 *= C0; inv1 *= C0; }
        unsigned* base0 = (seg ? g_k : g_q) + (bhh * N_ + nn0) * 16;
        unsigned* base1 = (seg ? g_k : g_q) + (bhh * N_ + nn1) * 16;
        #pragma unroll
        for (int nt = 0; nt < 4; ++nt) {
            int dp  = nt * 4 + qr;
            int pos = seg ? ((dp >> 3) * 8 + perm8(dp & 7)) : dp;
            base0[pos] = packh(o[nt][0] * inv0, o[nt][1] * inv0);
            base1[pos] = packh(o[nt][2] * inv1, o[nt][3] * inv1);
        }
    } else {
        const int pk0 = (nn0 & ~15) + perm8((nn0 >> 1) & 7) * 2 + (nn0 & 1);
        const int pk1 = (nn1 & ~15) + perm8((nn1 >> 1) & 7) * 2 + (nn1 & 1);
        #pragma unroll
        for (int nt = 0; nt < 4; ++nt) {
            int d = nt * 8 + qr * 2;
            unsigned short* vb = g_v + (bhh * DH + d) * N_;
            vb[pk0]      = __half_as_ushort(__float2half_rn(o[nt][0]));
            vb[N_ + pk0] = __half_as_ushort(__float2half_rn(o[nt][1]));
            vb[pk1]      = __half_as_ushort(__float2half_rn(o[nt][2]));
            vb[N_ + pk1] = __half_as_ushort(__float2half_rn(o[nt][3]));
        }
    }
}

// ---------------------------------------------------------------------------
// Kernel B: split-K flash attention (2 splits x 2048 keys). Fixed softmax
// offset makes partials exactly additive. grid (64, 8, 2), 128 threads.
// ---------------------------------------------------------------------------
__global__ void __launch_bounds__(128, 8) attn_kernel() {
    __shared__ __align__(16) unsigned sK[2][64 * 20];
    __shared__ __align__(16) unsigned sV[2][32 * 36];

    const int bh = blockIdx.y, sp = blockIdx.z, tid = threadIdx.x;
    const int warp = tid >> 5, lane = tid & 31, quad = lane >> 2, qr = lane & 3;
    const int qb = blockIdx.x * 64 + warp * 16;
    const int wt = qb >> 4;

    unsigned qf[2][4];
    {
        const unsigned* Q0 = g_q + ((size_t)bh * N_ + qb + quad) * 16;
        const unsigned* Q8 = Q0 + 8 * 16;
        #pragma unroll
        for (int ks = 0; ks < 2; ++ks) {
            qf[ks][0] = Q0[ks*8 + qr];      qf[ks][1] = Q8[ks*8 + qr];
            qf[ks][2] = Q0[ks*8 + qr + 4];  qf[ks][3] = Q8[ks*8 + qr + 4];
        }
    }

    float o[4][4];
    #pragma unroll
    for (int nt = 0; nt < 4; ++nt)
        o[nt][0] = o[nt][1] = o[nt][2] = o[nt][3] = 0.f;
    float l0 = 0.f, l1 = 0.f;

    const uint4* Kg = (const uint4*)g_k + (size_t)bh * N_ * 4;
    const uint4* Vg = (const uint4*)g_v + (size_t)bh * DH * (N_/8);
    const uint32_t sKa = smem_u32(sK), sVa = smem_u32(sV);

    #define STAGE(ch, buf) do {                                                \
        const int _k0 = (ch) * 64;                                             \
        const uint32_t _kb = sKa + (unsigned)(buf) * 5120u;                    \
        const uint32_t _vb = sVa + (unsigned)(buf) * 4608u;                    \
        _Pragma("unroll")                                                      \
        for (int _i = tid; _i < 256; _i += 128) {                              \
            int _key = _i >> 2, _p = _i & 3;                                   \
            cpa16(_kb + (uint32_t)(_key * 80 + _p * 16),                       \
                  Kg + (size_t)(_k0 + _key) * 4 + _p);                         \
        }                                                                      \
        _Pragma("unroll")                                                      \
        for (int _i = tid; _i < 256; _i += 128) {                              \
            int _dm = _i >> 3, _p = _i & 7;                                    \
            cpa16(_vb + (uint32_t)(_dm * 144 + _p * 16),                       \
                  Vg + (size_t)_dm * (N_/8) + _k0/8 + _p);                     \
        }                                                                      \
    } while (0)

    const int ch0 = sp * 32, chN = ch0 + 32;
    STAGE(ch0, 0);
    CPA_COMMIT();

    for (int ch = ch0; ch < chN; ++ch) {
        const int buf = ch & 1;
        if (ch < chN - 1) {
            STAGE(ch + 1, buf ^ 1);
            CPA_COMMIT();
            CPA_WAIT1();
        } else {
            CPA_WAIT0();
        }
        __syncthreads();
        const unsigned* Kb = sK[buf];
        const unsigned* Vb = sV[buf];

        #pragma unroll
        for (int half = 0; half < 2; ++half) {
            float p[4][4];
            #pragma unroll
            for (int j = 0; j < 4; ++j)
                p[j][0] = p[j][1] = p[j][2] = p[j][3] = -C0;
            #pragma unroll
            for (int ks = 0; ks < 2; ++ks) {
                #pragma unroll
                for (int j = 0; j < 4; ++j) {
                    const unsigned* kr = Kb + ((half*4 + j)*8 + quad) * 20;
                    uint2 b2 = *(const uint2*)(kr + ks*8 + 2*qr);
                    MMA16H(p[j], qf[ks][0], qf[ks][1], qf[ks][2], qf[ks][3],
                           b2.x, b2.y);
                }
            }
            #pragma unroll
            for (int j = 0; j < 4; ++j) {
                p[j][0] = ex2(p[j][0]); p[j][1] = ex2(p[j][1]);
                p[j][2] = ex2(p[j][2]); p[j][3] = ex2(p[j][3]);
                l0 += p[j][0] + p[j][1];
                l1 += p[j][2] + p[j][3];
            }
            #pragma unroll
            for (int kbl = 0; kbl < 2; ++kbl) {
                const int kbg = half * 2 + kbl;
                const float* pa = p[2*kbl];
                const float* pb = p[2*kbl + 1];
                unsigned a0 = packh(pa[0], pa[1]);
                unsigned a1 = packh(pa[2], pa[3]);
                unsigned a2 = packh(pb[0], pb[1]);
                unsigned a3 = packh(pb[2], pb[3]);
                #pragma unroll
                for (int nt = 0; nt < 4; ++nt) {
                    const unsigned* vr = Vb + (nt*8 + quad) * 36;
                    uint2 vv = *(const uint2*)(vr + kbg*8 + 2*qr);
                    MMA16H(o[nt], a0, a1, a2, a3, vv.x, vv.y);
                }
            }
        }
        __syncthreads();
    }

    l0 += __shfl_xor_sync(0xffffffffu, l0, 1);
    l0 += __shfl_xor_sync(0xffffffffu, l0, 2);
    l1 += __shfl_xor_sync(0xffffffffu, l1, 1);
    l1 += __shfl_xor_sync(0xffffffffu, l1, 2);
    const size_t job = (size_t)(sp * 8 + bh) * 256 + wt;
    #pragma unroll
    for (int nt = 0; nt < 4; ++nt)
        g_po[(job * 4 + nt) * 32 + lane] =
            make_float4(o[nt][0], o[nt][1], o[nt][2], o[nt][3]);
    g_pl[job * 32 + lane] = make_float2(l0, l1);
}

// ---------------------------------------------------------------------------
// Kernel C: combine splits + normalize + out-GEMM. grid (128, 2): block =
// 4 row-blocks (one/warp) x one 64-col half; stages only its 34KB w_out half.
// ---------------------------------------------------------------------------
__global__ void __launch_bounds__(128, 4) out_kernel(const float* __restrict__ bout,
                                                     float* __restrict__ out) {
    extern __shared__ unsigned smO[];
    unsigned* Bs = smO;                       // [64 n][132 words]
    float* bs = (float*)(smO + 64 * 132);     // bias (this half)

    const int tid = threadIdx.x;
    const int jh  = blockIdx.y;               // column half
    const uint32_t sBa = smem_u32(Bs);
    #pragma unroll
    for (int i = tid; i < 2048; i += 128) {
        int n = i >> 5, p4 = i & 31;
        cpa16(sBa + (uint32_t)(n * 528 + p4 * 16),
              g_woc + (size_t)(jh * 64 + n) * 128 + p4 * 4);
    }
    if (tid < 64) bs[tid] = bout[jh * 64 + tid];
    CPA_COMMIT();

    const int warp = tid >> 5, lane = tid & 31, quad = lane >> 2, qr = lane & 3;
    const int rbg = blockIdx.x * 4 + warp;    // 16-row block (0..511)
    const int b = rbg >> 8, wt = rbg & 255;

    // per-head inverse row sums (issued before smem wait: overlaps staging)
    float i0h[4], i1h[4];
    #pragma unroll
    for (int hh = 0; hh < 4; ++hh) {
        const int bh = b * 4 + hh;
        float2 la = g_pl[((size_t)bh * 256 + wt) * 32 + lane];
        float2 lb = g_pl[((size_t)(8 + bh) * 256 + wt) * 32 + lane];
        i0h[hh] = 1.0f / (la.x + lb.x);
        i1h[hh] = 1.0f / (la.y + lb.y);
    }

    float4 pa[2], pc[2];
    #define LOAD_PART(ks_) do {                                               \
        const int _hh = (ks_) >> 1, _sel = (ks_) & 1;                         \
        const int _bh = b * 4 + _hh;                                          \
        const size_t _j0 = ((size_t)_bh * 256 + wt) * 4;                      \
        const size_t _j1 = ((size_t)(8 + _bh) * 256 + wt) * 4;                \
        _Pragma("unroll")                                                     \
        for (int _s = 0; _s < 2; ++_s) {                                      \
            pa[_s] = g_po[(_j0 + 2 * _sel + _s) * 32 + lane];                 \
            pc[_s] = g_po[(_j1 + 2 * _sel + _s) * 32 + lane];                 \
        }                                                                     \
    } while (0)

    LOAD_PART(0);

    CPA_WAIT0();
    __syncthreads();

    float o[8][4];
    #pragma unroll
    for (int j = 0; j < 8; ++j) {
        float b0 = bs[j*8 + qr*2], b1 = bs[j*8 + qr*2 + 1];
        o[j][0] = b0; o[j][1] = b1; o[j][2] = b0; o[j][3] = b1;
    }

    #pragma unroll
    for (int ks = 0; ks < 8; ++ks) {
        const int hh = ks >> 1;
        const float i0 = i0h[hh], i1 = i1h[hh];
        unsigned fh[4], fl[4];
        #pragma unroll
        for (int s = 0; s < 2; ++s) {
            float v0 = (pa[s].x + pc[s].x) * i0, v1 = (pa[s].y + pc[s].y) * i0;
            float v2 = (pa[s].z + pc[s].z) * i1, v3 = (pa[s].w + pc[s].w) * i1;
            unsigned h0 = packbf(v0, v1), h1 = packbf(v2, v3);
            fh[2*s]   = h0;
            fh[2*s+1] = h1;
            fl[2*s]   = packbf(v0 - bf_lo(h0), v1 - bf_hi(h0));
            fl[2*s+1] = packbf(v2 - bf_lo(h1), v3 - bf_hi(h1));
        }
        if (ks < 7) LOAD_PART(ks + 1);
        #pragma unroll
        for (int j = 0; j < 8; ++j) {
            const unsigned* br = Bs + (j*8 + quad) * 132 + ks*8 + qr*2;
            uint2 bh2 = *(const uint2*)br;
            uint2 bl2 = *(const uint2*)(br + 64);
            MMA16(o[j], fh[0], fh[1], fh[2], fh[3], bh2.x, bh2.y);
            MMA16(o[j], fl[0], fl[1], fl[2], fl[3], bh2.x, bh2.y);
            MMA16(o[j], fh[0], fh[1], fh[2], fh[3], bl2.x, bl2.y);
        }
    }

    const int r0 = rbg * 16 + quad;
    #pragma unroll
    for (int j = 0; j < 8; ++j) {
        *(float2*)(out + (size_t)r0 * DIM + jh*64 + j*8 + qr*2) =
            make_float2(o[j][0], o[j][1]);
        *(float2*)(out + (size_t)(r0 + 8) * DIM + jh*64 + j*8 + qr*2) =
            make_float2(o[j][2], o[j][3]);
    }
}

// ---------------------------------------------------------------------------
extern "C" void kernel_launch(void* const* d_in, const int* in_sizes, int n_in,
                              void* d_out, int out_size) {
    const float *x = nullptr, *wqkv = nullptr, *wout = nullptr, *bout = nullptr;
    for (int i = 0; i < n_in; ++i) {
        switch (in_sizes[i]) {
            case ROWS_TOT * C_: x    = (const float*)d_in[i]; break;
            case C_ * QKV:      wqkv = (const float*)d_in[i]; break;
            case DIM * C_:      wout = (const float*)d_in[i]; break;
            case C_:            bout = (const float*)d_in[i]; break;
        }
    }
    float* out = (float*)d_out;

    const int smA = (64 + 64) * 132 * 4;           // 67584 B -> 3 CTAs/SM
    const int smO = 64 * 132 * 4 + 256;            // 34048 B -> 4 CTAs/SM
    cudaFuncSetAttribute(qkv_kernel, cudaFuncAttributeMaxDynamicSharedMemorySize, smA);
    cudaFuncSetAttribute(out_kernel, cudaFuncAttributeMaxDynamicSharedMemorySize, smO);

    prep_kernel<<<2176, 256>>>(x, wqkv, wout);
    qkv_kernel<<<dim3(128, 6), 256, smA>>>();
    attn_kernel<<<dim3(64, 8, 2), 128>>>();
    out_kernel<<<dim3(128, 2), 128, smO>>>(bout, out);
}